// round 1
// baseline (speedup 1.0000x reference)
#include <cuda_runtime.h>
#include <math.h>

// ------------------------- problem dimensions -------------------------
#define L_SEQ   2048
#define E_DIM   4096
#define HR_DIM  1024
#define NH      32          // attention heads
#define D_ATT   32          // attention head dim
#define NLAY    32          // predicted layers
#define DD      16          // importance head dim
#define OUT_FEAT (NLAY*NH*DD)   // 16384

// ------------------------- scratch (static device mem) ----------------
__device__ float g_hr  [(size_t)L_SEQ*HR_DIM];
__device__ float g_q   [(size_t)L_SEQ*HR_DIM];
__device__ float g_k   [(size_t)L_SEQ*HR_DIM];
__device__ float g_v   [(size_t)L_SEQ*HR_DIM];
__device__ float g_attn[(size_t)L_SEQ*HR_DIM];
__device__ float g_ln  [(size_t)L_SEQ*HR_DIM];
__device__ float g_f1  [(size_t)L_SEQ*2*HR_DIM];
__device__ float g_hid [(size_t)L_SEQ*E_DIM];
__device__ float g_aq  [(size_t)L_SEQ*HR_DIM];
__device__ float g_ak  [(size_t)L_SEQ*HR_DIM];
__device__ float g_qi  [(size_t)L_SEQ*OUT_FEAT];
__device__ float g_ki  [(size_t)L_SEQ*OUT_FEAT];

struct F16 { float f[16]; };
struct F8  { float f[8];  };

// ------------------------- activation helpers -------------------------
__device__ __forceinline__ float gelu_f(float x) {
    return 0.5f * x * (1.0f + erff(x * 0.7071067811865476f));
}
__device__ __forceinline__ float silu_f(float x) {
    return x / (1.0f + expf(-x));
}

// ------------------------- SGEMM: C[M,N] = A[M,K] * B[N,K]^T ----------
// EPI: 0 = none, 1 = gelu(acc+bias), 2 = acc+bias+resid, 3 = silu(acc)
#define BM 128
#define BN 128
#define BK 16

template<int EPI>
__global__ __launch_bounds__(256)
void sgemm_nt(const float* __restrict__ A, const float* __restrict__ B,
              float* __restrict__ C,
              const float* __restrict__ bias, const float* __restrict__ resid,
              int M, int N, int K)
{
    __shared__ float As[BK][BM];
    __shared__ float Bs[BK][BN];
    const int tid = threadIdx.x;
    const int bm = blockIdx.y, bn = blockIdx.x;
    const float* Ab = A + (size_t)bm * BM * K;
    const float* Bb = B + (size_t)bn * BN * K;
    const int ty = tid >> 4, tx = tid & 15;

    float acc[8][8];
#pragma unroll
    for (int i = 0; i < 8; i++)
#pragma unroll
        for (int j = 0; j < 8; j++) acc[i][j] = 0.0f;

    for (int k0 = 0; k0 < K; k0 += BK) {
#pragma unroll
        for (int i = 0; i < 2; i++) {
            int id  = tid + i * 256;
            int row = id >> 2;
            int k4  = (id & 3) << 2;
            float4 a = *reinterpret_cast<const float4*>(Ab + (size_t)row * K + k0 + k4);
            As[k4+0][row] = a.x; As[k4+1][row] = a.y;
            As[k4+2][row] = a.z; As[k4+3][row] = a.w;
            float4 b = *reinterpret_cast<const float4*>(Bb + (size_t)row * K + k0 + k4);
            Bs[k4+0][row] = b.x; Bs[k4+1][row] = b.y;
            Bs[k4+2][row] = b.z; Bs[k4+3][row] = b.w;
        }
        __syncthreads();
#pragma unroll
        for (int k = 0; k < BK; k++) {
            float ra[8], rb[8];
            *reinterpret_cast<float4*>(ra)     = *reinterpret_cast<const float4*>(&As[k][ty*8]);
            *reinterpret_cast<float4*>(ra + 4) = *reinterpret_cast<const float4*>(&As[k][ty*8+4]);
            *reinterpret_cast<float4*>(rb)     = *reinterpret_cast<const float4*>(&Bs[k][tx*8]);
            *reinterpret_cast<float4*>(rb + 4) = *reinterpret_cast<const float4*>(&Bs[k][tx*8+4]);
#pragma unroll
            for (int i = 0; i < 8; i++)
#pragma unroll
                for (int j = 0; j < 8; j++)
                    acc[i][j] = fmaf(ra[i], rb[j], acc[i][j]);
        }
        __syncthreads();
    }

#pragma unroll
    for (int i = 0; i < 8; i++) {
        int m = bm * BM + ty * 8 + i;
        size_t rowoff = (size_t)m * N + bn * BN + tx * 8;
#pragma unroll
        for (int j = 0; j < 8; j++) {
            float vv = acc[i][j];
            int n = bn * BN + tx * 8 + j;
            if (EPI == 1)      vv = gelu_f(vv + bias[n]);
            else if (EPI == 2) vv = vv + bias[n] + resid[rowoff + j];
            else if (EPI == 3) vv = silu_f(vv);
            C[rowoff + j] = vv;
        }
    }
}

// ------------------------- RoPE on q,k (in-place, head dim 32) --------
__global__ __launch_bounds__(256)
void rope_qk(float* __restrict__ q, float* __restrict__ k, F16 ft)
{
    int idx = blockIdx.x * blockDim.x + threadIdx.x;   // L*NH*16 = 1,048,576
    int i = idx & 15;
    int h = (idx >> 4) & 31;
    int l = idx >> 9;
    float ang = (float)l * ft.f[i];
    float c = cosf(ang), s = sinf(ang);
    size_t base = (size_t)l * HR_DIM + h * D_ATT + i;
    float x1 = q[base], x2 = q[base + 16];
    q[base]      = x1 * c - x2 * s;
    q[base + 16] = x2 * c + x1 * s;
    float y1 = k[base], y2 = k[base + 16];
    k[base]      = y1 * c - y2 * s;
    k[base + 16] = y2 * c + y1 * s;
}

// ------------------------- causal attention ---------------------------
// grid (L/4, NH), 128 threads = 4 warps; one warp per query row.
#define ACH 128
__global__ __launch_bounds__(128)
void attn_k(const float* __restrict__ Q, const float* __restrict__ K,
            const float* __restrict__ V, float* __restrict__ O)
{
    __shared__ float Ks[ACH][33];
    __shared__ float Vs[ACH][33];
    const int h = blockIdx.y;
    const int qbase = blockIdx.x * 4;
    const int lane = threadIdx.x & 31;
    const int wid  = threadIdx.x >> 5;
    const int l = qbase + wid;

    float qreg = Q[(size_t)l * HR_DIM + h * D_ATT + lane] * 0.17677669529663687f;
    float m = -INFINITY, ssum = 0.0f, acc = 0.0f;
    const int lmax = qbase + 3;

    for (int j0 = 0; j0 <= lmax; j0 += ACH) {
        for (int t = threadIdx.x; t < ACH * 32; t += 128) {
            int r = t >> 5, c = t & 31;
            size_t gi = (size_t)(j0 + r) * HR_DIM + h * D_ATT + c;
            Ks[r][c] = K[gi];
            Vs[r][c] = V[gi];
        }
        __syncthreads();
        if (j0 <= l) {
#pragma unroll 1
            for (int jj = 0; jj < ACH; jj += 32) {
                int j = j0 + jj + lane;
                float s = 0.0f;
#pragma unroll
                for (int d = 0; d < 32; d++)
                    s = fmaf(__shfl_sync(0xffffffffu, qreg, d), Ks[jj + lane][d], s);
                if (j > l) s = -1e30f;
                float mc = s;
#pragma unroll
                for (int o = 16; o; o >>= 1) mc = fmaxf(mc, __shfl_xor_sync(0xffffffffu, mc, o));
                float mnew = fmaxf(m, mc);
                float alpha = expf(m - mnew);
                float p = expf(s - mnew);
                float psum = p;
#pragma unroll
                for (int o = 16; o; o >>= 1) psum += __shfl_xor_sync(0xffffffffu, psum, o);
                ssum = ssum * alpha + psum;
                acc *= alpha;
#pragma unroll
                for (int j2 = 0; j2 < 32; j2++)
                    acc = fmaf(__shfl_sync(0xffffffffu, p, j2), Vs[jj + j2][lane], acc);
                m = mnew;
            }
        }
        __syncthreads();
    }
    O[(size_t)l * HR_DIM + h * D_ATT + lane] = acc / ssum;
}

// ------------------------- LayerNorm (rows of 1024) -------------------
__global__ __launch_bounds__(256)
void layernorm_k(const float* __restrict__ in, const float* __restrict__ w,
                 const float* __restrict__ b, float* __restrict__ out)
{
    __shared__ float red[8];
    const int row = blockIdx.x;
    const int tid = threadIdx.x;
    const int lane = tid & 31, wid = tid >> 5;
    float4 v = reinterpret_cast<const float4*>(in + (size_t)row * HR_DIM)[tid];

    float s = v.x + v.y + v.z + v.w;
#pragma unroll
    for (int o = 16; o; o >>= 1) s += __shfl_xor_sync(0xffffffffu, s, o);
    if (lane == 0) red[wid] = s;
    __syncthreads();
    float tot = red[0]+red[1]+red[2]+red[3]+red[4]+red[5]+red[6]+red[7];
    float mu = tot * (1.0f / HR_DIM);

    float dx0 = v.x - mu, dx1 = v.y - mu, dx2 = v.z - mu, dx3 = v.w - mu;
    float sq = dx0*dx0 + dx1*dx1 + dx2*dx2 + dx3*dx3;
#pragma unroll
    for (int o = 16; o; o >>= 1) sq += __shfl_xor_sync(0xffffffffu, sq, o);
    __syncthreads();
    if (lane == 0) red[wid] = sq;
    __syncthreads();
    float var = (red[0]+red[1]+red[2]+red[3]+red[4]+red[5]+red[6]+red[7]) * (1.0f / HR_DIM);
    float rstd = rsqrtf(var + 1e-5f);

    float4 wv = reinterpret_cast<const float4*>(w)[tid];
    float4 bv = reinterpret_cast<const float4*>(b)[tid];
    float4 o4;
    o4.x = dx0 * rstd * wv.x + bv.x;
    o4.y = dx1 * rstd * wv.y + bv.y;
    o4.z = dx2 * rstd * wv.z + bv.z;
    o4.w = dx3 * rstd * wv.w + bv.w;
    reinterpret_cast<float4*>(out + (size_t)row * HR_DIM)[tid] = o4;
}

// ---------------- importance RoPE + permute to (N,H,L,DD) -------------
__global__ __launch_bounds__(256)
void rope_perm(const float* __restrict__ in, float* __restrict__ out, F8 ft)
{
    int idx = blockIdx.x * blockDim.x + threadIdx.x;   // NLAY*NH*L*8 = 16,777,216
    int i = idx & 7;
    int l = (idx >> 3) & 2047;
    int h = (idx >> 14) & 31;
    int n = idx >> 19;
    float ang = (float)l * ft.f[i];
    float c = cosf(ang), s = sinf(ang);
    size_t ibase = (size_t)l * OUT_FEAT + n * (NH * DD) + h * DD + i;
    float x1 = in[ibase], x2 = in[ibase + 8];
    size_t obase = (((size_t)(n * NH + h)) * L_SEQ + l) * DD + i;
    out[obase]     = x1 * c - x2 * s;
    out[obase + 8] = x2 * c + x1 * s;
}

// ------------------------- launcher -----------------------------------
extern "C" void kernel_launch(void* const* d_in, const int* in_sizes, int n_in,
                              void* d_out, int out_size)
{
    const float* x    = (const float*)d_in[0];
    const float* Wi   = (const float*)d_in[1];
    const float* Wq   = (const float*)d_in[2];
    const float* Wk   = (const float*)d_in[3];
    const float* Wv   = (const float*)d_in[4];
    const float* ln1w = (const float*)d_in[5];
    const float* ln1b = (const float*)d_in[6];
    const float* Wf1  = (const float*)d_in[7];
    const float* bf1  = (const float*)d_in[8];
    const float* Wf2  = (const float*)d_in[9];
    const float* bf2  = (const float*)d_in[10];
    const float* Wqi1 = (const float*)d_in[11];
    const float* Wqi2 = (const float*)d_in[12];
    const float* Wki1 = (const float*)d_in[13];
    const float* Wki2 = (const float*)d_in[14];
    float* out = (float*)d_out;

    float *hr,*q,*k,*v,*attn,*ln,*f1,*hid,*aq,*ak,*qi,*ki;
    cudaGetSymbolAddress((void**)&hr,   g_hr);
    cudaGetSymbolAddress((void**)&q,    g_q);
    cudaGetSymbolAddress((void**)&k,    g_k);
    cudaGetSymbolAddress((void**)&v,    g_v);
    cudaGetSymbolAddress((void**)&attn, g_attn);
    cudaGetSymbolAddress((void**)&ln,   g_ln);
    cudaGetSymbolAddress((void**)&f1,   g_f1);
    cudaGetSymbolAddress((void**)&hid,  g_hid);
    cudaGetSymbolAddress((void**)&aq,   g_aq);
    cudaGetSymbolAddress((void**)&ak,   g_ak);
    cudaGetSymbolAddress((void**)&qi,   g_qi);
    cudaGetSymbolAddress((void**)&ki,   g_ki);

    F16 t16; for (int i = 0; i < 16; i++) t16.f[i] = (float)(1.0 / pow(10000.0, (double)i / 16.0));
    F8  t8;  for (int i = 0; i < 8;  i++) t8.f[i]  = (float)(1.0 / pow(10000.0, (double)i / 8.0));

    // hr = x @ Wi^T
    sgemm_nt<0><<<dim3(HR_DIM/BN, L_SEQ/BM), 256>>>(x, Wi, hr, nullptr, nullptr, L_SEQ, HR_DIM, E_DIM);
    // q, k, v
    sgemm_nt<0><<<dim3(HR_DIM/BN, L_SEQ/BM), 256>>>(hr, Wq, q, nullptr, nullptr, L_SEQ, HR_DIM, HR_DIM);
    sgemm_nt<0><<<dim3(HR_DIM/BN, L_SEQ/BM), 256>>>(hr, Wk, k, nullptr, nullptr, L_SEQ, HR_DIM, HR_DIM);
    sgemm_nt<0><<<dim3(HR_DIM/BN, L_SEQ/BM), 256>>>(hr, Wv, v, nullptr, nullptr, L_SEQ, HR_DIM, HR_DIM);
    // RoPE on q,k
    rope_qk<<<(L_SEQ*NH*16)/256, 256>>>(q, k, t16);
    // causal attention
    attn_k<<<dim3(L_SEQ/4, NH), 128>>>(q, k, v, attn);
    // layernorm
    layernorm_k<<<L_SEQ, 256>>>(attn, ln1w, ln1b, ln);
    // ffn1: gelu(ln @ Wf1^T + bf1)
    sgemm_nt<1><<<dim3(2*HR_DIM/BN, L_SEQ/BM), 256>>>(ln, Wf1, f1, bf1, nullptr, L_SEQ, 2*HR_DIM, HR_DIM);
    // ffn2 + residual: hid = x + f1 @ Wf2^T + bf2
    sgemm_nt<2><<<dim3(E_DIM/BN, L_SEQ/BM), 256>>>(f1, Wf2, hid, bf2, x, L_SEQ, E_DIM, 2*HR_DIM);
    // silu projections
    sgemm_nt<3><<<dim3(HR_DIM/BN, L_SEQ/BM), 256>>>(hid, Wqi1, aq, nullptr, nullptr, L_SEQ, HR_DIM, E_DIM);
    sgemm_nt<3><<<dim3(HR_DIM/BN, L_SEQ/BM), 256>>>(hid, Wki1, ak, nullptr, nullptr, L_SEQ, HR_DIM, E_DIM);
    // importance projections
    sgemm_nt<0><<<dim3(OUT_FEAT/BN, L_SEQ/BM), 256>>>(aq, Wqi2, qi, nullptr, nullptr, L_SEQ, OUT_FEAT, HR_DIM);
    sgemm_nt<0><<<dim3(OUT_FEAT/BN, L_SEQ/BM), 256>>>(ak, Wki2, ki, nullptr, nullptr, L_SEQ, OUT_FEAT, HR_DIM);
    // RoPE + permute into output
    rope_perm<<<(NLAY*NH*L_SEQ*8)/256, 256>>>(qi, out, t8);
    rope_perm<<<(NLAY*NH*L_SEQ*8)/256, 256>>>(ki, out + (size_t)NLAY*NH*L_SEQ*DD, t8);
}

// round 2
// speedup vs baseline: 2.0714x; 2.0714x over previous
#include <cuda_runtime.h>
#include <math.h>
#include <stdint.h>

// ------------------------- problem dimensions -------------------------
#define L_SEQ   2048
#define E_DIM   4096
#define HR_DIM  1024
#define NH      32          // attention heads
#define D_ATT   32          // attention head dim
#define NLAY    32          // predicted layers
#define DD      16          // importance head dim
#define OUT_FEAT (NLAY*NH*DD)   // 16384

// ------------------------- scratch (static device mem) ----------------
__device__ float g_hr  [(size_t)L_SEQ*HR_DIM];
__device__ float g_q   [(size_t)L_SEQ*HR_DIM];
__device__ float g_k   [(size_t)L_SEQ*HR_DIM];
__device__ float g_v   [(size_t)L_SEQ*HR_DIM];
__device__ float g_attn[(size_t)L_SEQ*HR_DIM];
__device__ float g_ln  [(size_t)L_SEQ*HR_DIM];
__device__ float g_f1  [(size_t)L_SEQ*2*HR_DIM];
__device__ float g_hid [(size_t)L_SEQ*E_DIM];
__device__ float g_aq  [(size_t)L_SEQ*HR_DIM];
__device__ float g_ak  [(size_t)L_SEQ*HR_DIM];
__device__ float g_qi  [(size_t)L_SEQ*OUT_FEAT];
__device__ float g_ki  [(size_t)L_SEQ*OUT_FEAT];

struct F16 { float f[16]; };
struct F8  { float f[8];  };

// ------------------------- activation helpers -------------------------
__device__ __forceinline__ float gelu_f(float x) {
    return 0.5f * x * (1.0f + erff(x * 0.7071067811865476f));
}
__device__ __forceinline__ float silu_f(float x) {
    return x / (1.0f + expf(-x));
}
__device__ __forceinline__ uint32_t f2tf32(float x) {
    uint32_t r;
    asm("cvt.rna.tf32.f32 %0, %1;" : "=r"(r) : "f"(x));
    return r;
}
__device__ __forceinline__ void mma1688(float c[4], const uint32_t a[4], const uint32_t b[2]) {
    asm volatile(
        "mma.sync.aligned.m16n8k8.row.col.f32.tf32.tf32.f32 "
        "{%0,%1,%2,%3}, {%4,%5,%6,%7}, {%8,%9}, {%0,%1,%2,%3};"
        : "+f"(c[0]), "+f"(c[1]), "+f"(c[2]), "+f"(c[3])
        : "r"(a[0]), "r"(a[1]), "r"(a[2]), "r"(a[3]), "r"(b[0]), "r"(b[1]));
}

// ---------------- TF32 tensor-core GEMM: C[M,N] = A[M,K] * B[N,K]^T ---
// EPI: 0 = none, 1 = gelu(acc+bias), 2 = acc+bias+resid, 3 = silu(acc)
#define TBM 128
#define TBN 128
#define TBK 32
#define TPAD 4
#define TSTR (TBK + TPAD)   // 36 floats per smem row

template<int EPI>
__global__ __launch_bounds__(256)
void tgemm_nt(const float* __restrict__ A, const float* __restrict__ B,
              float* __restrict__ C,
              const float* __restrict__ bias, const float* __restrict__ resid,
              int M, int N, int K)
{
    __shared__ uint32_t As[TBM][TSTR];
    __shared__ uint32_t Bs[TBN][TSTR];

    const int tid  = threadIdx.x;
    const int wid  = tid >> 5;
    const int lane = tid & 31;
    const int g    = lane >> 2;      // group id 0..7
    const int tig  = lane & 3;       // thread-in-group 0..3
    const int wm   = (wid & 1) * 64; // warp m offset (2 warps in m)
    const int wn   = (wid >> 1) * 32;// warp n offset (4 warps in n)
    const int bm   = blockIdx.y * TBM;
    const int bn   = blockIdx.x * TBN;

    float acc[4][4][4];
#pragma unroll
    for (int mi = 0; mi < 4; mi++)
#pragma unroll
        for (int ni = 0; ni < 4; ni++)
#pragma unroll
            for (int c = 0; c < 4; c++) acc[mi][ni][c] = 0.0f;

    for (int k0 = 0; k0 < K; k0 += TBK) {
        // load + convert A,B tiles (128x32 each)
#pragma unroll
        for (int i = 0; i < 4; i++) {
            int id  = tid + i * 256;
            int row = id >> 3;
            int c4  = (id & 7) << 2;
            float4 a = *reinterpret_cast<const float4*>(A + (size_t)(bm + row) * K + k0 + c4);
            As[row][c4+0] = f2tf32(a.x); As[row][c4+1] = f2tf32(a.y);
            As[row][c4+2] = f2tf32(a.z); As[row][c4+3] = f2tf32(a.w);
            float4 b = *reinterpret_cast<const float4*>(B + (size_t)(bn + row) * K + k0 + c4);
            Bs[row][c4+0] = f2tf32(b.x); Bs[row][c4+1] = f2tf32(b.y);
            Bs[row][c4+2] = f2tf32(b.z); Bs[row][c4+3] = f2tf32(b.w);
        }
        __syncthreads();

#pragma unroll
        for (int kk = 0; kk < 4; kk++) {
            const int kb = kk * 8;
            uint32_t af[4][4], bf[4][2];
#pragma unroll
            for (int mi = 0; mi < 4; mi++) {
                int r0 = wm + mi * 16 + g;
                af[mi][0] = As[r0    ][kb + tig];
                af[mi][1] = As[r0 + 8][kb + tig];
                af[mi][2] = As[r0    ][kb + tig + 4];
                af[mi][3] = As[r0 + 8][kb + tig + 4];
            }
#pragma unroll
            for (int ni = 0; ni < 4; ni++) {
                int r0 = wn + ni * 8 + g;
                bf[ni][0] = Bs[r0][kb + tig];
                bf[ni][1] = Bs[r0][kb + tig + 4];
            }
#pragma unroll
            for (int mi = 0; mi < 4; mi++)
#pragma unroll
                for (int ni = 0; ni < 4; ni++)
                    mma1688(acc[mi][ni], af[mi], bf[ni]);
        }
        __syncthreads();
    }

    // epilogue: c0 (g,2t), c1 (g,2t+1), c2 (g+8,2t), c3 (g+8,2t+1)
#pragma unroll
    for (int mi = 0; mi < 4; mi++) {
#pragma unroll
        for (int ni = 0; ni < 4; ni++) {
            int m0 = bm + wm + mi * 16 + g;
            int n0 = bn + wn + ni * 8 + tig * 2;
#pragma unroll
            for (int half = 0; half < 2; half++) {
                int m = m0 + half * 8;
                size_t off = (size_t)m * N + n0;
                float v0 = acc[mi][ni][half * 2 + 0];
                float v1 = acc[mi][ni][half * 2 + 1];
                if (EPI == 1) {
                    v0 = gelu_f(v0 + bias[n0]); v1 = gelu_f(v1 + bias[n0 + 1]);
                } else if (EPI == 2) {
                    v0 = v0 + bias[n0] + resid[off];
                    v1 = v1 + bias[n0 + 1] + resid[off + 1];
                } else if (EPI == 3) {
                    v0 = silu_f(v0); v1 = silu_f(v1);
                }
                *reinterpret_cast<float2*>(C + off) = make_float2(v0, v1);
            }
        }
    }
}

// ------------------------- RoPE on q,k (in-place, head dim 32) --------
__global__ __launch_bounds__(256)
void rope_qk(float* __restrict__ q, float* __restrict__ k, F16 ft)
{
    int idx = blockIdx.x * blockDim.x + threadIdx.x;   // L*NH*16 = 1,048,576
    int i = idx & 15;
    int h = (idx >> 4) & 31;
    int l = idx >> 9;
    float ang = (float)l * ft.f[i];
    float c = cosf(ang), s = sinf(ang);
    size_t base = (size_t)l * HR_DIM + h * D_ATT + i;
    float x1 = q[base], x2 = q[base + 16];
    q[base]      = x1 * c - x2 * s;
    q[base + 16] = x2 * c + x1 * s;
    float y1 = k[base], y2 = k[base + 16];
    k[base]      = y1 * c - y2 * s;
    k[base + 16] = y2 * c + y1 * s;
}

// ------------------------- causal attention ---------------------------
#define ACH 128
__global__ __launch_bounds__(128)
void attn_k(const float* __restrict__ Q, const float* __restrict__ K,
            const float* __restrict__ V, float* __restrict__ O)
{
    __shared__ float Ks[ACH][33];
    __shared__ float Vs[ACH][33];
    const int h = blockIdx.y;
    const int qbase = blockIdx.x * 4;
    const int lane = threadIdx.x & 31;
    const int wid  = threadIdx.x >> 5;
    const int l = qbase + wid;

    float qreg = Q[(size_t)l * HR_DIM + h * D_ATT + lane] * 0.17677669529663687f;
    float m = -INFINITY, ssum = 0.0f, acc = 0.0f;
    const int lmax = qbase + 3;

    for (int j0 = 0; j0 <= lmax; j0 += ACH) {
        for (int t = threadIdx.x; t < ACH * 32; t += 128) {
            int r = t >> 5, c = t & 31;
            size_t gi = (size_t)(j0 + r) * HR_DIM + h * D_ATT + c;
            Ks[r][c] = K[gi];
            Vs[r][c] = V[gi];
        }
        __syncthreads();
        if (j0 <= l) {
#pragma unroll 1
            for (int jj = 0; jj < ACH; jj += 32) {
                int j = j0 + jj + lane;
                float s = 0.0f;
#pragma unroll
                for (int d = 0; d < 32; d++)
                    s = fmaf(__shfl_sync(0xffffffffu, qreg, d), Ks[jj + lane][d], s);
                if (j > l) s = -1e30f;
                float mc = s;
#pragma unroll
                for (int o = 16; o; o >>= 1) mc = fmaxf(mc, __shfl_xor_sync(0xffffffffu, mc, o));
                float mnew = fmaxf(m, mc);
                float alpha = expf(m - mnew);
                float p = expf(s - mnew);
                float psum = p;
#pragma unroll
                for (int o = 16; o; o >>= 1) psum += __shfl_xor_sync(0xffffffffu, psum, o);
                ssum = ssum * alpha + psum;
                acc *= alpha;
#pragma unroll
                for (int j2 = 0; j2 < 32; j2++)
                    acc = fmaf(__shfl_sync(0xffffffffu, p, j2), Vs[jj + j2][lane], acc);
                m = mnew;
            }
        }
        __syncthreads();
    }
    O[(size_t)l * HR_DIM + h * D_ATT + lane] = acc / ssum;
}

// ------------------------- LayerNorm (rows of 1024) -------------------
__global__ __launch_bounds__(256)
void layernorm_k(const float* __restrict__ in, const float* __restrict__ w,
                 const float* __restrict__ b, float* __restrict__ out)
{
    __shared__ float red[8];
    const int row = blockIdx.x;
    const int tid = threadIdx.x;
    const int lane = tid & 31, wid = tid >> 5;
    float4 v = reinterpret_cast<const float4*>(in + (size_t)row * HR_DIM)[tid];

    float s = v.x + v.y + v.z + v.w;
#pragma unroll
    for (int o = 16; o; o >>= 1) s += __shfl_xor_sync(0xffffffffu, s, o);
    if (lane == 0) red[wid] = s;
    __syncthreads();
    float tot = red[0]+red[1]+red[2]+red[3]+red[4]+red[5]+red[6]+red[7];
    float mu = tot * (1.0f / HR_DIM);

    float dx0 = v.x - mu, dx1 = v.y - mu, dx2 = v.z - mu, dx3 = v.w - mu;
    float sq = dx0*dx0 + dx1*dx1 + dx2*dx2 + dx3*dx3;
#pragma unroll
    for (int o = 16; o; o >>= 1) sq += __shfl_xor_sync(0xffffffffu, sq, o);
    __syncthreads();
    if (lane == 0) red[wid] = sq;
    __syncthreads();
    float var = (red[0]+red[1]+red[2]+red[3]+red[4]+red[5]+red[6]+red[7]) * (1.0f / HR_DIM);
    float rstd = rsqrtf(var + 1e-5f);

    float4 wv = reinterpret_cast<const float4*>(w)[tid];
    float4 bv = reinterpret_cast<const float4*>(b)[tid];
    float4 o4;
    o4.x = dx0 * rstd * wv.x + bv.x;
    o4.y = dx1 * rstd * wv.y + bv.y;
    o4.z = dx2 * rstd * wv.z + bv.z;
    o4.w = dx3 * rstd * wv.w + bv.w;
    reinterpret_cast<float4*>(out + (size_t)row * HR_DIM)[tid] = o4;
}

// ---------------- importance RoPE + permute to (N,H,L,DD) -------------
__global__ __launch_bounds__(256)
void rope_perm(const float* __restrict__ in, float* __restrict__ out, F8 ft)
{
    int idx = blockIdx.x * blockDim.x + threadIdx.x;   // NLAY*NH*L*8 = 16,777,216
    int i = idx & 7;
    int l = (idx >> 3) & 2047;
    int h = (idx >> 14) & 31;
    int n = idx >> 19;
    float ang = (float)l * ft.f[i];
    float c = cosf(ang), s = sinf(ang);
    size_t ibase = (size_t)l * OUT_FEAT + n * (NH * DD) + h * DD + i;
    float x1 = in[ibase], x2 = in[ibase + 8];
    size_t obase = (((size_t)(n * NH + h)) * L_SEQ + l) * DD + i;
    out[obase]     = x1 * c - x2 * s;
    out[obase + 8] = x2 * c + x1 * s;
}

// ------------------------- launcher -----------------------------------
extern "C" void kernel_launch(void* const* d_in, const int* in_sizes, int n_in,
                              void* d_out, int out_size)
{
    const float* x    = (const float*)d_in[0];
    const float* Wi   = (const float*)d_in[1];
    const float* Wq   = (const float*)d_in[2];
    const float* Wk   = (const float*)d_in[3];
    const float* Wv   = (const float*)d_in[4];
    const float* ln1w = (const float*)d_in[5];
    const float* ln1b = (const float*)d_in[6];
    const float* Wf1  = (const float*)d_in[7];
    const float* bf1  = (const float*)d_in[8];
    const float* Wf2  = (const float*)d_in[9];
    const float* bf2  = (const float*)d_in[10];
    const float* Wqi1 = (const float*)d_in[11];
    const float* Wqi2 = (const float*)d_in[12];
    const float* Wki1 = (const float*)d_in[13];
    const float* Wki2 = (const float*)d_in[14];
    float* out = (float*)d_out;

    float *hr,*q,*k,*v,*attn,*ln,*f1,*hid,*aq,*ak,*qi,*ki;
    cudaGetSymbolAddress((void**)&hr,   g_hr);
    cudaGetSymbolAddress((void**)&q,    g_q);
    cudaGetSymbolAddress((void**)&k,    g_k);
    cudaGetSymbolAddress((void**)&v,    g_v);
    cudaGetSymbolAddress((void**)&attn, g_attn);
    cudaGetSymbolAddress((void**)&ln,   g_ln);
    cudaGetSymbolAddress((void**)&f1,   g_f1);
    cudaGetSymbolAddress((void**)&hid,  g_hid);
    cudaGetSymbolAddress((void**)&aq,   g_aq);
    cudaGetSymbolAddress((void**)&ak,   g_ak);
    cudaGetSymbolAddress((void**)&qi,   g_qi);
    cudaGetSymbolAddress((void**)&ki,   g_ki);

    F16 t16; for (int i = 0; i < 16; i++) t16.f[i] = (float)(1.0 / pow(10000.0, (double)i / 16.0));
    F8  t8;  for (int i = 0; i < 8;  i++) t8.f[i]  = (float)(1.0 / pow(10000.0, (double)i / 8.0));

    // hr = x @ Wi^T
    tgemm_nt<0><<<dim3(HR_DIM/TBN, L_SEQ/TBM), 256>>>(x, Wi, hr, nullptr, nullptr, L_SEQ, HR_DIM, E_DIM);
    // q, k, v
    tgemm_nt<0><<<dim3(HR_DIM/TBN, L_SEQ/TBM), 256>>>(hr, Wq, q, nullptr, nullptr, L_SEQ, HR_DIM, HR_DIM);
    tgemm_nt<0><<<dim3(HR_DIM/TBN, L_SEQ/TBM), 256>>>(hr, Wk, k, nullptr, nullptr, L_SEQ, HR_DIM, HR_DIM);
    tgemm_nt<0><<<dim3(HR_DIM/TBN, L_SEQ/TBM), 256>>>(hr, Wv, v, nullptr, nullptr, L_SEQ, HR_DIM, HR_DIM);
    // RoPE on q,k
    rope_qk<<<(L_SEQ*NH*16)/256, 256>>>(q, k, t16);
    // causal attention
    attn_k<<<dim3(L_SEQ/4, NH), 128>>>(q, k, v, attn);
    // layernorm
    layernorm_k<<<L_SEQ, 256>>>(attn, ln1w, ln1b, ln);
    // ffn1: gelu(ln @ Wf1^T + bf1)
    tgemm_nt<1><<<dim3(2*HR_DIM/TBN, L_SEQ/TBM), 256>>>(ln, Wf1, f1, bf1, nullptr, L_SEQ, 2*HR_DIM, HR_DIM);
    // ffn2 + residual: hid = x + f1 @ Wf2^T + bf2
    tgemm_nt<2><<<dim3(E_DIM/TBN, L_SEQ/TBM), 256>>>(f1, Wf2, hid, bf2, x, L_SEQ, E_DIM, 2*HR_DIM);
    // silu projections
    tgemm_nt<3><<<dim3(HR_DIM/TBN, L_SEQ/TBM), 256>>>(hid, Wqi1, aq, nullptr, nullptr, L_SEQ, HR_DIM, E_DIM);
    tgemm_nt<3><<<dim3(HR_DIM/TBN, L_SEQ/TBM), 256>>>(hid, Wki1, ak, nullptr, nullptr, L_SEQ, HR_DIM, E_DIM);
    // importance projections
    tgemm_nt<0><<<dim3(OUT_FEAT/TBN, L_SEQ/TBM), 256>>>(aq, Wqi2, qi, nullptr, nullptr, L_SEQ, OUT_FEAT, HR_DIM);
    tgemm_nt<0><<<dim3(OUT_FEAT/TBN, L_SEQ/TBM), 256>>>(ak, Wki2, ki, nullptr, nullptr, L_SEQ, OUT_FEAT, HR_DIM);
    // RoPE + permute into output
    rope_perm<<<(NLAY*NH*L_SEQ*8)/256, 256>>>(qi, out, t8);
    rope_perm<<<(NLAY*NH*L_SEQ*8)/256, 256>>>(ki, out + (size_t)NLAY*NH*L_SEQ*DD, t8);
}

// round 3
// speedup vs baseline: 2.1395x; 1.0329x over previous
#include <cuda_runtime.h>
#include <math.h>
#include <stdint.h>

// ------------------------- problem dimensions -------------------------
#define L_SEQ   2048
#define E_DIM   4096
#define HR_DIM  1024
#define NH      32          // attention heads
#define D_ATT   32          // attention head dim
#define NLAY    32          // predicted layers
#define DD      16          // importance head dim
#define OUT_FEAT (NLAY*NH*DD)   // 16384

// ------------------------- scratch (static device mem) ----------------
__device__ float g_hr  [(size_t)L_SEQ*HR_DIM];
__device__ float g_q   [(size_t)L_SEQ*HR_DIM];
__device__ float g_k   [(size_t)L_SEQ*HR_DIM];
__device__ float g_v   [(size_t)L_SEQ*HR_DIM];
__device__ float g_attn[(size_t)L_SEQ*HR_DIM];
__device__ float g_ln  [(size_t)L_SEQ*HR_DIM];
__device__ float g_f1  [(size_t)L_SEQ*2*HR_DIM];
__device__ float g_hid [(size_t)L_SEQ*E_DIM];
__device__ float g_aq  [(size_t)L_SEQ*HR_DIM];
__device__ float g_ak  [(size_t)L_SEQ*HR_DIM];
__device__ float g_qi  [(size_t)L_SEQ*OUT_FEAT];
__device__ float g_ki  [(size_t)L_SEQ*OUT_FEAT];

struct F16 { float f[16]; };
struct F8  { float f[8];  };
struct GArgs { const float* A[3]; const float* B[3]; float* C[3]; };

// ------------------------- activation helpers -------------------------
__device__ __forceinline__ float gelu_f(float x) {
    return 0.5f * x * (1.0f + erff(x * 0.7071067811865476f));
}
__device__ __forceinline__ float silu_f(float x) {
    return x / (1.0f + expf(-x));
}
__device__ __forceinline__ uint32_t f2tf32(float x) {
    uint32_t r;
    asm("cvt.rna.tf32.f32 %0, %1;" : "=r"(r) : "f"(x));
    return r;
}
__device__ __forceinline__ void mma1688(float c[4], const uint32_t a[4], const uint32_t b[2]) {
    asm volatile(
        "mma.sync.aligned.m16n8k8.row.col.f32.tf32.tf32.f32 "
        "{%0,%1,%2,%3}, {%4,%5,%6,%7}, {%8,%9}, {%0,%1,%2,%3};"
        : "+f"(c[0]), "+f"(c[1]), "+f"(c[2]), "+f"(c[3])
        : "r"(a[0]), "r"(a[1]), "r"(a[2]), "r"(a[3]), "r"(b[0]), "r"(b[1]));
}

// ---------------- fragment-ordered smem writers -----------------------
// A: float4 per (block,lane): {a0,a1,a2,a3}; block = R*4+kk; phys lane = logical^f(kk)
__device__ __forceinline__ void st_a(uint32_t* buf, int r, int k4, float4 a) {
    int R = r >> 4, g = r & 7, b = (r >> 3) & 1;
    int kk = k4 >> 3, hi = (k4 >> 2) & 1;
    int f = kk ^ (kk << 2);
    int base = ((R * 4 + kk) * 32) * 4 + b + (hi << 1);
    buf[base + (((g * 4 + 0) ^ f) << 2)] = f2tf32(a.x);
    buf[base + (((g * 4 + 1) ^ f) << 2)] = f2tf32(a.y);
    buf[base + (((g * 4 + 2) ^ f) << 2)] = f2tf32(a.z);
    buf[base + (((g * 4 + 3) ^ f) << 2)] = f2tf32(a.w);
}
// B: float2 per (block,lane): {b0,b1}; block = Rb*4+kk
__device__ __forceinline__ void st_b(uint32_t* buf, int r, int k4, float4 b) {
    int Rb = r >> 3, g = r & 7;
    int kk = k4 >> 3, hi = (k4 >> 2) & 1;
    int f = kk ^ (kk << 2);
    int base = ((Rb * 4 + kk) * 32) * 2 + hi;
    buf[base + (((g * 4 + 0) ^ f) << 1)] = f2tf32(b.x);
    buf[base + (((g * 4 + 1) ^ f) << 1)] = f2tf32(b.y);
    buf[base + (((g * 4 + 2) ^ f) << 1)] = f2tf32(b.z);
    buf[base + (((g * 4 + 3) ^ f) << 1)] = f2tf32(b.w);
}

// ---------------- TF32 GEMM: C[2048,N] = A[2048,K] * B[N,K]^T ---------
// tile 128x64x32, 8 warps (4m x 2n), warp tile 32x32, double-buffered.
// EPI: 0 none, 1 gelu(acc+bias), 2 acc+bias+resid, 3 silu(acc)
template<int EPI>
__global__ __launch_bounds__(256)
void tgemm(GArgs ga, const float* __restrict__ bias,
           const float* __restrict__ resid, int N, int K)
{
    constexpr int MI = 2, NI = 4;
    __shared__ uint32_t As2[2][4096];   // 128x32 frag-ordered
    __shared__ uint32_t Bs2[2][2048];   // 64x32 frag-ordered

    const float* __restrict__ A = ga.A[blockIdx.z];
    const float* __restrict__ B = ga.B[blockIdx.z];
    float* __restrict__ C = ga.C[blockIdx.z];

    const int tid = threadIdx.x, wid = tid >> 5, lane = tid & 31;
    const int g = lane >> 2, tig = lane & 3;
    const int wmi = wid & 3, wni = wid >> 2;
    const int bm = blockIdx.y * 128, bn = blockIdx.x * 64;

    const float* Abase = A + (size_t)bm * K;
    const float* Bbase = B + (size_t)bn * K;

    float acc[MI][NI][4];
#pragma unroll
    for (int mi = 0; mi < MI; mi++)
#pragma unroll
        for (int ni = 0; ni < NI; ni++)
#pragma unroll
            for (int c = 0; c < 4; c++) acc[mi][ni][c] = 0.0f;

    // prologue: fill stage 0
#pragma unroll
    for (int i = 0; i < 4; i++) {
        int id = tid + i * 256, r = id >> 3, k4 = (id & 7) << 2;
        st_a(As2[0], r, k4, *reinterpret_cast<const float4*>(Abase + (size_t)r * K + k4));
    }
#pragma unroll
    for (int i = 0; i < 2; i++) {
        int id = tid + i * 256, r = id >> 3, k4 = (id & 7) << 2;
        st_b(Bs2[0], r, k4, *reinterpret_cast<const float4*>(Bbase + (size_t)r * K + k4));
    }
    __syncthreads();

    const int T = K >> 5;
    for (int t = 0; t < T; t++) {
        const int cur = t & 1, nxt = (t + 1) & 1;
        const bool has = (t + 1 < T);
        float4 ra[4], rb[2];
        if (has) {
            const int k0 = (t + 1) << 5;
#pragma unroll
            for (int i = 0; i < 4; i++) {
                int id = tid + i * 256, r = id >> 3, k4 = (id & 7) << 2;
                ra[i] = *reinterpret_cast<const float4*>(Abase + (size_t)r * K + k0 + k4);
            }
#pragma unroll
            for (int i = 0; i < 2; i++) {
                int id = tid + i * 256, r = id >> 3, k4 = (id & 7) << 2;
                rb[i] = *reinterpret_cast<const float4*>(Bbase + (size_t)r * K + k0 + k4);
            }
        }

#pragma unroll
        for (int kk = 0; kk < 4; kk++) {
            const int lx = lane ^ (kk ^ (kk << 2));
            uint32_t af[MI][4], bf[NI][2];
#pragma unroll
            for (int mi = 0; mi < MI; mi++) {
                uint4 v = *reinterpret_cast<const uint4*>(
                    &As2[cur][(((wmi * MI + mi) * 4 + kk) * 32 + lx) * 4]);
                af[mi][0] = v.x; af[mi][1] = v.y; af[mi][2] = v.z; af[mi][3] = v.w;
            }
#pragma unroll
            for (int ni = 0; ni < NI; ni++) {
                uint2 v = *reinterpret_cast<const uint2*>(
                    &Bs2[cur][(((wni * NI + ni) * 4 + kk) * 32 + lx) * 2]);
                bf[ni][0] = v.x; bf[ni][1] = v.y;
            }
#pragma unroll
            for (int mi = 0; mi < MI; mi++)
#pragma unroll
                for (int ni = 0; ni < NI; ni++)
                    mma1688(acc[mi][ni], af[mi], bf[ni]);
        }

        if (has) {
#pragma unroll
            for (int i = 0; i < 4; i++) {
                int id = tid + i * 256, r = id >> 3, k4 = (id & 7) << 2;
                st_a(As2[nxt], r, k4, ra[i]);
            }
#pragma unroll
            for (int i = 0; i < 2; i++) {
                int id = tid + i * 256, r = id >> 3, k4 = (id & 7) << 2;
                st_b(Bs2[nxt], r, k4, rb[i]);
            }
        }
        __syncthreads();
    }

    // epilogue
    const int wm = wmi * 32, wn = wni * 32;
#pragma unroll
    for (int mi = 0; mi < MI; mi++) {
#pragma unroll
        for (int ni = 0; ni < NI; ni++) {
            int m0 = bm + wm + mi * 16 + g;
            int n0 = bn + wn + ni * 8 + tig * 2;
#pragma unroll
            for (int half = 0; half < 2; half++) {
                int m = m0 + half * 8;
                size_t off = (size_t)m * N + n0;
                float v0 = acc[mi][ni][half * 2 + 0];
                float v1 = acc[mi][ni][half * 2 + 1];
                if (EPI == 1) {
                    v0 = gelu_f(v0 + bias[n0]); v1 = gelu_f(v1 + bias[n0 + 1]);
                } else if (EPI == 2) {
                    v0 = v0 + bias[n0] + resid[off];
                    v1 = v1 + bias[n0 + 1] + resid[off + 1];
                } else if (EPI == 3) {
                    v0 = silu_f(v0); v1 = silu_f(v1);
                }
                *reinterpret_cast<float2*>(C + off) = make_float2(v0, v1);
            }
        }
    }
}

// ------------------------- RoPE on q,k (in-place, head dim 32) --------
__global__ __launch_bounds__(256)
void rope_qk(float* __restrict__ q, float* __restrict__ k, F16 ft)
{
    int idx = blockIdx.x * blockDim.x + threadIdx.x;
    int i = idx & 15;
    int h = (idx >> 4) & 31;
    int l = idx >> 9;
    float ang = (float)l * ft.f[i];
    float c = cosf(ang), s = sinf(ang);
    size_t base = (size_t)l * HR_DIM + h * D_ATT + i;
    float x1 = q[base], x2 = q[base + 16];
    q[base]      = x1 * c - x2 * s;
    q[base + 16] = x2 * c + x1 * s;
    float y1 = k[base], y2 = k[base + 16];
    k[base]      = y1 * c - y2 * s;
    k[base + 16] = y2 * c + y1 * s;
}

// ------------------------- causal attention ---------------------------
#define ACH 128
__global__ __launch_bounds__(128)
void attn_k(const float* __restrict__ Q, const float* __restrict__ K,
            const float* __restrict__ V, float* __restrict__ O)
{
    __shared__ float Ks[ACH][33];
    __shared__ float Vs[ACH][33];
    const int h = blockIdx.y;
    const int qbase = blockIdx.x * 4;
    const int lane = threadIdx.x & 31;
    const int wid  = threadIdx.x >> 5;
    const int l = qbase + wid;

    float qreg = Q[(size_t)l * HR_DIM + h * D_ATT + lane] * 0.17677669529663687f;
    float m = -INFINITY, ssum = 0.0f, acc = 0.0f;
    const int lmax = qbase + 3;

    for (int j0 = 0; j0 <= lmax; j0 += ACH) {
        for (int t = threadIdx.x; t < ACH * 32; t += 128) {
            int r = t >> 5, c = t & 31;
            size_t gi = (size_t)(j0 + r) * HR_DIM + h * D_ATT + c;
            Ks[r][c] = K[gi];
            Vs[r][c] = V[gi];
        }
        __syncthreads();
        if (j0 <= l) {
#pragma unroll 1
            for (int jj = 0; jj < ACH; jj += 32) {
                int j = j0 + jj + lane;
                float s = 0.0f;
#pragma unroll
                for (int d = 0; d < 32; d++)
                    s = fmaf(__shfl_sync(0xffffffffu, qreg, d), Ks[jj + lane][d], s);
                if (j > l) s = -1e30f;
                float mc = s;
#pragma unroll
                for (int o = 16; o; o >>= 1) mc = fmaxf(mc, __shfl_xor_sync(0xffffffffu, mc, o));
                float mnew = fmaxf(m, mc);
                float alpha = expf(m - mnew);
                float p = expf(s - mnew);
                float psum = p;
#pragma unroll
                for (int o = 16; o; o >>= 1) psum += __shfl_xor_sync(0xffffffffu, psum, o);
                ssum = ssum * alpha + psum;
                acc *= alpha;
#pragma unroll
                for (int j2 = 0; j2 < 32; j2++)
                    acc = fmaf(__shfl_sync(0xffffffffu, p, j2), Vs[jj + j2][lane], acc);
                m = mnew;
            }
        }
        __syncthreads();
    }
    O[(size_t)l * HR_DIM + h * D_ATT + lane] = acc / ssum;
}

// ------------------------- LayerNorm (rows of 1024) -------------------
__global__ __launch_bounds__(256)
void layernorm_k(const float* __restrict__ in, const float* __restrict__ w,
                 const float* __restrict__ b, float* __restrict__ out)
{
    __shared__ float red[8];
    const int row = blockIdx.x;
    const int tid = threadIdx.x;
    const int lane = tid & 31, wid = tid >> 5;
    float4 v = reinterpret_cast<const float4*>(in + (size_t)row * HR_DIM)[tid];

    float s = v.x + v.y + v.z + v.w;
#pragma unroll
    for (int o = 16; o; o >>= 1) s += __shfl_xor_sync(0xffffffffu, s, o);
    if (lane == 0) red[wid] = s;
    __syncthreads();
    float tot = red[0]+red[1]+red[2]+red[3]+red[4]+red[5]+red[6]+red[7];
    float mu = tot * (1.0f / HR_DIM);

    float dx0 = v.x - mu, dx1 = v.y - mu, dx2 = v.z - mu, dx3 = v.w - mu;
    float sq = dx0*dx0 + dx1*dx1 + dx2*dx2 + dx3*dx3;
#pragma unroll
    for (int o = 16; o; o >>= 1) sq += __shfl_xor_sync(0xffffffffu, sq, o);
    __syncthreads();
    if (lane == 0) red[wid] = sq;
    __syncthreads();
    float var = (red[0]+red[1]+red[2]+red[3]+red[4]+red[5]+red[6]+red[7]) * (1.0f / HR_DIM);
    float rstd = rsqrtf(var + 1e-5f);

    float4 wv = reinterpret_cast<const float4*>(w)[tid];
    float4 bv = reinterpret_cast<const float4*>(b)[tid];
    float4 o4;
    o4.x = dx0 * rstd * wv.x + bv.x;
    o4.y = dx1 * rstd * wv.y + bv.y;
    o4.z = dx2 * rstd * wv.z + bv.z;
    o4.w = dx3 * rstd * wv.w + bv.w;
    reinterpret_cast<float4*>(out + (size_t)row * HR_DIM)[tid] = o4;
}

// ---------------- importance RoPE + permute to (N,H,L,DD) -------------
__global__ __launch_bounds__(256)
void rope_perm(const float* __restrict__ in, float* __restrict__ out, F8 ft)
{
    int idx = blockIdx.x * blockDim.x + threadIdx.x;
    int i = idx & 7;
    int l = (idx >> 3) & 2047;
    int h = (idx >> 14) & 31;
    int n = idx >> 19;
    float ang = (float)l * ft.f[i];
    float c = cosf(ang), s = sinf(ang);
    size_t ibase = (size_t)l * OUT_FEAT + n * (NH * DD) + h * DD + i;
    float x1 = in[ibase], x2 = in[ibase + 8];
    size_t obase = (((size_t)(n * NH + h)) * L_SEQ + l) * DD + i;
    out[obase]     = x1 * c - x2 * s;
    out[obase + 8] = x2 * c + x1 * s;
}

// ------------------------- launcher -----------------------------------
extern "C" void kernel_launch(void* const* d_in, const int* in_sizes, int n_in,
                              void* d_out, int out_size)
{
    const float* x    = (const float*)d_in[0];
    const float* Wi   = (const float*)d_in[1];
    const float* Wq   = (const float*)d_in[2];
    const float* Wk   = (const float*)d_in[3];
    const float* Wv   = (const float*)d_in[4];
    const float* ln1w = (const float*)d_in[5];
    const float* ln1b = (const float*)d_in[6];
    const float* Wf1  = (const float*)d_in[7];
    const float* bf1  = (const float*)d_in[8];
    const float* Wf2  = (const float*)d_in[9];
    const float* bf2  = (const float*)d_in[10];
    const float* Wqi1 = (const float*)d_in[11];
    const float* Wqi2 = (const float*)d_in[12];
    const float* Wki1 = (const float*)d_in[13];
    const float* Wki2 = (const float*)d_in[14];
    float* out = (float*)d_out;

    float *hr,*q,*k,*v,*attn,*ln,*f1,*hid,*aq,*ak,*qi,*ki;
    cudaGetSymbolAddress((void**)&hr,   g_hr);
    cudaGetSymbolAddress((void**)&q,    g_q);
    cudaGetSymbolAddress((void**)&k,    g_k);
    cudaGetSymbolAddress((void**)&v,    g_v);
    cudaGetSymbolAddress((void**)&attn, g_attn);
    cudaGetSymbolAddress((void**)&ln,   g_ln);
    cudaGetSymbolAddress((void**)&f1,   g_f1);
    cudaGetSymbolAddress((void**)&hid,  g_hid);
    cudaGetSymbolAddress((void**)&aq,   g_aq);
    cudaGetSymbolAddress((void**)&ak,   g_ak);
    cudaGetSymbolAddress((void**)&qi,   g_qi);
    cudaGetSymbolAddress((void**)&ki,   g_ki);

    F16 t16; for (int i = 0; i < 16; i++) t16.f[i] = (float)(1.0 / pow(10000.0, (double)i / 16.0));
    F8  t8;  for (int i = 0; i < 8;  i++) t8.f[i]  = (float)(1.0 / pow(10000.0, (double)i / 8.0));

    GArgs ga;

    // hr = x @ Wi^T
    ga.A[0] = x; ga.B[0] = Wi; ga.C[0] = hr;
    tgemm<0><<<dim3(HR_DIM/64, 16, 1), 256>>>(ga, nullptr, nullptr, HR_DIM, E_DIM);

    // q, k, v (batched over z)
    ga.A[0] = hr; ga.A[1] = hr; ga.A[2] = hr;
    ga.B[0] = Wq; ga.B[1] = Wk; ga.B[2] = Wv;
    ga.C[0] = q;  ga.C[1] = k;  ga.C[2] = v;
    tgemm<0><<<dim3(HR_DIM/64, 16, 3), 256>>>(ga, nullptr, nullptr, HR_DIM, HR_DIM);

    rope_qk<<<(L_SEQ*NH*16)/256, 256>>>(q, k, t16);
    attn_k<<<dim3(L_SEQ/4, NH), 128>>>(q, k, v, attn);
    layernorm_k<<<L_SEQ, 256>>>(attn, ln1w, ln1b, ln);

    // ffn1: gelu(ln @ Wf1^T + bf1)
    ga.A[0] = ln; ga.B[0] = Wf1; ga.C[0] = f1;
    tgemm<1><<<dim3(2*HR_DIM/64, 16, 1), 256>>>(ga, bf1, nullptr, 2*HR_DIM, HR_DIM);

    // ffn2 + residual: hid = x + f1 @ Wf2^T + bf2
    ga.A[0] = f1; ga.B[0] = Wf2; ga.C[0] = hid;
    tgemm<2><<<dim3(E_DIM/64, 16, 1), 256>>>(ga, bf2, x, E_DIM, 2*HR_DIM);

    // silu projections (batched)
    ga.A[0] = hid; ga.A[1] = hid;
    ga.B[0] = Wqi1; ga.B[1] = Wki1;
    ga.C[0] = aq;  ga.C[1] = ak;
    tgemm<3><<<dim3(HR_DIM/64, 16, 2), 256>>>(ga, nullptr, nullptr, HR_DIM, E_DIM);

    // importance projections (batched)
    ga.A[0] = aq; ga.A[1] = ak;
    ga.B[0] = Wqi2; ga.B[1] = Wki2;
    ga.C[0] = qi;  ga.C[1] = ki;
    tgemm<0><<<dim3(OUT_FEAT/64, 16, 2), 256>>>(ga, nullptr, nullptr, OUT_FEAT, HR_DIM);

    rope_perm<<<(NLAY*NH*L_SEQ*8)/256, 256>>>(qi, out, t8);
    rope_perm<<<(NLAY*NH*L_SEQ*8)/256, 256>>>(ki, out + (size_t)NLAY*NH*L_SEQ*DD, t8);
}

// round 4
// speedup vs baseline: 2.4192x; 1.1308x over previous
#include <cuda_runtime.h>
#include <math.h>
#include <stdint.h>

// ------------------------- problem dimensions -------------------------
#define L_SEQ   2048
#define E_DIM   4096
#define HR_DIM  1024
#define NH      32
#define D_ATT   32
#define NLAY    32
#define DD      16
#define OUT_FEAT (NLAY*NH*DD)   // 16384

// ------------------------- scratch (static device mem) ----------------
__device__ float g_hr  [(size_t)L_SEQ*HR_DIM];
__device__ float g_q   [(size_t)L_SEQ*HR_DIM];
__device__ float g_k   [(size_t)L_SEQ*HR_DIM];
__device__ float g_v   [(size_t)L_SEQ*HR_DIM];
__device__ float g_attn[(size_t)L_SEQ*HR_DIM];
__device__ float g_ln  [(size_t)L_SEQ*HR_DIM];
__device__ float g_f1  [(size_t)L_SEQ*2*HR_DIM];
__device__ float g_hid [(size_t)L_SEQ*E_DIM];
__device__ float g_aq  [(size_t)L_SEQ*HR_DIM];
__device__ float g_ak  [(size_t)L_SEQ*HR_DIM];
__device__ float g_qi  [(size_t)L_SEQ*OUT_FEAT];
__device__ float g_ki  [(size_t)L_SEQ*OUT_FEAT];

struct F16 { float f[16]; };
struct F8  { float f[8];  };
struct GArgs { const float* A[3]; const float* B[3]; float* C[3]; };

// ------------------------- helpers ------------------------------------
__device__ __forceinline__ float gelu_f(float x) {
    return 0.5f * x * (1.0f + erff(x * 0.7071067811865476f));
}
__device__ __forceinline__ float silu_f(float x) {
    return x / (1.0f + expf(-x));
}
__device__ __forceinline__ uint32_t f2tf32(float x) {
    uint32_t r;
    asm("cvt.rna.tf32.f32 %0, %1;" : "=r"(r) : "f"(x));
    return r;
}
__device__ __forceinline__ void mma1688(float c[4], const uint32_t a[4], const uint32_t b[2]) {
    asm volatile(
        "mma.sync.aligned.m16n8k8.row.col.f32.tf32.tf32.f32 "
        "{%0,%1,%2,%3}, {%4,%5,%6,%7}, {%8,%9}, {%0,%1,%2,%3};"
        : "+f"(c[0]), "+f"(c[1]), "+f"(c[2]), "+f"(c[3])
        : "r"(a[0]), "r"(a[1]), "r"(a[2]), "r"(a[3]), "r"(b[0]), "r"(b[1]));
}
__device__ __forceinline__ void cpa16(uint32_t saddr, const float* g) {
    asm volatile("cp.async.cg.shared.global [%0], [%1], 16;\n" :: "r"(saddr), "l"(g));
}
#define CP_COMMIT() asm volatile("cp.async.commit_group;\n" ::: "memory")
#define CP_WAIT(n)  asm volatile("cp.async.wait_group %0;\n" :: "n"(n) : "memory")

// ---------------- TF32 GEMM: C[2048,N] = A[2048,K] * B[N,K]^T ---------
// CTA tile 128x64x32, 8 warps (4m x 2n), warp tile 32x32.
// 2-stage cp.async pipeline; smem raw fp32 with 16B-chunk XOR swizzle;
// cvt.rna.tf32 on the fragment-load path.
// EPI: 0 none, 1 gelu(acc+bias), 2 acc+bias+resid, 3 silu(acc)
template<int EPI>
__global__ __launch_bounds__(256, 2)
void tgemm(GArgs ga, const float* __restrict__ bias,
           const float* __restrict__ resid, int N, int K)
{
    __shared__ float sA[2][4096];    // 128 x 32, swizzled
    __shared__ float sB[2][2048];    // 64 x 32, swizzled

    const float* __restrict__ A = ga.A[blockIdx.z];
    const float* __restrict__ B = ga.B[blockIdx.z];
    float* __restrict__ C = ga.C[blockIdx.z];

    const int tid = threadIdx.x, wid = tid >> 5, lane = tid & 31;
    const int g = lane >> 2, tig = lane & 3;
    const int wmi = wid & 3, wni = wid >> 2;          // 4 m-warps, 2 n-warps
    const int wm = wmi * 32, wn = wni * 32;
    const int bm = blockIdx.y * 128, bn = blockIdx.x * 64;

    // loader mapping: each thread owns (row, 16B-chunk) slots
    const int lr = tid >> 3;          // 0..31
    const int ch = tid & 7;           // chunk 0..7
    uint32_t sA_u[2], sB_u[2];
    sA_u[0] = (uint32_t)__cvta_generic_to_shared(&sA[0][0]);
    sA_u[1] = (uint32_t)__cvta_generic_to_shared(&sA[1][0]);
    sB_u[0] = (uint32_t)__cvta_generic_to_shared(&sB[0][0]);
    sB_u[1] = (uint32_t)__cvta_generic_to_shared(&sB[1][0]);

    uint32_t aoff[4], boff[2];
    const float* aptr[4];
    const float* bptr[2];
#pragma unroll
    for (int i = 0; i < 4; i++) {
        int r = lr + i * 32;
        aoff[i] = (uint32_t)((r * 32 + ((ch ^ (r & 7)) << 2)) * 4);
        aptr[i] = A + (size_t)(bm + r) * K + ch * 4;
    }
#pragma unroll
    for (int i = 0; i < 2; i++) {
        int r = lr + i * 32;
        boff[i] = (uint32_t)((r * 32 + ((ch ^ (r & 7)) << 2)) * 4);
        bptr[i] = B + (size_t)(bn + r) * K + ch * 4;
    }

    float acc[2][4][4];
#pragma unroll
    for (int mi = 0; mi < 2; mi++)
#pragma unroll
        for (int ni = 0; ni < 4; ni++)
#pragma unroll
            for (int c = 0; c < 4; c++) acc[mi][ni][c] = 0.0f;

    // prologue: stage 0
#pragma unroll
    for (int i = 0; i < 4; i++) cpa16(sA_u[0] + aoff[i], aptr[i]);
#pragma unroll
    for (int i = 0; i < 2; i++) cpa16(sB_u[0] + boff[i], bptr[i]);
    CP_COMMIT();
#pragma unroll
    for (int i = 0; i < 4; i++) aptr[i] += 32;
#pragma unroll
    for (int i = 0; i < 2; i++) bptr[i] += 32;

    const int T = K >> 5;
    for (int t = 0; t < T; t++) {
        const int cur = t & 1, nxt = cur ^ 1;
        if (t + 1 < T) {
#pragma unroll
            for (int i = 0; i < 4; i++) cpa16(sA_u[nxt] + aoff[i], aptr[i]);
#pragma unroll
            for (int i = 0; i < 2; i++) cpa16(sB_u[nxt] + boff[i], bptr[i]);
            CP_COMMIT();
#pragma unroll
            for (int i = 0; i < 4; i++) aptr[i] += 32;
#pragma unroll
            for (int i = 0; i < 2; i++) bptr[i] += 32;
            CP_WAIT(1);
        } else {
            CP_WAIT(0);
        }
        __syncthreads();

        const float* __restrict__ Ac = sA[cur];
        const float* __restrict__ Bc = sB[cur];
#pragma unroll
        for (int kk = 0; kk < 4; kk++) {
            const int c0 = (((2 * kk)     ^ g) << 2) + tig;
            const int c1 = (((2 * kk + 1) ^ g) << 2) + tig;
            uint32_t af[2][4], bf[4][2];
#pragma unroll
            for (int mi = 0; mi < 2; mi++) {
                const int row = (wm + mi * 16 + g) * 32;
                af[mi][0] = f2tf32(Ac[row + c0]);
                af[mi][1] = f2tf32(Ac[row + 256 + c0]);   // +8 rows
                af[mi][2] = f2tf32(Ac[row + c1]);
                af[mi][3] = f2tf32(Ac[row + 256 + c1]);
            }
#pragma unroll
            for (int ni = 0; ni < 4; ni++) {
                const int row = (wn + ni * 8 + g) * 32;
                bf[ni][0] = f2tf32(Bc[row + c0]);
                bf[ni][1] = f2tf32(Bc[row + c1]);
            }
#pragma unroll
            for (int mi = 0; mi < 2; mi++)
#pragma unroll
                for (int ni = 0; ni < 4; ni++)
                    mma1688(acc[mi][ni], af[mi], bf[ni]);
        }
        __syncthreads();
    }

    // epilogue
#pragma unroll
    for (int mi = 0; mi < 2; mi++) {
#pragma unroll
        for (int ni = 0; ni < 4; ni++) {
            int m0 = bm + wm + mi * 16 + g;
            int n0 = bn + wn + ni * 8 + tig * 2;
#pragma unroll
            for (int half = 0; half < 2; half++) {
                int m = m0 + half * 8;
                size_t off = (size_t)m * N + n0;
                float v0 = acc[mi][ni][half * 2 + 0];
                float v1 = acc[mi][ni][half * 2 + 1];
                if (EPI == 1) {
                    v0 = gelu_f(v0 + bias[n0]); v1 = gelu_f(v1 + bias[n0 + 1]);
                } else if (EPI == 2) {
                    v0 = v0 + bias[n0] + resid[off];
                    v1 = v1 + bias[n0 + 1] + resid[off + 1];
                } else if (EPI == 3) {
                    v0 = silu_f(v0); v1 = silu_f(v1);
                }
                *reinterpret_cast<float2*>(C + off) = make_float2(v0, v1);
            }
        }
    }
}

// ------------------------- RoPE on q,k (in-place, head dim 32) --------
__global__ __launch_bounds__(256)
void rope_qk(float* __restrict__ q, float* __restrict__ k, F16 ft)
{
    int idx = blockIdx.x * blockDim.x + threadIdx.x;
    int i = idx & 15;
    int h = (idx >> 4) & 31;
    int l = idx >> 9;
    float ang = (float)l * ft.f[i];
    float c = cosf(ang), s = sinf(ang);
    size_t base = (size_t)l * HR_DIM + h * D_ATT + i;
    float x1 = q[base], x2 = q[base + 16];
    q[base]      = x1 * c - x2 * s;
    q[base + 16] = x2 * c + x1 * s;
    float y1 = k[base], y2 = k[base + 16];
    k[base]      = y1 * c - y2 * s;
    k[base + 16] = y2 * c + y1 * s;
}

// ------------------------- causal attention ---------------------------
#define ACH 128
__global__ __launch_bounds__(128)
void attn_k(const float* __restrict__ Q, const float* __restrict__ K,
            const float* __restrict__ V, float* __restrict__ O)
{
    __shared__ float Ks[ACH][33];
    __shared__ float Vs[ACH][33];
    const int h = blockIdx.y;
    const int qbase = blockIdx.x * 4;
    const int lane = threadIdx.x & 31;
    const int wid  = threadIdx.x >> 5;
    const int l = qbase + wid;

    float qreg = Q[(size_t)l * HR_DIM + h * D_ATT + lane] * 0.17677669529663687f;
    float m = -INFINITY, ssum = 0.0f, acc = 0.0f;
    const int lmax = qbase + 3;

    for (int j0 = 0; j0 <= lmax; j0 += ACH) {
        for (int t = threadIdx.x; t < ACH * 32; t += 128) {
            int r = t >> 5, c = t & 31;
            size_t gi = (size_t)(j0 + r) * HR_DIM + h * D_ATT + c;
            Ks[r][c] = K[gi];
            Vs[r][c] = V[gi];
        }
        __syncthreads();
        if (j0 <= l) {
#pragma unroll 1
            for (int jj = 0; jj < ACH; jj += 32) {
                int j = j0 + jj + lane;
                float s = 0.0f;
#pragma unroll
                for (int d = 0; d < 32; d++)
                    s = fmaf(__shfl_sync(0xffffffffu, qreg, d), Ks[jj + lane][d], s);
                if (j > l) s = -1e30f;
                float mc = s;
#pragma unroll
                for (int o = 16; o; o >>= 1) mc = fmaxf(mc, __shfl_xor_sync(0xffffffffu, mc, o));
                float mnew = fmaxf(m, mc);
                float alpha = expf(m - mnew);
                float p = expf(s - mnew);
                float psum = p;
#pragma unroll
                for (int o = 16; o; o >>= 1) psum += __shfl_xor_sync(0xffffffffu, psum, o);
                ssum = ssum * alpha + psum;
                acc *= alpha;
#pragma unroll
                for (int j2 = 0; j2 < 32; j2++)
                    acc = fmaf(__shfl_sync(0xffffffffu, p, j2), Vs[jj + j2][lane], acc);
                m = mnew;
            }
        }
        __syncthreads();
    }
    O[(size_t)l * HR_DIM + h * D_ATT + lane] = acc / ssum;
}

// ------------------------- LayerNorm (rows of 1024) -------------------
__global__ __launch_bounds__(256)
void layernorm_k(const float* __restrict__ in, const float* __restrict__ w,
                 const float* __restrict__ b, float* __restrict__ out)
{
    __shared__ float red[8];
    const int row = blockIdx.x;
    const int tid = threadIdx.x;
    const int lane = tid & 31, wid = tid >> 5;
    float4 v = reinterpret_cast<const float4*>(in + (size_t)row * HR_DIM)[tid];

    float s = v.x + v.y + v.z + v.w;
#pragma unroll
    for (int o = 16; o; o >>= 1) s += __shfl_xor_sync(0xffffffffu, s, o);
    if (lane == 0) red[wid] = s;
    __syncthreads();
    float tot = red[0]+red[1]+red[2]+red[3]+red[4]+red[5]+red[6]+red[7];
    float mu = tot * (1.0f / HR_DIM);

    float dx0 = v.x - mu, dx1 = v.y - mu, dx2 = v.z - mu, dx3 = v.w - mu;
    float sq = dx0*dx0 + dx1*dx1 + dx2*dx2 + dx3*dx3;
#pragma unroll
    for (int o = 16; o; o >>= 1) sq += __shfl_xor_sync(0xffffffffu, sq, o);
    __syncthreads();
    if (lane == 0) red[wid] = sq;
    __syncthreads();
    float var = (red[0]+red[1]+red[2]+red[3]+red[4]+red[5]+red[6]+red[7]) * (1.0f / HR_DIM);
    float rstd = rsqrtf(var + 1e-5f);

    float4 wv = reinterpret_cast<const float4*>(w)[tid];
    float4 bv = reinterpret_cast<const float4*>(b)[tid];
    float4 o4;
    o4.x = dx0 * rstd * wv.x + bv.x;
    o4.y = dx1 * rstd * wv.y + bv.y;
    o4.z = dx2 * rstd * wv.z + bv.z;
    o4.w = dx3 * rstd * wv.w + bv.w;
    reinterpret_cast<float4*>(out + (size_t)row * HR_DIM)[tid] = o4;
}

// ---------------- importance RoPE + permute to (N,H,L,DD) -------------
__global__ __launch_bounds__(256)
void rope_perm(const float* __restrict__ in, float* __restrict__ out, F8 ft)
{
    int idx = blockIdx.x * blockDim.x + threadIdx.x;
    int i = idx & 7;
    int l = (idx >> 3) & 2047;
    int h = (idx >> 14) & 31;
    int n = idx >> 19;
    float ang = (float)l * ft.f[i];
    float c = cosf(ang), s = sinf(ang);
    size_t ibase = (size_t)l * OUT_FEAT + n * (NH * DD) + h * DD + i;
    float x1 = in[ibase], x2 = in[ibase + 8];
    size_t obase = (((size_t)(n * NH + h)) * L_SEQ + l) * DD + i;
    out[obase]     = x1 * c - x2 * s;
    out[obase + 8] = x2 * c + x1 * s;
}

// ------------------------- launcher -----------------------------------
extern "C" void kernel_launch(void* const* d_in, const int* in_sizes, int n_in,
                              void* d_out, int out_size)
{
    const float* x    = (const float*)d_in[0];
    const float* Wi   = (const float*)d_in[1];
    const float* Wq   = (const float*)d_in[2];
    const float* Wk   = (const float*)d_in[3];
    const float* Wv   = (const float*)d_in[4];
    const float* ln1w = (const float*)d_in[5];
    const float* ln1b = (const float*)d_in[6];
    const float* Wf1  = (const float*)d_in[7];
    const float* bf1  = (const float*)d_in[8];
    const float* Wf2  = (const float*)d_in[9];
    const float* bf2  = (const float*)d_in[10];
    const float* Wqi1 = (const float*)d_in[11];
    const float* Wqi2 = (const float*)d_in[12];
    const float* Wki1 = (const float*)d_in[13];
    const float* Wki2 = (const float*)d_in[14];
    float* out = (float*)d_out;

    float *hr,*q,*k,*v,*attn,*ln,*f1,*hid,*aq,*ak,*qi,*ki;
    cudaGetSymbolAddress((void**)&hr,   g_hr);
    cudaGetSymbolAddress((void**)&q,    g_q);
    cudaGetSymbolAddress((void**)&k,    g_k);
    cudaGetSymbolAddress((void**)&v,    g_v);
    cudaGetSymbolAddress((void**)&attn, g_attn);
    cudaGetSymbolAddress((void**)&ln,   g_ln);
    cudaGetSymbolAddress((void**)&f1,   g_f1);
    cudaGetSymbolAddress((void**)&hid,  g_hid);
    cudaGetSymbolAddress((void**)&aq,   g_aq);
    cudaGetSymbolAddress((void**)&ak,   g_ak);
    cudaGetSymbolAddress((void**)&qi,   g_qi);
    cudaGetSymbolAddress((void**)&ki,   g_ki);

    F16 t16; for (int i = 0; i < 16; i++) t16.f[i] = (float)(1.0 / pow(10000.0, (double)i / 16.0));
    F8  t8;  for (int i = 0; i < 8;  i++) t8.f[i]  = (float)(1.0 / pow(10000.0, (double)i / 8.0));

    GArgs ga;

    // hr = x @ Wi^T
    ga.A[0] = x; ga.B[0] = Wi; ga.C[0] = hr;
    tgemm<0><<<dim3(HR_DIM/64, 16, 1), 256>>>(ga, nullptr, nullptr, HR_DIM, E_DIM);

    // q, k, v (batched over z)
    ga.A[0] = hr; ga.A[1] = hr; ga.A[2] = hr;
    ga.B[0] = Wq; ga.B[1] = Wk; ga.B[2] = Wv;
    ga.C[0] = q;  ga.C[1] = k;  ga.C[2] = v;
    tgemm<0><<<dim3(HR_DIM/64, 16, 3), 256>>>(ga, nullptr, nullptr, HR_DIM, HR_DIM);

    rope_qk<<<(L_SEQ*NH*16)/256, 256>>>(q, k, t16);
    attn_k<<<dim3(L_SEQ/4, NH), 128>>>(q, k, v, attn);
    layernorm_k<<<L_SEQ, 256>>>(attn, ln1w, ln1b, ln);

    // ffn1: gelu(ln @ Wf1^T + bf1)
    ga.A[0] = ln; ga.B[0] = Wf1; ga.C[0] = f1;
    tgemm<1><<<dim3(2*HR_DIM/64, 16, 1), 256>>>(ga, bf1, nullptr, 2*HR_DIM, HR_DIM);

    // ffn2 + residual: hid = x + f1 @ Wf2^T + bf2
    ga.A[0] = f1; ga.B[0] = Wf2; ga.C[0] = hid;
    tgemm<2><<<dim3(E_DIM/64, 16, 1), 256>>>(ga, bf2, x, E_DIM, 2*HR_DIM);

    // silu projections (batched)
    ga.A[0] = hid; ga.A[1] = hid;
    ga.B[0] = Wqi1; ga.B[1] = Wki1;
    ga.C[0] = aq;  ga.C[1] = ak;
    tgemm<3><<<dim3(HR_DIM/64, 16, 2), 256>>>(ga, nullptr, nullptr, HR_DIM, E_DIM);

    // importance projections (batched)
    ga.A[0] = aq; ga.A[1] = ak;
    ga.B[0] = Wqi2; ga.B[1] = Wki2;
    ga.C[0] = qi;  ga.C[1] = ki;
    tgemm<0><<<dim3(OUT_FEAT/64, 16, 2), 256>>>(ga, nullptr, nullptr, OUT_FEAT, HR_DIM);

    rope_perm<<<(NLAY*NH*L_SEQ*8)/256, 256>>>(qi, out, t8);
    rope_perm<<<(NLAY*NH*L_SEQ*8)/256, 256>>>(ki, out + (size_t)NLAY*NH*L_SEQ*DD, t8);
}

// round 5
// speedup vs baseline: 2.4356x; 1.0068x over previous
#include <cuda_runtime.h>
#include <math.h>
#include <stdint.h>

// ------------------------- problem dimensions -------------------------
#define L_SEQ   2048
#define E_DIM   4096
#define HR_DIM  1024
#define NH      32
#define D_ATT   32
#define NLAY    32
#define DD      16
#define OUT_FEAT (NLAY*NH*DD)   // 16384

// ------------------------- scratch (static device mem) ----------------
__device__ float g_hr  [(size_t)L_SEQ*HR_DIM];
__device__ float g_q   [(size_t)L_SEQ*HR_DIM];
__device__ float g_k   [(size_t)L_SEQ*HR_DIM];
__device__ float g_v   [(size_t)L_SEQ*HR_DIM];
__device__ float g_attn[(size_t)L_SEQ*HR_DIM];
__device__ float g_ln  [(size_t)L_SEQ*HR_DIM];
__device__ float g_f1  [(size_t)L_SEQ*2*HR_DIM];
__device__ float g_hid [(size_t)L_SEQ*E_DIM];
__device__ float g_aq  [(size_t)L_SEQ*HR_DIM];
__device__ float g_ak  [(size_t)L_SEQ*HR_DIM];
__device__ float g_qi  [(size_t)L_SEQ*OUT_FEAT];
__device__ float g_ki  [(size_t)L_SEQ*OUT_FEAT];

struct F16 { float f[16]; };
struct F8  { float f[8];  };
struct GArgs { const float* A[3]; const float* B[3]; float* C[3]; };

// ------------------------- helpers ------------------------------------
__device__ __forceinline__ float gelu_f(float x) {
    return 0.5f * x * (1.0f + erff(x * 0.7071067811865476f));
}
__device__ __forceinline__ float silu_f(float x) {
    return x / (1.0f + expf(-x));
}
__device__ __forceinline__ uint32_t f2tf32(float x) {
    uint32_t r;
    asm("cvt.rna.tf32.f32 %0, %1;" : "=r"(r) : "f"(x));
    return r;
}
__device__ __forceinline__ void mma1688(float c[4], const uint32_t a[4], const uint32_t b[2]) {
    asm volatile(
        "mma.sync.aligned.m16n8k8.row.col.f32.tf32.tf32.f32 "
        "{%0,%1,%2,%3}, {%4,%5,%6,%7}, {%8,%9}, {%0,%1,%2,%3};"
        : "+f"(c[0]), "+f"(c[1]), "+f"(c[2]), "+f"(c[3])
        : "r"(a[0]), "r"(a[1]), "r"(a[2]), "r"(a[3]), "r"(b[0]), "r"(b[1]));
}
__device__ __forceinline__ void cpa16(uint32_t saddr, const float* g) {
    asm volatile("cp.async.cg.shared.global [%0], [%1], 16;\n" :: "r"(saddr), "l"(g));
}
#define CP_COMMIT() asm volatile("cp.async.commit_group;\n" ::: "memory")
#define CP_WAIT(n)  asm volatile("cp.async.wait_group %0;\n" :: "n"(n) : "memory")

// ---------------- TF32 GEMM: C[2048,N] = A[2048,K] * B[N,K]^T ---------
// (unchanged from round 4)
template<int EPI>
__global__ __launch_bounds__(256, 2)
void tgemm(GArgs ga, const float* __restrict__ bias,
           const float* __restrict__ resid, int N, int K)
{
    __shared__ float sA[2][4096];
    __shared__ float sB[2][2048];

    const float* __restrict__ A = ga.A[blockIdx.z];
    const float* __restrict__ B = ga.B[blockIdx.z];
    float* __restrict__ C = ga.C[blockIdx.z];

    const int tid = threadIdx.x, wid = tid >> 5, lane = tid & 31;
    const int g = lane >> 2, tig = lane & 3;
    const int wmi = wid & 3, wni = wid >> 2;
    const int wm = wmi * 32, wn = wni * 32;
    const int bm = blockIdx.y * 128, bn = blockIdx.x * 64;

    const int lr = tid >> 3;
    const int ch = tid & 7;
    uint32_t sA_u[2], sB_u[2];
    sA_u[0] = (uint32_t)__cvta_generic_to_shared(&sA[0][0]);
    sA_u[1] = (uint32_t)__cvta_generic_to_shared(&sA[1][0]);
    sB_u[0] = (uint32_t)__cvta_generic_to_shared(&sB[0][0]);
    sB_u[1] = (uint32_t)__cvta_generic_to_shared(&sB[1][0]);

    uint32_t aoff[4], boff[2];
    const float* aptr[4];
    const float* bptr[2];
#pragma unroll
    for (int i = 0; i < 4; i++) {
        int r = lr + i * 32;
        aoff[i] = (uint32_t)((r * 32 + ((ch ^ (r & 7)) << 2)) * 4);
        aptr[i] = A + (size_t)(bm + r) * K + ch * 4;
    }
#pragma unroll
    for (int i = 0; i < 2; i++) {
        int r = lr + i * 32;
        boff[i] = (uint32_t)((r * 32 + ((ch ^ (r & 7)) << 2)) * 4);
        bptr[i] = B + (size_t)(bn + r) * K + ch * 4;
    }

    float acc[2][4][4];
#pragma unroll
    for (int mi = 0; mi < 2; mi++)
#pragma unroll
        for (int ni = 0; ni < 4; ni++)
#pragma unroll
            for (int c = 0; c < 4; c++) acc[mi][ni][c] = 0.0f;

#pragma unroll
    for (int i = 0; i < 4; i++) cpa16(sA_u[0] + aoff[i], aptr[i]);
#pragma unroll
    for (int i = 0; i < 2; i++) cpa16(sB_u[0] + boff[i], bptr[i]);
    CP_COMMIT();
#pragma unroll
    for (int i = 0; i < 4; i++) aptr[i] += 32;
#pragma unroll
    for (int i = 0; i < 2; i++) bptr[i] += 32;

    const int T = K >> 5;
    for (int t = 0; t < T; t++) {
        const int cur = t & 1, nxt = cur ^ 1;
        if (t + 1 < T) {
#pragma unroll
            for (int i = 0; i < 4; i++) cpa16(sA_u[nxt] + aoff[i], aptr[i]);
#pragma unroll
            for (int i = 0; i < 2; i++) cpa16(sB_u[nxt] + boff[i], bptr[i]);
            CP_COMMIT();
#pragma unroll
            for (int i = 0; i < 4; i++) aptr[i] += 32;
#pragma unroll
            for (int i = 0; i < 2; i++) bptr[i] += 32;
            CP_WAIT(1);
        } else {
            CP_WAIT(0);
        }
        __syncthreads();

        const float* __restrict__ Ac = sA[cur];
        const float* __restrict__ Bc = sB[cur];
#pragma unroll
        for (int kk = 0; kk < 4; kk++) {
            const int c0 = (((2 * kk)     ^ g) << 2) + tig;
            const int c1 = (((2 * kk + 1) ^ g) << 2) + tig;
            uint32_t af[2][4], bf[4][2];
#pragma unroll
            for (int mi = 0; mi < 2; mi++) {
                const int row = (wm + mi * 16 + g) * 32;
                af[mi][0] = f2tf32(Ac[row + c0]);
                af[mi][1] = f2tf32(Ac[row + 256 + c0]);
                af[mi][2] = f2tf32(Ac[row + c1]);
                af[mi][3] = f2tf32(Ac[row + 256 + c1]);
            }
#pragma unroll
            for (int ni = 0; ni < 4; ni++) {
                const int row = (wn + ni * 8 + g) * 32;
                bf[ni][0] = f2tf32(Bc[row + c0]);
                bf[ni][1] = f2tf32(Bc[row + c1]);
            }
#pragma unroll
            for (int mi = 0; mi < 2; mi++)
#pragma unroll
                for (int ni = 0; ni < 4; ni++)
                    mma1688(acc[mi][ni], af[mi], bf[ni]);
        }
        __syncthreads();
    }

#pragma unroll
    for (int mi = 0; mi < 2; mi++) {
#pragma unroll
        for (int ni = 0; ni < 4; ni++) {
            int m0 = bm + wm + mi * 16 + g;
            int n0 = bn + wn + ni * 8 + tig * 2;
#pragma unroll
            for (int half = 0; half < 2; half++) {
                int m = m0 + half * 8;
                size_t off = (size_t)m * N + n0;
                float v0 = acc[mi][ni][half * 2 + 0];
                float v1 = acc[mi][ni][half * 2 + 1];
                if (EPI == 1) {
                    v0 = gelu_f(v0 + bias[n0]); v1 = gelu_f(v1 + bias[n0 + 1]);
                } else if (EPI == 2) {
                    v0 = v0 + bias[n0] + resid[off];
                    v1 = v1 + bias[n0 + 1] + resid[off + 1];
                } else if (EPI == 3) {
                    v0 = silu_f(v0); v1 = silu_f(v1);
                }
                *reinterpret_cast<float2*>(C + off) = make_float2(v0, v1);
            }
        }
    }
}

// ------------------------- RoPE on q,k (in-place, head dim 32) --------
__global__ __launch_bounds__(256)
void rope_qk(float* __restrict__ q, float* __restrict__ k, F16 ft)
{
    int idx = blockIdx.x * blockDim.x + threadIdx.x;
    int i = idx & 15;
    int h = (idx >> 4) & 31;
    int l = idx >> 9;
    float ang = (float)l * ft.f[i];
    float c = cosf(ang), s = sinf(ang);
    size_t base = (size_t)l * HR_DIM + h * D_ATT + i;
    float x1 = q[base], x2 = q[base + 16];
    q[base]      = x1 * c - x2 * s;
    q[base + 16] = x2 * c + x1 * s;
    float y1 = k[base], y2 = k[base + 16];
    k[base]      = y1 * c - y2 * s;
    k[base + 16] = y2 * c + y1 * s;
}

// ------------------------- causal attention ---------------------------
// 64 queries / block, 8 warps x 8 queries each; 128-key K/V smem tiles.
#define AQB 64
#define AKT 128
__global__ __launch_bounds__(256)
void attn_k(const float* __restrict__ Q, const float* __restrict__ K,
            const float* __restrict__ V, float* __restrict__ O)
{
    __shared__ float Ks[AKT][33];
    __shared__ float Vs[AKT][33];
    const int h = blockIdx.y;
    const int q0 = blockIdx.x * AQB;
    const int lane = threadIdx.x & 31;
    const int w = threadIdx.x >> 5;
    const int lbase = q0 + w * 8;

    float qreg[8], m[8], ssum[8], acc[8];
#pragma unroll
    for (int i = 0; i < 8; i++) {
        qreg[i] = Q[(size_t)(lbase + i) * HR_DIM + h * D_ATT + lane] * 0.17677669529663687f;
        m[i] = -INFINITY; ssum[i] = 0.0f; acc[i] = 0.0f;
    }

    const int jmax = q0 + AQB - 1;
    for (int j0 = 0; j0 <= jmax; j0 += AKT) {
        for (int t = threadIdx.x; t < AKT * 32; t += 256) {
            int r = t >> 5, c = t & 31;
            size_t gi = (size_t)(j0 + r) * HR_DIM + h * D_ATT + c;
            Ks[r][c] = K[gi];
            Vs[r][c] = V[gi];
        }
        __syncthreads();

#pragma unroll
        for (int i = 0; i < 8; i++) {
            const int l = lbase + i;
            if (j0 > l) continue;
#pragma unroll 1
            for (int jj = 0; jj < AKT; jj += 32) {
                if (j0 + jj > l) break;
                int j = j0 + jj + lane;
                float s = 0.0f;
#pragma unroll
                for (int d = 0; d < 32; d++)
                    s = fmaf(__shfl_sync(0xffffffffu, qreg[i], d), Ks[jj + lane][d], s);
                if (j > l) s = -1e30f;
                float mc = s;
#pragma unroll
                for (int o = 16; o; o >>= 1) mc = fmaxf(mc, __shfl_xor_sync(0xffffffffu, mc, o));
                float mnew = fmaxf(m[i], mc);
                float alpha = expf(m[i] - mnew);
                float p = expf(s - mnew);
                float psum = p;
#pragma unroll
                for (int o = 16; o; o >>= 1) psum += __shfl_xor_sync(0xffffffffu, psum, o);
                ssum[i] = ssum[i] * alpha + psum;
                acc[i] *= alpha;
#pragma unroll
                for (int j2 = 0; j2 < 32; j2++)
                    acc[i] = fmaf(__shfl_sync(0xffffffffu, p, j2), Vs[jj + j2][lane], acc[i]);
                m[i] = mnew;
            }
        }
        __syncthreads();
    }
#pragma unroll
    for (int i = 0; i < 8; i++)
        O[(size_t)(lbase + i) * HR_DIM + h * D_ATT + lane] = acc[i] / ssum[i];
}

// ------------------------- LayerNorm (rows of 1024) -------------------
__global__ __launch_bounds__(256)
void layernorm_k(const float* __restrict__ in, const float* __restrict__ w,
                 const float* __restrict__ b, float* __restrict__ out)
{
    __shared__ float red[8];
    const int row = blockIdx.x;
    const int tid = threadIdx.x;
    const int lane = tid & 31, wid = tid >> 5;
    float4 v = reinterpret_cast<const float4*>(in + (size_t)row * HR_DIM)[tid];

    float s = v.x + v.y + v.z + v.w;
#pragma unroll
    for (int o = 16; o; o >>= 1) s += __shfl_xor_sync(0xffffffffu, s, o);
    if (lane == 0) red[wid] = s;
    __syncthreads();
    float tot = red[0]+red[1]+red[2]+red[3]+red[4]+red[5]+red[6]+red[7];
    float mu = tot * (1.0f / HR_DIM);

    float dx0 = v.x - mu, dx1 = v.y - mu, dx2 = v.z - mu, dx3 = v.w - mu;
    float sq = dx0*dx0 + dx1*dx1 + dx2*dx2 + dx3*dx3;
#pragma unroll
    for (int o = 16; o; o >>= 1) sq += __shfl_xor_sync(0xffffffffu, sq, o);
    __syncthreads();
    if (lane == 0) red[wid] = sq;
    __syncthreads();
    float var = (red[0]+red[1]+red[2]+red[3]+red[4]+red[5]+red[6]+red[7]) * (1.0f / HR_DIM);
    float rstd = rsqrtf(var + 1e-5f);

    float4 wv = reinterpret_cast<const float4*>(w)[tid];
    float4 bv = reinterpret_cast<const float4*>(b)[tid];
    float4 o4;
    o4.x = dx0 * rstd * wv.x + bv.x;
    o4.y = dx1 * rstd * wv.y + bv.y;
    o4.z = dx2 * rstd * wv.z + bv.z;
    o4.w = dx3 * rstd * wv.w + bv.w;
    reinterpret_cast<float4*>(out + (size_t)row * HR_DIM)[tid] = o4;
}

// ---------------- importance RoPE + permute to (N,H,L,DD) -------------
__global__ __launch_bounds__(256)
void rope_perm(const float* __restrict__ in, float* __restrict__ out, F8 ft)
{
    int idx = blockIdx.x * blockDim.x + threadIdx.x;
    int i = idx & 7;
    int l = (idx >> 3) & 2047;
    int h = (idx >> 14) & 31;
    int n = idx >> 19;
    float ang = (float)l * ft.f[i];
    float c = cosf(ang), s = sinf(ang);
    size_t ibase = (size_t)l * OUT_FEAT + n * (NH * DD) + h * DD + i;
    float x1 = in[ibase], x2 = in[ibase + 8];
    size_t obase = (((size_t)(n * NH + h)) * L_SEQ + l) * DD + i;
    out[obase]     = x1 * c - x2 * s;
    out[obase + 8] = x2 * c + x1 * s;
}

// ------------------------- launcher -----------------------------------
extern "C" void kernel_launch(void* const* d_in, const int* in_sizes, int n_in,
                              void* d_out, int out_size)
{
    const float* x    = (const float*)d_in[0];
    const float* Wi   = (const float*)d_in[1];
    const float* Wq   = (const float*)d_in[2];
    const float* Wk   = (const float*)d_in[3];
    const float* Wv   = (const float*)d_in[4];
    const float* ln1w = (const float*)d_in[5];
    const float* ln1b = (const float*)d_in[6];
    const float* Wf1  = (const float*)d_in[7];
    const float* bf1  = (const float*)d_in[8];
    const float* Wf2  = (const float*)d_in[9];
    const float* bf2  = (const float*)d_in[10];
    const float* Wqi1 = (const float*)d_in[11];
    const float* Wqi2 = (const float*)d_in[12];
    const float* Wki1 = (const float*)d_in[13];
    const float* Wki2 = (const float*)d_in[14];
    float* out = (float*)d_out;

    float *hr,*q,*k,*v,*attn,*ln,*f1,*hid,*aq,*ak,*qi,*ki;
    cudaGetSymbolAddress((void**)&hr,   g_hr);
    cudaGetSymbolAddress((void**)&q,    g_q);
    cudaGetSymbolAddress((void**)&k,    g_k);
    cudaGetSymbolAddress((void**)&v,    g_v);
    cudaGetSymbolAddress((void**)&attn, g_attn);
    cudaGetSymbolAddress((void**)&ln,   g_ln);
    cudaGetSymbolAddress((void**)&f1,   g_f1);
    cudaGetSymbolAddress((void**)&hid,  g_hid);
    cudaGetSymbolAddress((void**)&aq,   g_aq);
    cudaGetSymbolAddress((void**)&ak,   g_ak);
    cudaGetSymbolAddress((void**)&qi,   g_qi);
    cudaGetSymbolAddress((void**)&ki,   g_ki);

    F16 t16; for (int i = 0; i < 16; i++) t16.f[i] = (float)(1.0 / pow(10000.0, (double)i / 16.0));
    F8  t8;  for (int i = 0; i < 8;  i++) t8.f[i]  = (float)(1.0 / pow(10000.0, (double)i / 8.0));

    GArgs ga;

    // hr = x @ Wi^T
    ga.A[0] = x; ga.B[0] = Wi; ga.C[0] = hr;
    tgemm<0><<<dim3(HR_DIM/64, 16, 1), 256>>>(ga, nullptr, nullptr, HR_DIM, E_DIM);

    // q, k, v (batched over z)
    ga.A[0] = hr; ga.A[1] = hr; ga.A[2] = hr;
    ga.B[0] = Wq; ga.B[1] = Wk; ga.B[2] = Wv;
    ga.C[0] = q;  ga.C[1] = k;  ga.C[2] = v;
    tgemm<0><<<dim3(HR_DIM/64, 16, 3), 256>>>(ga, nullptr, nullptr, HR_DIM, HR_DIM);

    rope_qk<<<(L_SEQ*NH*16)/256, 256>>>(q, k, t16);
    attn_k<<<dim3(L_SEQ/AQB, NH), 256>>>(q, k, v, attn);
    layernorm_k<<<L_SEQ, 256>>>(attn, ln1w, ln1b, ln);

    // ffn1: gelu(ln @ Wf1^T + bf1)
    ga.A[0] = ln; ga.B[0] = Wf1; ga.C[0] = f1;
    tgemm<1><<<dim3(2*HR_DIM/64, 16, 1), 256>>>(ga, bf1, nullptr, 2*HR_DIM, HR_DIM);

    // ffn2 + residual: hid = x + f1 @ Wf2^T + bf2
    ga.A[0] = f1; ga.B[0] = Wf2; ga.C[0] = hid;
    tgemm<2><<<dim3(E_DIM/64, 16, 1), 256>>>(ga, bf2, x, E_DIM, 2*HR_DIM);

    // silu projections (batched)
    ga.A[0] = hid; ga.A[1] = hid;
    ga.B[0] = Wqi1; ga.B[1] = Wki1;
    ga.C[0] = aq;  ga.C[1] = ak;
    tgemm<3><<<dim3(HR_DIM/64, 16, 2), 256>>>(ga, nullptr, nullptr, HR_DIM, E_DIM);

    // importance projections (batched)
    ga.A[0] = aq; ga.A[1] = ak;
    ga.B[0] = Wqi2; ga.B[1] = Wki2;
    ga.C[0] = qi;  ga.C[1] = ki;
    tgemm<0><<<dim3(OUT_FEAT/64, 16, 2), 256>>>(ga, nullptr, nullptr, OUT_FEAT, HR_DIM);

    rope_perm<<<(NLAY*NH*L_SEQ*8)/256, 256>>>(qi, out, t8);
    rope_perm<<<(NLAY*NH*L_SEQ*8)/256, 256>>>(ki, out + (size_t)NLAY*NH*L_SEQ*DD, t8);
}

// round 6
// speedup vs baseline: 2.6556x; 1.0903x over previous
#include <cuda_runtime.h>
#include <math.h>
#include <stdint.h>

// ------------------------- problem dimensions -------------------------
#define L_SEQ   2048
#define E_DIM   4096
#define HR_DIM  1024
#define NH      32
#define D_ATT   32
#define NLAY    32
#define DD      16
#define OUT_FEAT (NLAY*NH*DD)   // 16384

// ------------------------- scratch (static device mem) ----------------
__device__ float g_hr  [(size_t)L_SEQ*HR_DIM];
__device__ float g_q   [(size_t)L_SEQ*HR_DIM];
__device__ float g_k   [(size_t)L_SEQ*HR_DIM];
__device__ float g_v   [(size_t)L_SEQ*HR_DIM];
__device__ float g_attn[(size_t)L_SEQ*HR_DIM];
__device__ float g_ln  [(size_t)L_SEQ*HR_DIM];
__device__ float g_f1  [(size_t)L_SEQ*2*HR_DIM];
__device__ float g_hid [(size_t)L_SEQ*E_DIM];
__device__ float g_aq  [(size_t)L_SEQ*HR_DIM];
__device__ float g_ak  [(size_t)L_SEQ*HR_DIM];
__device__ float g_qi  [(size_t)L_SEQ*OUT_FEAT];
__device__ float g_ki  [(size_t)L_SEQ*OUT_FEAT];
// tf32-rounded operand copies
__device__ float g_rx   [(size_t)L_SEQ*E_DIM];
__device__ float g_rWi  [(size_t)HR_DIM*E_DIM];
__device__ float g_rWq  [(size_t)HR_DIM*HR_DIM];
__device__ float g_rWk  [(size_t)HR_DIM*HR_DIM];
__device__ float g_rWv  [(size_t)HR_DIM*HR_DIM];
__device__ float g_rWf1 [(size_t)2*HR_DIM*HR_DIM];
__device__ float g_rWf2 [(size_t)E_DIM*2*HR_DIM];
__device__ float g_rWqi1[(size_t)HR_DIM*E_DIM];
__device__ float g_rWki1[(size_t)HR_DIM*E_DIM];
__device__ float g_rWqi2[(size_t)OUT_FEAT*HR_DIM];
__device__ float g_rWki2[(size_t)OUT_FEAT*HR_DIM];

struct F16 { float f[16]; };
struct F8  { float f[8];  };
struct GArgs { const float* A[3]; const float* B[3]; float* C[3]; };

// ------------------------- helpers ------------------------------------
__device__ __forceinline__ float gelu_f(float x) {
    return 0.5f * x * (1.0f + erff(x * 0.7071067811865476f));
}
__device__ __forceinline__ float silu_f(float x) {
    return x / (1.0f + expf(-x));
}
__device__ __forceinline__ uint32_t f2tf32(float x) {
    uint32_t r;
    asm("cvt.rna.tf32.f32 %0, %1;" : "=r"(r) : "f"(x));
    return r;
}
__device__ __forceinline__ float rnd_tf32(float x) {
    return __uint_as_float(f2tf32(x));
}
__device__ __forceinline__ void mma1688(float c[4], const uint32_t a[4], const uint32_t b[2]) {
    asm volatile(
        "mma.sync.aligned.m16n8k8.row.col.f32.tf32.tf32.f32 "
        "{%0,%1,%2,%3}, {%4,%5,%6,%7}, {%8,%9}, {%0,%1,%2,%3};"
        : "+f"(c[0]), "+f"(c[1]), "+f"(c[2]), "+f"(c[3])
        : "r"(a[0]), "r"(a[1]), "r"(a[2]), "r"(a[3]), "r"(b[0]), "r"(b[1]));
}
__device__ __forceinline__ void cpa16(uint32_t saddr, const float* g) {
    asm volatile("cp.async.cg.shared.global [%0], [%1], 16;\n" :: "r"(saddr), "l"(g));
}
#define CP_COMMIT() asm volatile("cp.async.commit_group;\n" ::: "memory")
#define CP_WAIT(n)  asm volatile("cp.async.wait_group %0;\n" :: "n"(n) : "memory")
__device__ __forceinline__ void ldsm4(uint32_t& r0, uint32_t& r1, uint32_t& r2, uint32_t& r3,
                                      uint32_t addr) {
    asm volatile("ldmatrix.sync.aligned.m8n8.x4.shared.b16 {%0,%1,%2,%3}, [%4];"
                 : "=r"(r0), "=r"(r1), "=r"(r2), "=r"(r3) : "r"(addr));
}

// ------------------ pre-round: dst = tf32_rna(src) --------------------
__global__ __launch_bounds__(256)
void round_k(const float4* __restrict__ in, float4* __restrict__ out)
{
    int i = blockIdx.x * blockDim.x + threadIdx.x;
    float4 v = in[i];
    v.x = rnd_tf32(v.x); v.y = rnd_tf32(v.y);
    v.z = rnd_tf32(v.z); v.w = rnd_tf32(v.w);
    out[i] = v;
}

// ---------------- TF32 GEMM: C[2048,N] = A[2048,K] * B[N,K]^T ---------
// CTA tile 128x64x32, 8 warps (4m x 2n), warp tile 32x32.
// cp.async 2-stage; raw fp32 smem with 16B-chunk XOR swizzle; ldmatrix
// fragment loads (operands pre-rounded to tf32 => no cvt in mainloop).
// EPI: 0 none, 1 gelu(acc+bias), 2 acc+bias+resid, 3 silu(acc)
// RND: round C to tf32 at store (when consumed by a later GEMM A-side)
template<int EPI, int RND>
__global__ __launch_bounds__(256, 2)
void tgemm(GArgs ga, const float* __restrict__ bias,
           const float* __restrict__ resid, int N, int K)
{
    __shared__ float sA[2][4096];    // 128 x 32
    __shared__ float sB[2][2048];    // 64 x 32

    const float* __restrict__ A = ga.A[blockIdx.z];
    const float* __restrict__ B = ga.B[blockIdx.z];
    float* __restrict__ C = ga.C[blockIdx.z];

    const int tid = threadIdx.x, wid = tid >> 5, lane = tid & 31;
    const int g = lane >> 2, tig = lane & 3;
    const int wmi = wid & 3, wni = wid >> 2;
    const int wm = wmi * 32, wn = wni * 32;
    const int bm = blockIdx.y * 128, bn = blockIdx.x * 64;

    // ---- cp.async loader mapping ----
    const int lr = tid >> 3;
    const int ch = tid & 7;
    uint32_t sA_u[2], sB_u[2];
    sA_u[0] = (uint32_t)__cvta_generic_to_shared(&sA[0][0]);
    sA_u[1] = (uint32_t)__cvta_generic_to_shared(&sA[1][0]);
    sB_u[0] = (uint32_t)__cvta_generic_to_shared(&sB[0][0]);
    sB_u[1] = (uint32_t)__cvta_generic_to_shared(&sB[1][0]);

    uint32_t aoff[4], boff[2];
    const float* aptr[4];
    const float* bptr[2];
#pragma unroll
    for (int i = 0; i < 4; i++) {
        int r = lr + i * 32;
        aoff[i] = (uint32_t)((r * 32 + ((ch ^ (r & 7)) << 2)) * 4);
        aptr[i] = A + (size_t)(bm + r) * K + ch * 4;
    }
#pragma unroll
    for (int i = 0; i < 2; i++) {
        int r = lr + i * 32;
        boff[i] = (uint32_t)((r * 32 + ((ch ^ (r & 7)) << 2)) * 4);
        bptr[i] = B + (size_t)(bn + r) * K + ch * 4;
    }

    // ---- ldmatrix per-lane address components ----
    // A: row = wm + mi*16 + (lane&15); chunk bit = lane>>4
    const int aRowL = wm + (lane & 15);
    const int cAbit = lane >> 4;
    uint32_t aRowByte[2]; int aMask[2];
#pragma unroll
    for (int mi = 0; mi < 2; mi++) {
        int r = aRowL + mi * 16;
        aRowByte[mi] = (uint32_t)(r * 128);
        aMask[mi] = r & 7;
    }
    // B: row = wn + (p*2 + (lane>>4))*8 + (lane&7); chunk bit = (lane>>3)&1
    const int cBbit = (lane >> 3) & 1;
    uint32_t bRowByte[2]; int bMask[2];
#pragma unroll
    for (int p = 0; p < 2; p++) {
        int r = wn + (p * 2 + (lane >> 4)) * 8 + (lane & 7);
        bRowByte[p] = (uint32_t)(r * 128);
        bMask[p] = r & 7;
    }

    float acc[2][4][4];
#pragma unroll
    for (int mi = 0; mi < 2; mi++)
#pragma unroll
        for (int ni = 0; ni < 4; ni++)
#pragma unroll
            for (int c = 0; c < 4; c++) acc[mi][ni][c] = 0.0f;

    // prologue: stage 0
#pragma unroll
    for (int i = 0; i < 4; i++) cpa16(sA_u[0] + aoff[i], aptr[i]);
#pragma unroll
    for (int i = 0; i < 2; i++) cpa16(sB_u[0] + boff[i], bptr[i]);
    CP_COMMIT();
#pragma unroll
    for (int i = 0; i < 4; i++) aptr[i] += 32;
#pragma unroll
    for (int i = 0; i < 2; i++) bptr[i] += 32;

    const int T = K >> 5;
    for (int t = 0; t < T; t++) {
        const int cur = t & 1, nxt = cur ^ 1;
        if (t + 1 < T) {
#pragma unroll
            for (int i = 0; i < 4; i++) cpa16(sA_u[nxt] + aoff[i], aptr[i]);
#pragma unroll
            for (int i = 0; i < 2; i++) cpa16(sB_u[nxt] + boff[i], bptr[i]);
            CP_COMMIT();
#pragma unroll
            for (int i = 0; i < 4; i++) aptr[i] += 32;
#pragma unroll
            for (int i = 0; i < 2; i++) bptr[i] += 32;
            CP_WAIT(1);
        } else {
            CP_WAIT(0);
        }
        __syncthreads();

        const uint32_t sAc = sA_u[cur], sBc = sB_u[cur];
#pragma unroll
        for (int kk = 0; kk < 4; kk++) {
            const int cA = 2 * kk + cAbit;
            const int cB = 2 * kk + cBbit;
            uint32_t af[2][4], bf[4][2];
#pragma unroll
            for (int mi = 0; mi < 2; mi++)
                ldsm4(af[mi][0], af[mi][1], af[mi][2], af[mi][3],
                      sAc + aRowByte[mi] + (uint32_t)((cA ^ aMask[mi]) << 4));
#pragma unroll
            for (int p = 0; p < 2; p++)
                ldsm4(bf[p*2][0], bf[p*2][1], bf[p*2+1][0], bf[p*2+1][1],
                      sBc + bRowByte[p] + (uint32_t)((cB ^ bMask[p]) << 4));
#pragma unroll
            for (int mi = 0; mi < 2; mi++)
#pragma unroll
                for (int ni = 0; ni < 4; ni++)
                    mma1688(acc[mi][ni], af[mi], bf[ni]);
        }
        __syncthreads();
    }

    // epilogue
#pragma unroll
    for (int mi = 0; mi < 2; mi++) {
#pragma unroll
        for (int ni = 0; ni < 4; ni++) {
            int m0 = bm + wm + mi * 16 + g;
            int n0 = bn + wn + ni * 8 + tig * 2;
#pragma unroll
            for (int half = 0; half < 2; half++) {
                int m = m0 + half * 8;
                size_t off = (size_t)m * N + n0;
                float v0 = acc[mi][ni][half * 2 + 0];
                float v1 = acc[mi][ni][half * 2 + 1];
                if (EPI == 1) {
                    v0 = gelu_f(v0 + bias[n0]); v1 = gelu_f(v1 + bias[n0 + 1]);
                } else if (EPI == 2) {
                    v0 = v0 + bias[n0] + resid[off];
                    v1 = v1 + bias[n0 + 1] + resid[off + 1];
                } else if (EPI == 3) {
                    v0 = silu_f(v0); v1 = silu_f(v1);
                }
                if (RND) { v0 = rnd_tf32(v0); v1 = rnd_tf32(v1); }
                *reinterpret_cast<float2*>(C + off) = make_float2(v0, v1);
            }
        }
    }
}

// ------------------------- RoPE on q,k (in-place, head dim 32) --------
__global__ __launch_bounds__(256)
void rope_qk(float* __restrict__ q, float* __restrict__ k, F16 ft)
{
    int idx = blockIdx.x * blockDim.x + threadIdx.x;
    int i = idx & 15;
    int h = (idx >> 4) & 31;
    int l = idx >> 9;
    float ang = (float)l * ft.f[i];
    float c = cosf(ang), s = sinf(ang);
    size_t base = (size_t)l * HR_DIM + h * D_ATT + i;
    float x1 = q[base], x2 = q[base + 16];
    q[base]      = x1 * c - x2 * s;
    q[base + 16] = x2 * c + x1 * s;
    float y1 = k[base], y2 = k[base + 16];
    k[base]      = y1 * c - y2 * s;
    k[base + 16] = y2 * c + y1 * s;
}

// ------------------------- causal attention ---------------------------
#define AQB 64
#define AKT 128
__global__ __launch_bounds__(256)
void attn_k(const float* __restrict__ Q, const float* __restrict__ K,
            const float* __restrict__ V, float* __restrict__ O)
{
    __shared__ float Ks[AKT][33];
    __shared__ float Vs[AKT][33];
    const int h = blockIdx.y;
    const int q0 = blockIdx.x * AQB;
    const int lane = threadIdx.x & 31;
    const int w = threadIdx.x >> 5;
    const int lbase = q0 + w * 8;

    float qreg[8], m[8], ssum[8], acc[8];
#pragma unroll
    for (int i = 0; i < 8; i++) {
        qreg[i] = Q[(size_t)(lbase + i) * HR_DIM + h * D_ATT + lane] * 0.17677669529663687f;
        m[i] = -INFINITY; ssum[i] = 0.0f; acc[i] = 0.0f;
    }

    const int jmax = q0 + AQB - 1;
    for (int j0 = 0; j0 <= jmax; j0 += AKT) {
        for (int t = threadIdx.x; t < AKT * 32; t += 256) {
            int r = t >> 5, c = t & 31;
            size_t gi = (size_t)(j0 + r) * HR_DIM + h * D_ATT + c;
            Ks[r][c] = K[gi];
            Vs[r][c] = V[gi];
        }
        __syncthreads();

#pragma unroll
        for (int i = 0; i < 8; i++) {
            const int l = lbase + i;
            if (j0 > l) continue;
#pragma unroll 1
            for (int jj = 0; jj < AKT; jj += 32) {
                if (j0 + jj > l) break;
                int j = j0 + jj + lane;
                float s = 0.0f;
#pragma unroll
                for (int d = 0; d < 32; d++)
                    s = fmaf(__shfl_sync(0xffffffffu, qreg[i], d), Ks[jj + lane][d], s);
                if (j > l) s = -1e30f;
                float mc = s;
#pragma unroll
                for (int o = 16; o; o >>= 1) mc = fmaxf(mc, __shfl_xor_sync(0xffffffffu, mc, o));
                float mnew = fmaxf(m[i], mc);
                float alpha = expf(m[i] - mnew);
                float p = expf(s - mnew);
                float psum = p;
#pragma unroll
                for (int o = 16; o; o >>= 1) psum += __shfl_xor_sync(0xffffffffu, psum, o);
                ssum[i] = ssum[i] * alpha + psum;
                acc[i] *= alpha;
#pragma unroll
                for (int j2 = 0; j2 < 32; j2++)
                    acc[i] = fmaf(__shfl_sync(0xffffffffu, p, j2), Vs[jj + j2][lane], acc[i]);
                m[i] = mnew;
            }
        }
        __syncthreads();
    }
#pragma unroll
    for (int i = 0; i < 8; i++)
        O[(size_t)(lbase + i) * HR_DIM + h * D_ATT + lane] = acc[i] / ssum[i];
}

// ------------------------- LayerNorm (rows of 1024) -------------------
// output rounded to tf32 (consumed by ffn1 GEMM A-side)
__global__ __launch_bounds__(256)
void layernorm_k(const float* __restrict__ in, const float* __restrict__ w,
                 const float* __restrict__ b, float* __restrict__ out)
{
    __shared__ float red[8];
    const int row = blockIdx.x;
    const int tid = threadIdx.x;
    const int lane = tid & 31, wid = tid >> 5;
    float4 v = reinterpret_cast<const float4*>(in + (size_t)row * HR_DIM)[tid];

    float s = v.x + v.y + v.z + v.w;
#pragma unroll
    for (int o = 16; o; o >>= 1) s += __shfl_xor_sync(0xffffffffu, s, o);
    if (lane == 0) red[wid] = s;
    __syncthreads();
    float tot = red[0]+red[1]+red[2]+red[3]+red[4]+red[5]+red[6]+red[7];
    float mu = tot * (1.0f / HR_DIM);

    float dx0 = v.x - mu, dx1 = v.y - mu, dx2 = v.z - mu, dx3 = v.w - mu;
    float sq = dx0*dx0 + dx1*dx1 + dx2*dx2 + dx3*dx3;
#pragma unroll
    for (int o = 16; o; o >>= 1) sq += __shfl_xor_sync(0xffffffffu, sq, o);
    __syncthreads();
    if (lane == 0) red[wid] = sq;
    __syncthreads();
    float var = (red[0]+red[1]+red[2]+red[3]+red[4]+red[5]+red[6]+red[7]) * (1.0 / HR_DIM);
    float rstd = rsqrtf(var + 1e-5f);

    float4 wv = reinterpret_cast<const float4*>(w)[tid];
    float4 bv = reinterpret_cast<const float4*>(b)[tid];
    float4 o4;
    o4.x = rnd_tf32(dx0 * rstd * wv.x + bv.x);
    o4.y = rnd_tf32(dx1 * rstd * wv.y + bv.y);
    o4.z = rnd_tf32(dx2 * rstd * wv.z + bv.z);
    o4.w = rnd_tf32(dx3 * rstd * wv.w + bv.w);
    reinterpret_cast<float4*>(out + (size_t)row * HR_DIM)[tid] = o4;
}

// ---------------- importance RoPE + permute to (N,H,L,DD) -------------
__global__ __launch_bounds__(256)
void rope_perm(const float* __restrict__ in, float* __restrict__ out, F8 ft)
{
    int idx = blockIdx.x * blockDim.x + threadIdx.x;
    int i = idx & 7;
    int l = (idx >> 3) & 2047;
    int h = (idx >> 14) & 31;
    int n = idx >> 19;
    float ang = (float)l * ft.f[i];
    float c = cosf(ang), s = sinf(ang);
    size_t ibase = (size_t)l * OUT_FEAT + n * (NH * DD) + h * DD + i;
    float x1 = in[ibase], x2 = in[ibase + 8];
    size_t obase = (((size_t)(n * NH + h)) * L_SEQ + l) * DD + i;
    out[obase]     = x1 * c - x2 * s;
    out[obase + 8] = x2 * c + x1 * s;
}

// ------------------------- launcher -----------------------------------
static void launch_round(const float* src, float* dst, size_t n) {
    round_k<<<(unsigned)(n / 1024), 256>>>((const float4*)src, (float4*)dst);
}

extern "C" void kernel_launch(void* const* d_in, const int* in_sizes, int n_in,
                              void* d_out, int out_size)
{
    const float* x    = (const float*)d_in[0];
    const float* Wi   = (const float*)d_in[1];
    const float* Wq   = (const float*)d_in[2];
    const float* Wk   = (const float*)d_in[3];
    const float* Wv   = (const float*)d_in[4];
    const float* ln1w = (const float*)d_in[5];
    const float* ln1b = (const float*)d_in[6];
    const float* Wf1  = (const float*)d_in[7];
    const float* bf1  = (const float*)d_in[8];
    const float* Wf2  = (const float*)d_in[9];
    const float* bf2  = (const float*)d_in[10];
    const float* Wqi1 = (const float*)d_in[11];
    const float* Wqi2 = (const float*)d_in[12];
    const float* Wki1 = (const float*)d_in[13];
    const float* Wki2 = (const float*)d_in[14];
    float* out = (float*)d_out;

    float *hr,*q,*k,*v,*attn,*ln,*f1,*hid,*aq,*ak,*qi,*ki;
    float *rx,*rWi,*rWq,*rWk,*rWv,*rWf1,*rWf2,*rWqi1,*rWki1,*rWqi2,*rWki2;
    cudaGetSymbolAddress((void**)&hr,   g_hr);
    cudaGetSymbolAddress((void**)&q,    g_q);
    cudaGetSymbolAddress((void**)&k,    g_k);
    cudaGetSymbolAddress((void**)&v,    g_v);
    cudaGetSymbolAddress((void**)&attn, g_attn);
    cudaGetSymbolAddress((void**)&ln,   g_ln);
    cudaGetSymbolAddress((void**)&f1,   g_f1);
    cudaGetSymbolAddress((void**)&hid,  g_hid);
    cudaGetSymbolAddress((void**)&aq,   g_aq);
    cudaGetSymbolAddress((void**)&ak,   g_ak);
    cudaGetSymbolAddress((void**)&qi,   g_qi);
    cudaGetSymbolAddress((void**)&ki,   g_ki);
    cudaGetSymbolAddress((void**)&rx,    g_rx);
    cudaGetSymbolAddress((void**)&rWi,   g_rWi);
    cudaGetSymbolAddress((void**)&rWq,   g_rWq);
    cudaGetSymbolAddress((void**)&rWk,   g_rWk);
    cudaGetSymbolAddress((void**)&rWv,   g_rWv);
    cudaGetSymbolAddress((void**)&rWf1,  g_rWf1);
    cudaGetSymbolAddress((void**)&rWf2,  g_rWf2);
    cudaGetSymbolAddress((void**)&rWqi1, g_rWqi1);
    cudaGetSymbolAddress((void**)&rWki1, g_rWki1);
    cudaGetSymbolAddress((void**)&rWqi2, g_rWqi2);
    cudaGetSymbolAddress((void**)&rWki2, g_rWki2);

    F16 t16; for (int i = 0; i < 16; i++) t16.f[i] = (float)(1.0 / pow(10000.0, (double)i / 16.0));
    F8  t8;  for (int i = 0; i < 8;  i++) t8.f[i]  = (float)(1.0 / pow(10000.0, (double)i / 8.0));

    // pre-round all GEMM operands to tf32 (rna)
    launch_round(x,    rx,    (size_t)L_SEQ*E_DIM);
    launch_round(Wi,   rWi,   (size_t)HR_DIM*E_DIM);
    launch_round(Wq,   rWq,   (size_t)HR_DIM*HR_DIM);
    launch_round(Wk,   rWk,   (size_t)HR_DIM*HR_DIM);
    launch_round(Wv,   rWv,   (size_t)HR_DIM*HR_DIM);
    launch_round(Wf1,  rWf1,  (size_t)2*HR_DIM*HR_DIM);
    launch_round(Wf2,  rWf2,  (size_t)E_DIM*2*HR_DIM);
    launch_round(Wqi1, rWqi1, (size_t)HR_DIM*E_DIM);
    launch_round(Wki1, rWki1, (size_t)HR_DIM*E_DIM);
    launch_round(Wqi2, rWqi2, (size_t)OUT_FEAT*HR_DIM);
    launch_round(Wki2, rWki2, (size_t)OUT_FEAT*HR_DIM);

    GArgs ga;

    // hr = x @ Wi^T   (hr feeds qkv GEMM A-side -> round)
    ga.A[0] = rx; ga.B[0] = rWi; ga.C[0] = hr;
    tgemm<0,1><<<dim3(HR_DIM/64, 16, 1), 256>>>(ga, nullptr, nullptr, HR_DIM, E_DIM);

    // q, k, v (full precision out)
    ga.A[0] = hr; ga.A[1] = hr; ga.A[2] = hr;
    ga.B[0] = rWq; ga.B[1] = rWk; ga.B[2] = rWv;
    ga.C[0] = q;  ga.C[1] = k;  ga.C[2] = v;
    tgemm<0,0><<<dim3(HR_DIM/64, 16, 3), 256>>>(ga, nullptr, nullptr, HR_DIM, HR_DIM);

    rope_qk<<<(L_SEQ*NH*16)/256, 256>>>(q, k, t16);
    attn_k<<<dim3(L_SEQ/AQB, NH), 256>>>(q, k, v, attn);
    layernorm_k<<<L_SEQ, 256>>>(attn, ln1w, ln1b, ln);

    // ffn1: gelu(ln @ Wf1^T + bf1)  -> f1 (A of ffn2 -> round)
    ga.A[0] = ln; ga.B[0] = rWf1; ga.C[0] = f1;
    tgemm<1,1><<<dim3(2*HR_DIM/64, 16, 1), 256>>>(ga, bf1, nullptr, 2*HR_DIM, HR_DIM);

    // ffn2 + residual: hid = x + f1 @ Wf2^T + bf2 (A of silu -> round)
    ga.A[0] = f1; ga.B[0] = rWf2; ga.C[0] = hid;
    tgemm<2,1><<<dim3(E_DIM/64, 16, 1), 256>>>(ga, bf2, x, E_DIM, 2*HR_DIM);

    // silu projections (A of qi/ki -> round)
    ga.A[0] = hid; ga.A[1] = hid;
    ga.B[0] = rWqi1; ga.B[1] = rWki1;
    ga.C[0] = aq;  ga.C[1] = ak;
    tgemm<3,1><<<dim3(HR_DIM/64, 16, 2), 256>>>(ga, nullptr, nullptr, HR_DIM, E_DIM);

    // importance projections (final, full precision out)
    ga.A[0] = aq; ga.A[1] = ak;
    ga.B[0] = rWqi2; ga.B[1] = rWki2;
    ga.C[0] = qi;  ga.C[1] = ki;
    tgemm<0,0><<<dim3(OUT_FEAT/64, 16, 2), 256>>>(ga, nullptr, nullptr, OUT_FEAT, HR_DIM);

    rope_perm<<<(NLAY*NH*L_SEQ*8)/256, 256>>>(qi, out, t8);
    rope_perm<<<(NLAY*NH*L_SEQ*8)/256, 256>>>(ki, out + (size_t)NLAY*NH*L_SEQ*DD, t8);
}

// round 7
// speedup vs baseline: 3.2684x; 1.2308x over previous
#include <cuda_runtime.h>
#include <cuda_fp16.h>
#include <math.h>
#include <stdint.h>

// ------------------------- problem dimensions -------------------------
#define L_SEQ   2048
#define E_DIM   4096
#define HR_DIM  1024
#define NH      32
#define D_ATT   32
#define NLAY    32
#define DD      16
#define OUT_FEAT (NLAY*NH*DD)   // 16384

// ------------------------- scratch (static device mem) ----------------
// fp32 (consumed by non-GEMM stages)
__device__ float g_q   [(size_t)L_SEQ*HR_DIM];
__device__ float g_k   [(size_t)L_SEQ*HR_DIM];
__device__ float g_v   [(size_t)L_SEQ*HR_DIM];
__device__ float g_attn[(size_t)L_SEQ*HR_DIM];
// fp16 GEMM operands
__device__ __half g_xh   [(size_t)L_SEQ*E_DIM];
__device__ __half g_hWi  [(size_t)HR_DIM*E_DIM];
__device__ __half g_hWq  [(size_t)HR_DIM*HR_DIM];
__device__ __half g_hWk  [(size_t)HR_DIM*HR_DIM];
__device__ __half g_hWv  [(size_t)HR_DIM*HR_DIM];
__device__ __half g_hWf1 [(size_t)2*HR_DIM*HR_DIM];
__device__ __half g_hWf2 [(size_t)E_DIM*2*HR_DIM];
__device__ __half g_hWqi1[(size_t)HR_DIM*E_DIM];
__device__ __half g_hWki1[(size_t)HR_DIM*E_DIM];
__device__ __half g_hWqi2[(size_t)OUT_FEAT*HR_DIM];
__device__ __half g_hWki2[(size_t)OUT_FEAT*HR_DIM];
__device__ __half g_hrh  [(size_t)L_SEQ*HR_DIM];
__device__ __half g_lnh  [(size_t)L_SEQ*HR_DIM];
__device__ __half g_f1h  [(size_t)L_SEQ*2*HR_DIM];
__device__ __half g_hidh [(size_t)L_SEQ*E_DIM];
__device__ __half g_aqh  [(size_t)L_SEQ*HR_DIM];
__device__ __half g_akh  [(size_t)L_SEQ*HR_DIM];

struct F16 { float f[16]; };
struct F8  { float f[8];  };
struct GArgs { const __half* A[3]; const __half* B[3]; void* C[3]; };

// ------------------------- helpers ------------------------------------
__device__ __forceinline__ float gelu_f(float x) {
    return 0.5f * x * (1.0f + erff(x * 0.7071067811865476f));
}
__device__ __forceinline__ float silu_f(float x) {
    return x / (1.0f + expf(-x));
}
__device__ __forceinline__ void mma16816(float c[4], const uint32_t a[4], const uint32_t b[2]) {
    asm volatile(
        "mma.sync.aligned.m16n8k16.row.col.f32.f16.f16.f32 "
        "{%0,%1,%2,%3}, {%4,%5,%6,%7}, {%8,%9}, {%0,%1,%2,%3};"
        : "+f"(c[0]), "+f"(c[1]), "+f"(c[2]), "+f"(c[3])
        : "r"(a[0]), "r"(a[1]), "r"(a[2]), "r"(a[3]), "r"(b[0]), "r"(b[1]));
}
__device__ __forceinline__ void cpa16(uint32_t saddr, const __half* g) {
    asm volatile("cp.async.cg.shared.global [%0], [%1], 16;\n" :: "r"(saddr), "l"(g));
}
#define CP_COMMIT() asm volatile("cp.async.commit_group;\n" ::: "memory")
#define CP_WAIT(n)  asm volatile("cp.async.wait_group %0;\n" :: "n"(n) : "memory")
__device__ __forceinline__ void ldsm4(uint32_t& r0, uint32_t& r1, uint32_t& r2, uint32_t& r3,
                                      uint32_t addr) {
    asm volatile("ldmatrix.sync.aligned.m8n8.x4.shared.b16 {%0,%1,%2,%3}, [%4];"
                 : "=r"(r0), "=r"(r1), "=r"(r2), "=r"(r3) : "r"(addr));
}

// ------------------ convert: dst = half(src) --------------------------
__global__ __launch_bounds__(256)
void cvt_k(const float4* __restrict__ in, uint2* __restrict__ out)
{
    int i = blockIdx.x * blockDim.x + threadIdx.x;
    float4 v = in[i];
    __half2 h0 = __floats2half2_rn(v.x, v.y);
    __half2 h1 = __floats2half2_rn(v.z, v.w);
    uint2 o;
    o.x = *reinterpret_cast<uint32_t*>(&h0);
    o.y = *reinterpret_cast<uint32_t*>(&h1);
    out[i] = o;
}

// ---------------- FP16 GEMM: C[2048,N] = A[2048,K] * B[N,K]^T ---------
// CTA tile 128x64x32, 8 warps (4m x 2n), warp tile 32x32.
// 2-stage cp.async; fp16 smem, 16B-chunk swizzle c^= (row>>1)&3; ldmatrix.
// EPI: 0 none, 1 gelu(acc+bias), 2 acc+bias+resid, 3 silu(acc),
//      4 rope+permute into output (qi/ki)
// OUTH: 1 -> store C as fp16 (feeds a later GEMM), 0 -> fp32
template<int EPI, int OUTH>
__global__ __launch_bounds__(256, 2)
void tgemm(GArgs ga, const float* __restrict__ bias,
           const float* __restrict__ resid, int N, int K, F8 ft)
{
    __shared__ __half sA[2][128*32];
    __shared__ __half sB[2][64*32];

    const __half* __restrict__ A = ga.A[blockIdx.z];
    const __half* __restrict__ B = ga.B[blockIdx.z];

    const int tid = threadIdx.x, wid = tid >> 5, lane = tid & 31;
    const int g = lane >> 2, tig = lane & 3;
    const int wmi = wid & 3, wni = wid >> 2;
    const int wm = wmi * 32, wn = wni * 32;
    const int bm = blockIdx.y * 128, bn = blockIdx.x * 64;

    // ---- cp.async loader mapping: rows of 64B (32 halves), 4 chunks ----
    uint32_t sA_u[2], sB_u[2];
    sA_u[0] = (uint32_t)__cvta_generic_to_shared(&sA[0][0]);
    sA_u[1] = (uint32_t)__cvta_generic_to_shared(&sA[1][0]);
    sB_u[0] = (uint32_t)__cvta_generic_to_shared(&sB[0][0]);
    sB_u[1] = (uint32_t)__cvta_generic_to_shared(&sB[1][0]);

    uint32_t aoff[2]; uint32_t boff;
    const __half* aptr[2];
    const __half* bptr;
#pragma unroll
    for (int i = 0; i < 2; i++) {
        int id = tid + i * 256;
        int r = id >> 2, c = id & 3;
        aoff[i] = (uint32_t)(r * 64 + ((c ^ ((r >> 1) & 3)) << 4));
        aptr[i] = A + (size_t)(bm + r) * K + c * 8;
    }
    {
        int r = tid >> 2, c = tid & 3;
        boff = (uint32_t)(r * 64 + ((c ^ ((r >> 1) & 3)) << 4));
        bptr = B + (size_t)(bn + r) * K + c * 8;
    }

    // ---- ldmatrix per-lane address components ----
    const int cAbit = lane >> 4;          // A: chunk bit
    uint32_t aRowByte[2]; int aMask[2];
#pragma unroll
    for (int mi = 0; mi < 2; mi++) {
        int r = wm + mi * 16 + (lane & 15);
        aRowByte[mi] = (uint32_t)(r * 64);
        aMask[mi] = (r >> 1) & 3;
    }
    const int cBbit = (lane >> 3) & 1;    // B: chunk bit
    uint32_t bRowByte[2]; int bMask[2];
#pragma unroll
    for (int p = 0; p < 2; p++) {
        int r = wn + p * 16 + ((lane >> 4) << 3) + (lane & 7);
        bRowByte[p] = (uint32_t)(r * 64);
        bMask[p] = (r >> 1) & 3;
    }

    float acc[2][4][4];
#pragma unroll
    for (int mi = 0; mi < 2; mi++)
#pragma unroll
        for (int ni = 0; ni < 4; ni++)
#pragma unroll
            for (int c = 0; c < 4; c++) acc[mi][ni][c] = 0.0f;

    // prologue: stage 0
#pragma unroll
    for (int i = 0; i < 2; i++) cpa16(sA_u[0] + aoff[i], aptr[i]);
    cpa16(sB_u[0] + boff, bptr);
    CP_COMMIT();
#pragma unroll
    for (int i = 0; i < 2; i++) aptr[i] += 32;
    bptr += 32;

    const int T = K >> 5;
    for (int t = 0; t < T; t++) {
        const int cur = t & 1, nxt = cur ^ 1;
        if (t + 1 < T) {
#pragma unroll
            for (int i = 0; i < 2; i++) cpa16(sA_u[nxt] + aoff[i], aptr[i]);
            cpa16(sB_u[nxt] + boff, bptr);
            CP_COMMIT();
#pragma unroll
            for (int i = 0; i < 2; i++) aptr[i] += 32;
            bptr += 32;
            CP_WAIT(1);
        } else {
            CP_WAIT(0);
        }
        __syncthreads();

        const uint32_t sAc = sA_u[cur], sBc = sB_u[cur];
#pragma unroll
        for (int kk = 0; kk < 2; kk++) {
            uint32_t af[2][4], bf[4][2];
#pragma unroll
            for (int mi = 0; mi < 2; mi++)
                ldsm4(af[mi][0], af[mi][1], af[mi][2], af[mi][3],
                      sAc + aRowByte[mi] + (uint32_t)(((2*kk + cAbit) ^ aMask[mi]) << 4));
#pragma unroll
            for (int p = 0; p < 2; p++)
                ldsm4(bf[p*2][0], bf[p*2][1], bf[p*2+1][0], bf[p*2+1][1],
                      sBc + bRowByte[p] + (uint32_t)(((2*kk + cBbit) ^ bMask[p]) << 4));
#pragma unroll
            for (int mi = 0; mi < 2; mi++)
#pragma unroll
                for (int ni = 0; ni < 4; ni++)
                    mma16816(acc[mi][ni], af[mi], bf[ni]);
        }
        __syncthreads();
    }

    // ---------------- epilogue ----------------
    if (EPI == 4) {
        // rope + permute to (NL, NH, L, DD) in fp32 output
        float* __restrict__ Cf = (float*)ga.C[blockIdx.z];
#pragma unroll
        for (int mi = 0; mi < 2; mi++) {
#pragma unroll
            for (int j = 0; j < 2; j++) {        // DD blocks: ni pair (2j, 2j+1)
                int nb = bn + wn + j * 16;
                int h  = (nb >> 4) & 31;
                int nl = nb >> 9;
                size_t ob0 = ((size_t)(nl * NH + h)) * L_SEQ;
                int i0 = tig * 2;
#pragma unroll
                for (int half = 0; half < 2; half++) {
                    int l = bm + wm + mi * 16 + g + half * 8;
                    size_t ob = (ob0 + l) * DD + i0;
                    float x1a = acc[mi][j*2  ][half*2+0];
                    float x1b = acc[mi][j*2  ][half*2+1];
                    float x2a = acc[mi][j*2+1][half*2+0];
                    float x2b = acc[mi][j*2+1][half*2+1];
                    float a0 = (float)l * ft.f[i0];
                    float a1 = (float)l * ft.f[i0+1];
                    float c0 = cosf(a0), s0 = sinf(a0);
                    float c1 = cosf(a1), s1 = sinf(a1);
                    *reinterpret_cast<float2*>(Cf + ob) =
                        make_float2(x1a*c0 - x2a*s0, x1b*c1 - x2b*s1);
                    *reinterpret_cast<float2*>(Cf + ob + 8) =
                        make_float2(x2a*c0 + x1a*s0, x2b*c1 + x1b*s1);
                }
            }
        }
        return;
    }

#pragma unroll
    for (int mi = 0; mi < 2; mi++) {
#pragma unroll
        for (int ni = 0; ni < 4; ni++) {
            int m0 = bm + wm + mi * 16 + g;
            int n0 = bn + wn + ni * 8 + tig * 2;
#pragma unroll
            for (int half = 0; half < 2; half++) {
                int m = m0 + half * 8;
                size_t off = (size_t)m * N + n0;
                float v0 = acc[mi][ni][half * 2 + 0];
                float v1 = acc[mi][ni][half * 2 + 1];
                if (EPI == 1) {
                    v0 = gelu_f(v0 + bias[n0]); v1 = gelu_f(v1 + bias[n0 + 1]);
                } else if (EPI == 2) {
                    v0 = v0 + bias[n0] + resid[off];
                    v1 = v1 + bias[n0 + 1] + resid[off + 1];
                } else if (EPI == 3) {
                    v0 = silu_f(v0); v1 = silu_f(v1);
                }
                if (OUTH) {
                    __half2 hv = __floats2half2_rn(v0, v1);
                    *reinterpret_cast<__half2*>((__half*)ga.C[blockIdx.z] + off) = hv;
                } else {
                    *reinterpret_cast<float2*>((float*)ga.C[blockIdx.z] + off) =
                        make_float2(v0, v1);
                }
            }
        }
    }
}

// ------------------------- RoPE on q,k (in-place, head dim 32) --------
__global__ __launch_bounds__(256)
void rope_qk(float* __restrict__ q, float* __restrict__ k, F16 ft)
{
    int idx = blockIdx.x * blockDim.x + threadIdx.x;
    int i = idx & 15;
    int h = (idx >> 4) & 31;
    int l = idx >> 9;
    float ang = (float)l * ft.f[i];
    float c = cosf(ang), s = sinf(ang);
    size_t base = (size_t)l * HR_DIM + h * D_ATT + i;
    float x1 = q[base], x2 = q[base + 16];
    q[base]      = x1 * c - x2 * s;
    q[base + 16] = x2 * c + x1 * s;
    float y1 = k[base], y2 = k[base + 16];
    k[base]      = y1 * c - y2 * s;
    k[base + 16] = y2 * c + y1 * s;
}

// ------------------------- causal attention ---------------------------
#define AQB 64
#define AKT 128
__global__ __launch_bounds__(256)
void attn_k(const float* __restrict__ Q, const float* __restrict__ K,
            const float* __restrict__ V, float* __restrict__ O)
{
    __shared__ float Ks[AKT][33];
    __shared__ float Vs[AKT][33];
    const int h = blockIdx.y;
    const int q0 = blockIdx.x * AQB;
    const int lane = threadIdx.x & 31;
    const int w = threadIdx.x >> 5;
    const int lbase = q0 + w * 8;

    float qreg[8], m[8], ssum[8], acc[8];
#pragma unroll
    for (int i = 0; i < 8; i++) {
        qreg[i] = Q[(size_t)(lbase + i) * HR_DIM + h * D_ATT + lane] * 0.17677669529663687f;
        m[i] = -INFINITY; ssum[i] = 0.0f; acc[i] = 0.0f;
    }

    const int jmax = q0 + AQB - 1;
    for (int j0 = 0; j0 <= jmax; j0 += AKT) {
        for (int t = threadIdx.x; t < AKT * 32; t += 256) {
            int r = t >> 5, c = t & 31;
            size_t gi = (size_t)(j0 + r) * HR_DIM + h * D_ATT + c;
            Ks[r][c] = K[gi];
            Vs[r][c] = V[gi];
        }
        __syncthreads();

#pragma unroll
        for (int i = 0; i < 8; i++) {
            const int l = lbase + i;
            if (j0 > l) continue;
#pragma unroll 1
            for (int jj = 0; jj < AKT; jj += 32) {
                if (j0 + jj > l) break;
                int j = j0 + jj + lane;
                float s = 0.0f;
#pragma unroll
                for (int d = 0; d < 32; d++)
                    s = fmaf(__shfl_sync(0xffffffffu, qreg[i], d), Ks[jj + lane][d], s);
                if (j > l) s = -1e30f;
                float mc = s;
#pragma unroll
                for (int o = 16; o; o >>= 1) mc = fmaxf(mc, __shfl_xor_sync(0xffffffffu, mc, o));
                float mnew = fmaxf(m[i], mc);
                float alpha = expf(m[i] - mnew);
                float p = expf(s - mnew);
                float psum = p;
#pragma unroll
                for (int o = 16; o; o >>= 1) psum += __shfl_xor_sync(0xffffffffu, psum, o);
                ssum[i] = ssum[i] * alpha + psum;
                acc[i] *= alpha;
#pragma unroll
                for (int j2 = 0; j2 < 32; j2++)
                    acc[i] = fmaf(__shfl_sync(0xffffffffu, p, j2), Vs[jj + j2][lane], acc[i]);
                m[i] = mnew;
            }
        }
        __syncthreads();
    }
#pragma unroll
    for (int i = 0; i < 8; i++)
        O[(size_t)(lbase + i) * HR_DIM + h * D_ATT + lane] = acc[i] / ssum[i];
}

// ------------------------- LayerNorm (rows of 1024, fp16 out) ---------
__global__ __launch_bounds__(256)
void layernorm_k(const float* __restrict__ in, const float* __restrict__ w,
                 const float* __restrict__ b, __half* __restrict__ out)
{
    __shared__ float red[8];
    const int row = blockIdx.x;
    const int tid = threadIdx.x;
    const int lane = tid & 31, wid = tid >> 5;
    float4 v = reinterpret_cast<const float4*>(in + (size_t)row * HR_DIM)[tid];

    float s = v.x + v.y + v.z + v.w;
#pragma unroll
    for (int o = 16; o; o >>= 1) s += __shfl_xor_sync(0xffffffffu, s, o);
    if (lane == 0) red[wid] = s;
    __syncthreads();
    float tot = red[0]+red[1]+red[2]+red[3]+red[4]+red[5]+red[6]+red[7];
    float mu = tot * (1.0f / HR_DIM);

    float dx0 = v.x - mu, dx1 = v.y - mu, dx2 = v.z - mu, dx3 = v.w - mu;
    float sq = dx0*dx0 + dx1*dx1 + dx2*dx2 + dx3*dx3;
#pragma unroll
    for (int o = 16; o; o >>= 1) sq += __shfl_xor_sync(0xffffffffu, sq, o);
    __syncthreads();
    if (lane == 0) red[wid] = sq;
    __syncthreads();
    float var = (red[0]+red[1]+red[2]+red[3]+red[4]+red[5]+red[6]+red[7]) * (1.0f / HR_DIM);
    float rstd = rsqrtf(var + 1e-5f);

    float4 wv = reinterpret_cast<const float4*>(w)[tid];
    float4 bv = reinterpret_cast<const float4*>(b)[tid];
    __half2 h0 = __floats2half2_rn(dx0 * rstd * wv.x + bv.x, dx1 * rstd * wv.y + bv.y);
    __half2 h1 = __floats2half2_rn(dx2 * rstd * wv.z + bv.z, dx3 * rstd * wv.w + bv.w);
    uint2 o;
    o.x = *reinterpret_cast<uint32_t*>(&h0);
    o.y = *reinterpret_cast<uint32_t*>(&h1);
    reinterpret_cast<uint2*>(out + (size_t)row * HR_DIM)[tid] = o;
}

// ------------------------- launcher -----------------------------------
static void launch_cvt(const float* src, __half* dst, size_t n) {
    cvt_k<<<(unsigned)(n / 1024), 256>>>((const float4*)src, (uint2*)dst);
}

extern "C" void kernel_launch(void* const* d_in, const int* in_sizes, int n_in,
                              void* d_out, int out_size)
{
    const float* x    = (const float*)d_in[0];
    const float* Wi   = (const float*)d_in[1];
    const float* Wq   = (const float*)d_in[2];
    const float* Wk   = (const float*)d_in[3];
    const float* Wv   = (const float*)d_in[4];
    const float* ln1w = (const float*)d_in[5];
    const float* ln1b = (const float*)d_in[6];
    const float* Wf1  = (const float*)d_in[7];
    const float* bf1  = (const float*)d_in[8];
    const float* Wf2  = (const float*)d_in[9];
    const float* bf2  = (const float*)d_in[10];
    const float* Wqi1 = (const float*)d_in[11];
    const float* Wqi2 = (const float*)d_in[12];
    const float* Wki1 = (const float*)d_in[13];
    const float* Wki2 = (const float*)d_in[14];
    float* out = (float*)d_out;

    float *q,*k,*v,*attn;
    __half *xh,*hWi,*hWq,*hWk,*hWv,*hWf1,*hWf2,*hWqi1,*hWki1,*hWqi2,*hWki2;
    __half *hrh,*lnh,*f1h,*hidh,*aqh,*akh;
    cudaGetSymbolAddress((void**)&q,    g_q);
    cudaGetSymbolAddress((void**)&k,    g_k);
    cudaGetSymbolAddress((void**)&v,    g_v);
    cudaGetSymbolAddress((void**)&attn, g_attn);
    cudaGetSymbolAddress((void**)&xh,    g_xh);
    cudaGetSymbolAddress((void**)&hWi,   g_hWi);
    cudaGetSymbolAddress((void**)&hWq,   g_hWq);
    cudaGetSymbolAddress((void**)&hWk,   g_hWk);
    cudaGetSymbolAddress((void**)&hWv,   g_hWv);
    cudaGetSymbolAddress((void**)&hWf1,  g_hWf1);
    cudaGetSymbolAddress((void**)&hWf2,  g_hWf2);
    cudaGetSymbolAddress((void**)&hWqi1, g_hWqi1);
    cudaGetSymbolAddress((void**)&hWki1, g_hWki1);
    cudaGetSymbolAddress((void**)&hWqi2, g_hWqi2);
    cudaGetSymbolAddress((void**)&hWki2, g_hWki2);
    cudaGetSymbolAddress((void**)&hrh,   g_hrh);
    cudaGetSymbolAddress((void**)&lnh,   g_lnh);
    cudaGetSymbolAddress((void**)&f1h,   g_f1h);
    cudaGetSymbolAddress((void**)&hidh,  g_hidh);
    cudaGetSymbolAddress((void**)&aqh,   g_aqh);
    cudaGetSymbolAddress((void**)&akh,   g_akh);

    F16 t16; for (int i = 0; i < 16; i++) t16.f[i] = (float)(1.0 / pow(10000.0, (double)i / 16.0));
    F8  t8;  for (int i = 0; i < 8;  i++) t8.f[i]  = (float)(1.0 / pow(10000.0, (double)i / 8.0));
    F8  t0 = {};

    // convert all GEMM operands to fp16
    launch_cvt(x,    xh,    (size_t)L_SEQ*E_DIM);
    launch_cvt(Wi,   hWi,   (size_t)HR_DIM*E_DIM);
    launch_cvt(Wq,   hWq,   (size_t)HR_DIM*HR_DIM);
    launch_cvt(Wk,   hWk,   (size_t)HR_DIM*HR_DIM);
    launch_cvt(Wv,   hWv,   (size_t)HR_DIM*HR_DIM);
    launch_cvt(Wf1,  hWf1,  (size_t)2*HR_DIM*HR_DIM);
    launch_cvt(Wf2,  hWf2,  (size_t)E_DIM*2*HR_DIM);
    launch_cvt(Wqi1, hWqi1, (size_t)HR_DIM*E_DIM);
    launch_cvt(Wki1, hWki1, (size_t)HR_DIM*E_DIM);
    launch_cvt(Wqi2, hWqi2, (size_t)OUT_FEAT*HR_DIM);
    launch_cvt(Wki2, hWki2, (size_t)OUT_FEAT*HR_DIM);

    GArgs ga;

    // hr = x @ Wi^T  (fp16 out, feeds qkv A-side)
    ga.A[0] = xh; ga.B[0] = hWi; ga.C[0] = hrh;
    tgemm<0,1><<<dim3(HR_DIM/64, 16, 1), 256>>>(ga, nullptr, nullptr, HR_DIM, E_DIM, t0);

    // q, k, v (fp32 out)
    ga.A[0] = hrh; ga.A[1] = hrh; ga.A[2] = hrh;
    ga.B[0] = hWq; ga.B[1] = hWk; ga.B[2] = hWv;
    ga.C[0] = q;  ga.C[1] = k;  ga.C[2] = v;
    tgemm<0,0><<<dim3(HR_DIM/64, 16, 3), 256>>>(ga, nullptr, nullptr, HR_DIM, HR_DIM, t0);

    rope_qk<<<(L_SEQ*NH*16)/256, 256>>>(q, k, t16);
    attn_k<<<dim3(L_SEQ/AQB, NH), 256>>>(q, k, v, attn);
    layernorm_k<<<L_SEQ, 256>>>(attn, ln1w, ln1b, lnh);

    // ffn1: gelu(ln @ Wf1^T + bf1) -> fp16
    ga.A[0] = lnh; ga.B[0] = hWf1; ga.C[0] = f1h;
    tgemm<1,1><<<dim3(2*HR_DIM/64, 16, 1), 256>>>(ga, bf1, nullptr, 2*HR_DIM, HR_DIM, t0);

    // ffn2 + residual: hid = x + f1 @ Wf2^T + bf2 -> fp16
    ga.A[0] = f1h; ga.B[0] = hWf2; ga.C[0] = hidh;
    tgemm<2,1><<<dim3(E_DIM/64, 16, 1), 256>>>(ga, bf2, x, E_DIM, 2*HR_DIM, t0);

    // silu projections -> fp16
    ga.A[0] = hidh; ga.A[1] = hidh;
    ga.B[0] = hWqi1; ga.B[1] = hWki1;
    ga.C[0] = aqh;  ga.C[1] = akh;
    tgemm<3,1><<<dim3(HR_DIM/64, 16, 2), 256>>>(ga, nullptr, nullptr, HR_DIM, E_DIM, t0);

    // importance projections with fused rope+permute into output
    ga.A[0] = aqh; ga.A[1] = akh;
    ga.B[0] = hWqi2; ga.B[1] = hWki2;
    ga.C[0] = out;  ga.C[1] = out + (size_t)NLAY*NH*L_SEQ*DD;
    tgemm<4,0><<<dim3(OUT_FEAT/64, 16, 2), 256>>>(ga, nullptr, nullptr, OUT_FEAT, HR_DIM, t8);
}

// round 8
// speedup vs baseline: 3.6387x; 1.1133x over previous
#include <cuda_runtime.h>
#include <cuda_fp16.h>
#include <math.h>
#include <stdint.h>

// ------------------------- problem dimensions -------------------------
#define L_SEQ   2048
#define E_DIM   4096
#define HR_DIM  1024
#define NH      32
#define D_ATT   32
#define NLAY    32
#define DD      16
#define OUT_FEAT (NLAY*NH*DD)   // 16384

// ------------------------- scratch (static device mem) ----------------
__device__ float g_q   [(size_t)L_SEQ*HR_DIM];
__device__ float g_k   [(size_t)L_SEQ*HR_DIM];
__device__ float g_v   [(size_t)L_SEQ*HR_DIM];
__device__ float g_attn[(size_t)L_SEQ*HR_DIM];
__device__ __half g_xh   [(size_t)L_SEQ*E_DIM];
__device__ __half g_hWi  [(size_t)HR_DIM*E_DIM];
__device__ __half g_hWq  [(size_t)HR_DIM*HR_DIM];
__device__ __half g_hWk  [(size_t)HR_DIM*HR_DIM];
__device__ __half g_hWv  [(size_t)HR_DIM*HR_DIM];
__device__ __half g_hWf1 [(size_t)2*HR_DIM*HR_DIM];
__device__ __half g_hWf2 [(size_t)E_DIM*2*HR_DIM];
__device__ __half g_hWqi1[(size_t)HR_DIM*E_DIM];
__device__ __half g_hWki1[(size_t)HR_DIM*E_DIM];
__device__ __half g_hWqi2[(size_t)OUT_FEAT*HR_DIM];
__device__ __half g_hWki2[(size_t)OUT_FEAT*HR_DIM];
__device__ __half g_hrh  [(size_t)L_SEQ*HR_DIM];
__device__ __half g_lnh  [(size_t)L_SEQ*HR_DIM];
__device__ __half g_f1h  [(size_t)L_SEQ*2*HR_DIM];
__device__ __half g_hidh [(size_t)L_SEQ*E_DIM];
__device__ __half g_aqh  [(size_t)L_SEQ*HR_DIM];
__device__ __half g_akh  [(size_t)L_SEQ*HR_DIM];

struct F16 { float f[16]; };
struct F8  { float f[8];  };
struct GArgs { const __half* A[3]; const __half* B[3]; void* C[3]; };

// ------------------------- helpers ------------------------------------
__device__ __forceinline__ float gelu_f(float x) {
    return 0.5f * x * (1.0f + erff(x * 0.7071067811865476f));
}
__device__ __forceinline__ float silu_f(float x) {
    return x / (1.0f + expf(-x));
}
__device__ __forceinline__ void mma16816(float c[4], const uint32_t a[4], const uint32_t b[2]) {
    asm volatile(
        "mma.sync.aligned.m16n8k16.row.col.f32.f16.f16.f32 "
        "{%0,%1,%2,%3}, {%4,%5,%6,%7}, {%8,%9}, {%0,%1,%2,%3};"
        : "+f"(c[0]), "+f"(c[1]), "+f"(c[2]), "+f"(c[3])
        : "r"(a[0]), "r"(a[1]), "r"(a[2]), "r"(a[3]), "r"(b[0]), "r"(b[1]));
}
__device__ __forceinline__ void cpa16(uint32_t saddr, const __half* g) {
    asm volatile("cp.async.cg.shared.global [%0], [%1], 16;\n" :: "r"(saddr), "l"(g));
}
#define CP_COMMIT() asm volatile("cp.async.commit_group;\n" ::: "memory")
#define CP_WAIT(n)  asm volatile("cp.async.wait_group %0;\n" :: "n"(n) : "memory")
__device__ __forceinline__ void ldsm4(uint32_t& r0, uint32_t& r1, uint32_t& r2, uint32_t& r3,
                                      uint32_t addr) {
    asm volatile("ldmatrix.sync.aligned.m8n8.x4.shared.b16 {%0,%1,%2,%3}, [%4];"
                 : "=r"(r0), "=r"(r1), "=r"(r2), "=r"(r3) : "r"(addr));
}

// ------------------ convert: dst = half(src) --------------------------
__global__ __launch_bounds__(256)
void cvt_k(const float4* __restrict__ in, uint2* __restrict__ out)
{
    int i = blockIdx.x * blockDim.x + threadIdx.x;
    float4 v = in[i];
    __half2 h0 = __floats2half2_rn(v.x, v.y);
    __half2 h1 = __floats2half2_rn(v.z, v.w);
    uint2 o;
    o.x = *reinterpret_cast<uint32_t*>(&h0);
    o.y = *reinterpret_cast<uint32_t*>(&h1);
    out[i] = o;
}

// ---------------- FP16 GEMM: C[2048,N] = A[2048,K] * B[N,K]^T ---------
// CTA tile 128x128x32, 8 warps (2m x 4n), warp tile 64x32.
// 2-stage cp.async; fp16 smem, 16B-chunk swizzle c ^= (row>>1)&3; ldmatrix.
// EPI: 0 none, 1 gelu(acc+bias), 2 acc+bias+resid, 3 silu(acc),
//      4 rope+permute into output (qi/ki)
// OUTH: 1 -> store C as fp16 (feeds a later GEMM), 0 -> fp32
template<int EPI, int OUTH>
__global__ __launch_bounds__(256, 2)
void tgemm(GArgs ga, const float* __restrict__ bias,
           const float* __restrict__ resid, int N, int K, F8 ft)
{
    __shared__ __half sA[2][128*32];
    __shared__ __half sB[2][128*32];

    const __half* __restrict__ A = ga.A[blockIdx.z];
    const __half* __restrict__ B = ga.B[blockIdx.z];

    const int tid = threadIdx.x, wid = tid >> 5, lane = tid & 31;
    const int g = lane >> 2, tig = lane & 3;
    const int wm = (wid & 1) * 64;        // 2 m-warps
    const int wn = (wid >> 1) * 32;       // 4 n-warps
    const int bm = blockIdx.y * 128, bn = blockIdx.x * 128;

    uint32_t sA_u[2], sB_u[2];
    sA_u[0] = (uint32_t)__cvta_generic_to_shared(&sA[0][0]);
    sA_u[1] = (uint32_t)__cvta_generic_to_shared(&sA[1][0]);
    sB_u[0] = (uint32_t)__cvta_generic_to_shared(&sB[0][0]);
    sB_u[1] = (uint32_t)__cvta_generic_to_shared(&sB[1][0]);

    uint32_t aoff[2], boff[2];
    const __half* aptr[2];
    const __half* bptr[2];
#pragma unroll
    for (int i = 0; i < 2; i++) {
        int id = tid + i * 256;
        int r = id >> 2, c = id & 3;
        uint32_t off = (uint32_t)(r * 64 + ((c ^ ((r >> 1) & 3)) << 4));
        aoff[i] = off;
        boff[i] = off;
        aptr[i] = A + (size_t)(bm + r) * K + c * 8;
        bptr[i] = B + (size_t)(bn + r) * K + c * 8;
    }

    // ---- ldmatrix per-lane address components ----
    const int cAbit = lane >> 4;          // A chunk bit
    uint32_t aRowByte[4]; int aMask[4];
#pragma unroll
    for (int mi = 0; mi < 4; mi++) {
        int r = wm + mi * 16 + (lane & 15);
        aRowByte[mi] = (uint32_t)(r * 64);
        aMask[mi] = (r >> 1) & 3;
    }
    const int cBbit = (lane >> 3) & 1;    // B chunk bit
    uint32_t bRowByte[2]; int bMask[2];
#pragma unroll
    for (int p = 0; p < 2; p++) {
        int r = wn + p * 16 + ((lane >> 4) << 3) + (lane & 7);
        bRowByte[p] = (uint32_t)(r * 64);
        bMask[p] = (r >> 1) & 3;
    }

    float acc[4][4][4];
#pragma unroll
    for (int mi = 0; mi < 4; mi++)
#pragma unroll
        for (int ni = 0; ni < 4; ni++)
#pragma unroll
            for (int c = 0; c < 4; c++) acc[mi][ni][c] = 0.0f;

    // prologue: stage 0
#pragma unroll
    for (int i = 0; i < 2; i++) { cpa16(sA_u[0] + aoff[i], aptr[i]); }
#pragma unroll
    for (int i = 0; i < 2; i++) { cpa16(sB_u[0] + boff[i], bptr[i]); }
    CP_COMMIT();
#pragma unroll
    for (int i = 0; i < 2; i++) { aptr[i] += 32; bptr[i] += 32; }

    const int T = K >> 5;
    for (int t = 0; t < T; t++) {
        const int cur = t & 1, nxt = cur ^ 1;
        if (t + 1 < T) {
#pragma unroll
            for (int i = 0; i < 2; i++) { cpa16(sA_u[nxt] + aoff[i], aptr[i]); }
#pragma unroll
            for (int i = 0; i < 2; i++) { cpa16(sB_u[nxt] + boff[i], bptr[i]); }
            CP_COMMIT();
#pragma unroll
            for (int i = 0; i < 2; i++) { aptr[i] += 32; bptr[i] += 32; }
            CP_WAIT(1);
        } else {
            CP_WAIT(0);
        }
        __syncthreads();

        const uint32_t sAc = sA_u[cur], sBc = sB_u[cur];
#pragma unroll
        for (int kk = 0; kk < 2; kk++) {
            uint32_t af[4][4], bf[4][2];
#pragma unroll
            for (int mi = 0; mi < 4; mi++)
                ldsm4(af[mi][0], af[mi][1], af[mi][2], af[mi][3],
                      sAc + aRowByte[mi] + (uint32_t)(((2*kk + cAbit) ^ aMask[mi]) << 4));
#pragma unroll
            for (int p = 0; p < 2; p++)
                ldsm4(bf[p*2][0], bf[p*2][1], bf[p*2+1][0], bf[p*2+1][1],
                      sBc + bRowByte[p] + (uint32_t)(((2*kk + cBbit) ^ bMask[p]) << 4));
#pragma unroll
            for (int mi = 0; mi < 4; mi++)
#pragma unroll
                for (int ni = 0; ni < 4; ni++)
                    mma16816(acc[mi][ni], af[mi], bf[ni]);
        }
        __syncthreads();
    }

    // ---------------- epilogue ----------------
    if (EPI == 4) {
        // rope + permute to (NL, NH, L, DD) in fp32 output
        float* __restrict__ Cf = (float*)ga.C[blockIdx.z];
#pragma unroll
        for (int mi = 0; mi < 4; mi++) {
#pragma unroll
            for (int j = 0; j < 2; j++) {        // DD blocks: ni pair (2j, 2j+1)
                int nb = bn + wn + j * 16;
                int h  = (nb >> 4) & 31;
                int nl = nb >> 9;
                size_t ob0 = ((size_t)(nl * NH + h)) * L_SEQ;
                int i0 = tig * 2;
#pragma unroll
                for (int half = 0; half < 2; half++) {
                    int l = bm + wm + mi * 16 + g + half * 8;
                    size_t ob = (ob0 + l) * DD + i0;
                    float x1a = acc[mi][j*2  ][half*2+0];
                    float x1b = acc[mi][j*2  ][half*2+1];
                    float x2a = acc[mi][j*2+1][half*2+0];
                    float x2b = acc[mi][j*2+1][half*2+1];
                    float a0 = (float)l * ft.f[i0];
                    float a1 = (float)l * ft.f[i0+1];
                    float c0 = cosf(a0), s0 = sinf(a0);
                    float c1 = cosf(a1), s1 = sinf(a1);
                    *reinterpret_cast<float2*>(Cf + ob) =
                        make_float2(x1a*c0 - x2a*s0, x1b*c1 - x2b*s1);
                    *reinterpret_cast<float2*>(Cf + ob + 8) =
                        make_float2(x2a*c0 + x1a*s0, x2b*c1 + x1b*s1);
                }
            }
        }
        return;
    }

#pragma unroll
    for (int mi = 0; mi < 4; mi++) {
#pragma unroll
        for (int ni = 0; ni < 4; ni++) {
            int m0 = bm + wm + mi * 16 + g;
            int n0 = bn + wn + ni * 8 + tig * 2;
#pragma unroll
            for (int half = 0; half < 2; half++) {
                int m = m0 + half * 8;
                size_t off = (size_t)m * N + n0;
                float v0 = acc[mi][ni][half * 2 + 0];
                float v1 = acc[mi][ni][half * 2 + 1];
                if (EPI == 1) {
                    v0 = gelu_f(v0 + bias[n0]); v1 = gelu_f(v1 + bias[n0 + 1]);
                } else if (EPI == 2) {
                    v0 = v0 + bias[n0] + resid[off];
                    v1 = v1 + bias[n0 + 1] + resid[off + 1];
                } else if (EPI == 3) {
                    v0 = silu_f(v0); v1 = silu_f(v1);
                }
                if (OUTH) {
                    __half2 hv = __floats2half2_rn(v0, v1);
                    *reinterpret_cast<__half2*>((__half*)ga.C[blockIdx.z] + off) = hv;
                } else {
                    *reinterpret_cast<float2*>((float*)ga.C[blockIdx.z] + off) =
                        make_float2(v0, v1);
                }
            }
        }
    }
}

// ------------------------- RoPE on q,k (in-place, head dim 32) --------
__global__ __launch_bounds__(256)
void rope_qk(float* __restrict__ q, float* __restrict__ k, F16 ft)
{
    int idx = blockIdx.x * blockDim.x + threadIdx.x;
    int i = idx & 15;
    int h = (idx >> 4) & 31;
    int l = idx >> 9;
    float ang = (float)l * ft.f[i];
    float c = cosf(ang), s = sinf(ang);
    size_t base = (size_t)l * HR_DIM + h * D_ATT + i;
    float x1 = q[base], x2 = q[base + 16];
    q[base]      = x1 * c - x2 * s;
    q[base + 16] = x2 * c + x1 * s;
    float y1 = k[base], y2 = k[base + 16];
    k[base]      = y1 * c - y2 * s;
    k[base + 16] = y2 * c + y1 * s;
}

// ------------------------- causal attention ---------------------------
#define AQB 64
#define AKT 128
__global__ __launch_bounds__(256)
void attn_k(const float* __restrict__ Q, const float* __restrict__ K,
            const float* __restrict__ V, float* __restrict__ O)
{
    __shared__ float Ks[AKT][33];
    __shared__ float Vs[AKT][33];
    const int h = blockIdx.y;
    const int q0 = blockIdx.x * AQB;
    const int lane = threadIdx.x & 31;
    const int w = threadIdx.x >> 5;
    const int lbase = q0 + w * 8;

    float qreg[8], m[8], ssum[8], acc[8];
#pragma unroll
    for (int i = 0; i < 8; i++) {
        qreg[i] = Q[(size_t)(lbase + i) * HR_DIM + h * D_ATT + lane] * 0.17677669529663687f;
        m[i] = -INFINITY; ssum[i] = 0.0f; acc[i] = 0.0f;
    }

    const int jmax = q0 + AQB - 1;
    for (int j0 = 0; j0 <= jmax; j0 += AKT) {
        for (int t = threadIdx.x; t < AKT * 32; t += 256) {
            int r = t >> 5, c = t & 31;
            size_t gi = (size_t)(j0 + r) * HR_DIM + h * D_ATT + c;
            Ks[r][c] = K[gi];
            Vs[r][c] = V[gi];
        }
        __syncthreads();

#pragma unroll
        for (int i = 0; i < 8; i++) {
            const int l = lbase + i;
            if (j0 > l) continue;
#pragma unroll 1
            for (int jj = 0; jj < AKT; jj += 32) {
                if (j0 + jj > l) break;
                int j = j0 + jj + lane;
                float s = 0.0f;
#pragma unroll
                for (int d = 0; d < 32; d++)
                    s = fmaf(__shfl_sync(0xffffffffu, qreg[i], d), Ks[jj + lane][d], s);
                if (j > l) s = -1e30f;
                float mc = s;
#pragma unroll
                for (int o = 16; o; o >>= 1) mc = fmaxf(mc, __shfl_xor_sync(0xffffffffu, mc, o));
                float mnew = fmaxf(m[i], mc);
                float alpha = expf(m[i] - mnew);
                float p = expf(s - mnew);
                float psum = p;
#pragma unroll
                for (int o = 16; o; o >>= 1) psum += __shfl_xor_sync(0xffffffffu, psum, o);
                ssum[i] = ssum[i] * alpha + psum;
                acc[i] *= alpha;
#pragma unroll
                for (int j2 = 0; j2 < 32; j2++)
                    acc[i] = fmaf(__shfl_sync(0xffffffffu, p, j2), Vs[jj + j2][lane], acc[i]);
                m[i] = mnew;
            }
        }
        __syncthreads();
    }
#pragma unroll
    for (int i = 0; i < 8; i++)
        O[(size_t)(lbase + i) * HR_DIM + h * D_ATT + lane] = acc[i] / ssum[i];
}

// ------------------------- LayerNorm (rows of 1024, fp16 out) ---------
__global__ __launch_bounds__(256)
void layernorm_k(const float* __restrict__ in, const float* __restrict__ w,
                 const float* __restrict__ b, __half* __restrict__ out)
{
    __shared__ float red[8];
    const int row = blockIdx.x;
    const int tid = threadIdx.x;
    const int lane = tid & 31, wid = tid >> 5;
    float4 v = reinterpret_cast<const float4*>(in + (size_t)row * HR_DIM)[tid];

    float s = v.x + v.y + v.z + v.w;
#pragma unroll
    for (int o = 16; o; o >>= 1) s += __shfl_xor_sync(0xffffffffu, s, o);
    if (lane == 0) red[wid] = s;
    __syncthreads();
    float tot = red[0]+red[1]+red[2]+red[3]+red[4]+red[5]+red[6]+red[7];
    float mu = tot * (1.0f / HR_DIM);

    float dx0 = v.x - mu, dx1 = v.y - mu, dx2 = v.z - mu, dx3 = v.w - mu;
    float sq = dx0*dx0 + dx1*dx1 + dx2*dx2 + dx3*dx3;
#pragma unroll
    for (int o = 16; o; o >>= 1) sq += __shfl_xor_sync(0xffffffffu, sq, o);
    __syncthreads();
    if (lane == 0) red[wid] = sq;
    __syncthreads();
    float var = (red[0]+red[1]+red[2]+red[3]+red[4]+red[5]+red[6]+red[7]) * (1.0f / HR_DIM);
    float rstd = rsqrtf(var + 1e-5f);

    float4 wv = reinterpret_cast<const float4*>(w)[tid];
    float4 bv = reinterpret_cast<const float4*>(b)[tid];
    __half2 h0 = __floats2half2_rn(dx0 * rstd * wv.x + bv.x, dx1 * rstd * wv.y + bv.y);
    __half2 h1 = __floats2half2_rn(dx2 * rstd * wv.z + bv.z, dx3 * rstd * wv.w + bv.w);
    uint2 o;
    o.x = *reinterpret_cast<uint32_t*>(&h0);
    o.y = *reinterpret_cast<uint32_t*>(&h1);
    reinterpret_cast<uint2*>(out + (size_t)row * HR_DIM)[tid] = o;
}

// ------------------------- launcher -----------------------------------
static void launch_cvt(const float* src, __half* dst, size_t n) {
    cvt_k<<<(unsigned)(n / 1024), 256>>>((const float4*)src, (uint2*)dst);
}

extern "C" void kernel_launch(void* const* d_in, const int* in_sizes, int n_in,
                              void* d_out, int out_size)
{
    const float* x    = (const float*)d_in[0];
    const float* Wi   = (const float*)d_in[1];
    const float* Wq   = (const float*)d_in[2];
    const float* Wk   = (const float*)d_in[3];
    const float* Wv   = (const float*)d_in[4];
    const float* ln1w = (const float*)d_in[5];
    const float* ln1b = (const float*)d_in[6];
    const float* Wf1  = (const float*)d_in[7];
    const float* bf1  = (const float*)d_in[8];
    const float* Wf2  = (const float*)d_in[9];
    const float* bf2  = (const float*)d_in[10];
    const float* Wqi1 = (const float*)d_in[11];
    const float* Wqi2 = (const float*)d_in[12];
    const float* Wki1 = (const float*)d_in[13];
    const float* Wki2 = (const float*)d_in[14];
    float* out = (float*)d_out;

    float *q,*k,*v,*attn;
    __half *xh,*hWi,*hWq,*hWk,*hWv,*hWf1,*hWf2,*hWqi1,*hWki1,*hWqi2,*hWki2;
    __half *hrh,*lnh,*f1h,*hidh,*aqh,*akh;
    cudaGetSymbolAddress((void**)&q,    g_q);
    cudaGetSymbolAddress((void**)&k,    g_k);
    cudaGetSymbolAddress((void**)&v,    g_v);
    cudaGetSymbolAddress((void**)&attn, g_attn);
    cudaGetSymbolAddress((void**)&xh,    g_xh);
    cudaGetSymbolAddress((void**)&hWi,   g_hWi);
    cudaGetSymbolAddress((void**)&hWq,   g_hWq);
    cudaGetSymbolAddress((void**)&hWk,   g_hWk);
    cudaGetSymbolAddress((void**)&hWv,   g_hWv);
    cudaGetSymbolAddress((void**)&hWf1,  g_hWf1);
    cudaGetSymbolAddress((void**)&hWf2,  g_hWf2);
    cudaGetSymbolAddress((void**)&hWqi1, g_hWqi1);
    cudaGetSymbolAddress((void**)&hWki1, g_hWki1);
    cudaGetSymbolAddress((void**)&hWqi2, g_hWqi2);
    cudaGetSymbolAddress((void**)&hWki2, g_hWki2);
    cudaGetSymbolAddress((void**)&hrh,   g_hrh);
    cudaGetSymbolAddress((void**)&lnh,   g_lnh);
    cudaGetSymbolAddress((void**)&f1h,   g_f1h);
    cudaGetSymbolAddress((void**)&hidh,  g_hidh);
    cudaGetSymbolAddress((void**)&aqh,   g_aqh);
    cudaGetSymbolAddress((void**)&akh,   g_akh);

    F16 t16; for (int i = 0; i < 16; i++) t16.f[i] = (float)(1.0 / pow(10000.0, (double)i / 16.0));
    F8  t8;  for (int i = 0; i < 8;  i++) t8.f[i]  = (float)(1.0 / pow(10000.0, (double)i / 8.0));
    F8  t0 = {};

    // convert all GEMM operands to fp16
    launch_cvt(x,    xh,    (size_t)L_SEQ*E_DIM);
    launch_cvt(Wi,   hWi,   (size_t)HR_DIM*E_DIM);
    launch_cvt(Wq,   hWq,   (size_t)HR_DIM*HR_DIM);
    launch_cvt(Wk,   hWk,   (size_t)HR_DIM*HR_DIM);
    launch_cvt(Wv,   hWv,   (size_t)HR_DIM*HR_DIM);
    launch_cvt(Wf1,  hWf1,  (size_t)2*HR_DIM*HR_DIM);
    launch_cvt(Wf2,  hWf2,  (size_t)E_DIM*2*HR_DIM);
    launch_cvt(Wqi1, hWqi1, (size_t)HR_DIM*E_DIM);
    launch_cvt(Wki1, hWki1, (size_t)HR_DIM*E_DIM);
    launch_cvt(Wqi2, hWqi2, (size_t)OUT_FEAT*HR_DIM);
    launch_cvt(Wki2, hWki2, (size_t)OUT_FEAT*HR_DIM);

    GArgs ga;

    // hr = x @ Wi^T  (fp16 out, feeds qkv A-side)
    ga.A[0] = xh; ga.B[0] = hWi; ga.C[0] = hrh;
    tgemm<0,1><<<dim3(HR_DIM/128, 16, 1), 256>>>(ga, nullptr, nullptr, HR_DIM, E_DIM, t0);

    // q, k, v (fp32 out)
    ga.A[0] = hrh; ga.A[1] = hrh; ga.A[2] = hrh;
    ga.B[0] = hWq; ga.B[1] = hWk; ga.B[2] = hWv;
    ga.C[0] = q;  ga.C[1] = k;  ga.C[2] = v;
    tgemm<0,0><<<dim3(HR_DIM/128, 16, 3), 256>>>(ga, nullptr, nullptr, HR_DIM, HR_DIM, t0);

    rope_qk<<<(L_SEQ*NH*16)/256, 256>>>(q, k, t16);
    attn_k<<<dim3(L_SEQ/AQB, NH), 256>>>(q, k, v, attn);
    layernorm_k<<<L_SEQ, 256>>>(attn, ln1w, ln1b, lnh);

    // ffn1: gelu(ln @ Wf1^T + bf1) -> fp16
    ga.A[0] = lnh; ga.B[0] = hWf1; ga.C[0] = f1h;
    tgemm<1,1><<<dim3(2*HR_DIM/128, 16, 1), 256>>>(ga, bf1, nullptr, 2*HR_DIM, HR_DIM, t0);

    // ffn2 + residual: hid = x + f1 @ Wf2^T + bf2 -> fp16
    ga.A[0] = f1h; ga.B[0] = hWf2; ga.C[0] = hidh;
    tgemm<2,1><<<dim3(E_DIM/128, 16, 1), 256>>>(ga, bf2, x, E_DIM, 2*HR_DIM, t0);

    // silu projections -> fp16
    ga.A[0] = hidh; ga.A[1] = hidh;
    ga.B[0] = hWqi1; ga.B[1] = hWki1;
    ga.C[0] = aqh;  ga.C[1] = akh;
    tgemm<3,1><<<dim3(HR_DIM/128, 16, 2), 256>>>(ga, nullptr, nullptr, HR_DIM, E_DIM, t0);

    // importance projections with fused rope+permute into output
    ga.A[0] = aqh; ga.A[1] = akh;
    ga.B[0] = hWqi2; ga.B[1] = hWki2;
    ga.C[0] = out;  ga.C[1] = out + (size_t)NLAY*NH*L_SEQ*DD;
    tgemm<4,0><<<dim3(OUT_FEAT/128, 16, 2), 256>>>(ga, nullptr, nullptr, OUT_FEAT, HR_DIM, t8);
}

// round 10
// speedup vs baseline: 8.6159x; 2.3679x over previous
#include <cuda_runtime.h>
#include <cuda_fp16.h>
#include <math.h>
#include <stdint.h>

// ------------------------- problem dimensions -------------------------
#define L_SEQ   2048
#define E_DIM   4096
#define HR_DIM  1024
#define NH      32
#define D_ATT   32
#define NLAY    32
#define DD      16
#define OUT_FEAT (NLAY*NH*DD)   // 16384

// ------------------------- scratch (static device mem) ----------------
__device__ float g_attn[(size_t)L_SEQ*HR_DIM];
__device__ __half g_xh   [(size_t)L_SEQ*E_DIM];
__device__ __half g_hWi  [(size_t)HR_DIM*E_DIM];
__device__ __half g_hWq  [(size_t)HR_DIM*HR_DIM];
__device__ __half g_hWk  [(size_t)HR_DIM*HR_DIM];
__device__ __half g_hWv  [(size_t)HR_DIM*HR_DIM];
__device__ __half g_hWf1 [(size_t)2*HR_DIM*HR_DIM];
__device__ __half g_hWf2 [(size_t)E_DIM*2*HR_DIM];
__device__ __half g_hWqi1[(size_t)HR_DIM*E_DIM];
__device__ __half g_hWki1[(size_t)HR_DIM*E_DIM];
__device__ __half g_hWqi2[(size_t)OUT_FEAT*HR_DIM];
__device__ __half g_hWki2[(size_t)OUT_FEAT*HR_DIM];
__device__ __half g_hrh  [(size_t)L_SEQ*HR_DIM];
__device__ __half g_qh   [(size_t)L_SEQ*HR_DIM];
__device__ __half g_kh   [(size_t)L_SEQ*HR_DIM];
__device__ __half g_vh   [(size_t)L_SEQ*HR_DIM];
__device__ __half g_lnh  [(size_t)L_SEQ*HR_DIM];
__device__ __half g_f1h  [(size_t)L_SEQ*2*HR_DIM];
__device__ __half g_hidh [(size_t)L_SEQ*E_DIM];
__device__ __half g_aqh  [(size_t)L_SEQ*HR_DIM];
__device__ __half g_akh  [(size_t)L_SEQ*HR_DIM];

struct F16 { float f[16]; };
struct GArgs { const __half* A[3]; const __half* B[3]; void* C[3]; };

// ------------------------- helpers ------------------------------------
__device__ __forceinline__ float gelu_f(float x) {
    return 0.5f * x * (1.0f + erff(x * 0.7071067811865476f));
}
__device__ __forceinline__ float silu_f(float x) {
    return x / (1.0f + expf(-x));
}
__device__ __forceinline__ void mma16816(float c[4], const uint32_t a[4], const uint32_t b[2]) {
    asm volatile(
        "mma.sync.aligned.m16n8k16.row.col.f32.f16.f16.f32 "
        "{%0,%1,%2,%3}, {%4,%5,%6,%7}, {%8,%9}, {%0,%1,%2,%3};"
        : "+f"(c[0]), "+f"(c[1]), "+f"(c[2]), "+f"(c[3])
        : "r"(a[0]), "r"(a[1]), "r"(a[2]), "r"(a[3]), "r"(b[0]), "r"(b[1]));
}
__device__ __forceinline__ void cpa16(uint32_t saddr, const __half* g) {
    asm volatile("cp.async.cg.shared.global [%0], [%1], 16;\n" :: "r"(saddr), "l"(g));
}
#define CP_COMMIT() asm volatile("cp.async.commit_group;\n" ::: "memory")
#define CP_WAIT(n)  asm volatile("cp.async.wait_group %0;\n" :: "n"(n) : "memory")
__device__ __forceinline__ void ldsm4(uint32_t& r0, uint32_t& r1, uint32_t& r2, uint32_t& r3,
                                      uint32_t addr) {
    asm volatile("ldmatrix.sync.aligned.m8n8.x4.shared.b16 {%0,%1,%2,%3}, [%4];"
                 : "=r"(r0), "=r"(r1), "=r"(r2), "=r"(r3) : "r"(addr));
}
__device__ __forceinline__ void ldsm4t(uint32_t& r0, uint32_t& r1, uint32_t& r2, uint32_t& r3,
                                       uint32_t addr) {
    asm volatile("ldmatrix.sync.aligned.m8n8.x4.trans.shared.b16 {%0,%1,%2,%3}, [%4];"
                 : "=r"(r0), "=r"(r1), "=r"(r2), "=r"(r3) : "r"(addr));
}
__device__ __forceinline__ uint32_t packh2(float a, float b) {
    __half2 h = __floats2half2_rn(a, b);
    return *reinterpret_cast<uint32_t*>(&h);
}

// ------------------ convert: dst = half(src) --------------------------
__global__ __launch_bounds__(256)
void cvt_k(const float4* __restrict__ in, uint2* __restrict__ out)
{
    int i = blockIdx.x * blockDim.x + threadIdx.x;
    float4 v = in[i];
    uint2 o;
    o.x = packh2(v.x, v.y);
    o.y = packh2(v.z, v.w);
    out[i] = o;
}

// ---------------- FP16 GEMM: C[2048,N] = A[2048,K] * B[N,K]^T ---------
// CTA tile 128x128x32, 8 warps (2m x 4n), warp tile 64x32.
// EPI: 0 none, 1 gelu(acc+bias), 2 acc+bias+resid, 3 silu(acc),
//      4 rope+permute into output (qi/ki), 5 qkv rope (z<2) fp16 out
// OUTH: 1 -> fp16 C, 0 -> fp32 C
template<int EPI, int OUTH>
__global__ __launch_bounds__(256, 2)
void tgemm(GArgs ga, const float* __restrict__ bias,
           const float* __restrict__ resid, int N, int K, F16 ft)
{
    __shared__ __align__(16) __half sA[2][128*32];
    __shared__ __align__(16) __half sB[2][128*32];

    const __half* __restrict__ A = ga.A[blockIdx.z];
    const __half* __restrict__ B = ga.B[blockIdx.z];

    const int tid = threadIdx.x, wid = tid >> 5, lane = tid & 31;
    const int g = lane >> 2, tig = lane & 3;
    const int wm = (wid & 1) * 64;
    const int wn = (wid >> 1) * 32;
    const int bm = blockIdx.y * 128, bn = blockIdx.x * 128;

    uint32_t sA_u[2], sB_u[2];
    sA_u[0] = (uint32_t)__cvta_generic_to_shared(&sA[0][0]);
    sA_u[1] = (uint32_t)__cvta_generic_to_shared(&sA[1][0]);
    sB_u[0] = (uint32_t)__cvta_generic_to_shared(&sB[0][0]);
    sB_u[1] = (uint32_t)__cvta_generic_to_shared(&sB[1][0]);

    uint32_t aoff[2], boff[2];
    const __half* aptr[2];
    const __half* bptr[2];
#pragma unroll
    for (int i = 0; i < 2; i++) {
        int id = tid + i * 256;
        int r = id >> 2, c = id & 3;
        uint32_t off = (uint32_t)(r * 64 + ((c ^ ((r >> 1) & 3)) << 4));
        aoff[i] = off; boff[i] = off;
        aptr[i] = A + (size_t)(bm + r) * K + c * 8;
        bptr[i] = B + (size_t)(bn + r) * K + c * 8;
    }

    const int cAbit = lane >> 4;
    uint32_t aRowByte[4]; int aMask[4];
#pragma unroll
    for (int mi = 0; mi < 4; mi++) {
        int r = wm + mi * 16 + (lane & 15);
        aRowByte[mi] = (uint32_t)(r * 64);
        aMask[mi] = (r >> 1) & 3;
    }
    const int cBbit = (lane >> 3) & 1;
    uint32_t bRowByte[2]; int bMask[2];
#pragma unroll
    for (int p = 0; p < 2; p++) {
        int r = wn + p * 16 + ((lane >> 4) << 3) + (lane & 7);
        bRowByte[p] = (uint32_t)(r * 64);
        bMask[p] = (r >> 1) & 3;
    }

    float acc[4][4][4];
#pragma unroll
    for (int mi = 0; mi < 4; mi++)
#pragma unroll
        for (int ni = 0; ni < 4; ni++)
#pragma unroll
            for (int c = 0; c < 4; c++) acc[mi][ni][c] = 0.0f;

#pragma unroll
    for (int i = 0; i < 2; i++) { cpa16(sA_u[0] + aoff[i], aptr[i]); }
#pragma unroll
    for (int i = 0; i < 2; i++) { cpa16(sB_u[0] + boff[i], bptr[i]); }
    CP_COMMIT();
#pragma unroll
    for (int i = 0; i < 2; i++) { aptr[i] += 32; bptr[i] += 32; }

    const int T = K >> 5;
    for (int t = 0; t < T; t++) {
        const int cur = t & 1, nxt = cur ^ 1;
        if (t + 1 < T) {
#pragma unroll
            for (int i = 0; i < 2; i++) { cpa16(sA_u[nxt] + aoff[i], aptr[i]); }
#pragma unroll
            for (int i = 0; i < 2; i++) { cpa16(sB_u[nxt] + boff[i], bptr[i]); }
            CP_COMMIT();
#pragma unroll
            for (int i = 0; i < 2; i++) { aptr[i] += 32; bptr[i] += 32; }
            CP_WAIT(1);
        } else {
            CP_WAIT(0);
        }
        __syncthreads();

        const uint32_t sAc = sA_u[cur], sBc = sB_u[cur];
#pragma unroll
        for (int kk = 0; kk < 2; kk++) {
            uint32_t af[4][4], bf[4][2];
#pragma unroll
            for (int mi = 0; mi < 4; mi++)
                ldsm4(af[mi][0], af[mi][1], af[mi][2], af[mi][3],
                      sAc + aRowByte[mi] + (uint32_t)(((2*kk + cAbit) ^ aMask[mi]) << 4));
#pragma unroll
            for (int p = 0; p < 2; p++)
                ldsm4(bf[p*2][0], bf[p*2][1], bf[p*2+1][0], bf[p*2+1][1],
                      sBc + bRowByte[p] + (uint32_t)(((2*kk + cBbit) ^ bMask[p]) << 4));
#pragma unroll
            for (int mi = 0; mi < 4; mi++)
#pragma unroll
                for (int ni = 0; ni < 4; ni++)
                    mma16816(acc[mi][ni], af[mi], bf[ni]);
        }
        __syncthreads();
    }

    // ---------------- epilogue ----------------
    if (EPI == 4) {
        float* __restrict__ Cf = (float*)ga.C[blockIdx.z];
#pragma unroll
        for (int mi = 0; mi < 4; mi++) {
#pragma unroll
            for (int j = 0; j < 2; j++) {
                int nb = bn + wn + j * 16;
                int h  = (nb >> 4) & 31;
                int nl = nb >> 9;
                size_t ob0 = ((size_t)(nl * NH + h)) * L_SEQ;
                int i0 = tig * 2;
#pragma unroll
                for (int hf = 0; hf < 2; hf++) {
                    int l = bm + wm + mi * 16 + g + hf * 8;
                    size_t ob = (ob0 + l) * DD + i0;
                    float x1a = acc[mi][j*2  ][hf*2+0];
                    float x1b = acc[mi][j*2  ][hf*2+1];
                    float x2a = acc[mi][j*2+1][hf*2+0];
                    float x2b = acc[mi][j*2+1][hf*2+1];
                    float a0 = (float)l * ft.f[i0];
                    float a1 = (float)l * ft.f[i0+1];
                    float c0 = cosf(a0), s0 = sinf(a0);
                    float c1 = cosf(a1), s1 = sinf(a1);
                    *reinterpret_cast<float2*>(Cf + ob) =
                        make_float2(x1a*c0 - x2a*s0, x1b*c1 - x2b*s1);
                    *reinterpret_cast<float2*>(Cf + ob + 8) =
                        make_float2(x2a*c0 + x1a*s0, x2b*c1 + x1b*s1);
                }
            }
        }
        return;
    }
    if (EPI == 5) {
        // rope on q/k (z<2), scale q by 1/sqrt(d), fp16 out; v plain fp16
        __half* __restrict__ Ch = (__half*)ga.C[blockIdx.z];
        const bool dorope = (blockIdx.z < 2);
        const float sc = (blockIdx.z == 0) ? 0.17677669529663687f : 1.0f;
#pragma unroll
        for (int mi = 0; mi < 4; mi++) {
#pragma unroll
            for (int hf = 0; hf < 2; hf++) {
                int l = bm + wm + mi * 16 + g + hf * 8;
                size_t rowo = (size_t)l * N;
#pragma unroll
                for (int ni = 0; ni < 2; ni++) {
                    int i0 = ni * 8 + tig * 2;          // within-head idx (<16)
                    int n0 = bn + wn + ni * 8 + tig * 2;
                    float x1a = acc[mi][ni  ][hf*2+0] * sc;
                    float x1b = acc[mi][ni  ][hf*2+1] * sc;
                    float x2a = acc[mi][ni+2][hf*2+0] * sc;
                    float x2b = acc[mi][ni+2][hf*2+1] * sc;
                    float y1a, y1b, y2a, y2b;
                    if (dorope) {
                        float a0 = (float)l * ft.f[i0];
                        float a1 = (float)l * ft.f[i0+1];
                        float c0 = cosf(a0), s0 = sinf(a0);
                        float c1 = cosf(a1), s1 = sinf(a1);
                        y1a = x1a*c0 - x2a*s0; y1b = x1b*c1 - x2b*s1;
                        y2a = x2a*c0 + x1a*s0; y2b = x2b*c1 + x1b*s1;
                    } else {
                        y1a = x1a; y1b = x1b; y2a = x2a; y2b = x2b;
                    }
                    *reinterpret_cast<uint32_t*>(Ch + rowo + n0)      = packh2(y1a, y1b);
                    *reinterpret_cast<uint32_t*>(Ch + rowo + n0 + 16) = packh2(y2a, y2b);
                }
            }
        }
        return;
    }

#pragma unroll
    for (int mi = 0; mi < 4; mi++) {
#pragma unroll
        for (int ni = 0; ni < 4; ni++) {
            int m0 = bm + wm + mi * 16 + g;
            int n0 = bn + wn + ni * 8 + tig * 2;
#pragma unroll
            for (int hf = 0; hf < 2; hf++) {
                int m = m0 + hf * 8;
                size_t off = (size_t)m * N + n0;
                float v0 = acc[mi][ni][hf * 2 + 0];
                float v1 = acc[mi][ni][hf * 2 + 1];
                if (EPI == 1) {
                    v0 = gelu_f(v0 + bias[n0]); v1 = gelu_f(v1 + bias[n0 + 1]);
                } else if (EPI == 2) {
                    v0 = v0 + bias[n0] + resid[off];
                    v1 = v1 + bias[n0 + 1] + resid[off + 1];
                } else if (EPI == 3) {
                    v0 = silu_f(v0); v1 = silu_f(v1);
                }
                if (OUTH) {
                    *reinterpret_cast<uint32_t*>((__half*)ga.C[blockIdx.z] + off) = packh2(v0, v1);
                } else {
                    *reinterpret_cast<float2*>((float*)ga.C[blockIdx.z] + off) =
                        make_float2(v0, v1);
                }
            }
        }
    }
}

// ---------------- tensor-core causal flash attention ------------------
// block = (64 queries, 1 head), 4 warps x 16 rows; K/V tiles of 64 keys.
__global__ __launch_bounds__(128)
void attn_mma(const __half* __restrict__ Q, const __half* __restrict__ K,
              const __half* __restrict__ V, float* __restrict__ O)
{
    __shared__ __align__(16) __half sQ[64*32];
    __shared__ __align__(16) __half sK[64*32];
    __shared__ __align__(16) __half sV[64*32];
    const int h = blockIdx.y;
    const int q0 = blockIdx.x * 64;
    const int tid = threadIdx.x, w = tid >> 5, lane = tid & 31;
    const int g = lane >> 2, tig = lane & 3;

    const uint32_t uQ = (uint32_t)__cvta_generic_to_shared(sQ);
    const uint32_t uK = (uint32_t)__cvta_generic_to_shared(sK);
    const uint32_t uV = (uint32_t)__cvta_generic_to_shared(sV);

    // load Q tile (swizzled, 64 rows x 32 halves; 16B = 8-half chunks)
#pragma unroll
    for (int i = 0; i < 2; i++) {
        int id = tid + i * 128;
        int r = id >> 2, c = id & 3;
        *reinterpret_cast<uint4*>(sQ + r * 32 + ((c ^ ((r >> 1) & 3)) << 3)) =
            *reinterpret_cast<const uint4*>(Q + (size_t)(q0 + r) * HR_DIM + h * 32 + c * 8);
    }

    // fragment addressing
    const int cAbit = lane >> 4;
    const int aR = w * 16 + (lane & 15);
    const uint32_t aRowByte = (uint32_t)(aR * 64);
    const int aMask = (aR >> 1) & 3;
    const int cBbit = (lane >> 3) & 1;
    uint32_t bRowByte[4]; int bMask[4];
#pragma unroll
    for (int p = 0; p < 4; p++) {
        int r = p * 16 + ((lane >> 4) << 3) + (lane & 7);
        bRowByte[p] = (uint32_t)(r * 64);
        bMask[p] = (r >> 1) & 3;
    }
    const int vR0 = ((lane >> 3) & 1) * 8 + (lane & 7);
    const uint32_t vRowByte = (uint32_t)(vR0 * 64);
    const int vMask = (vR0 >> 1) & 3;
    const int vCbit = lane >> 4;

    float m0 = -INFINITY, m1 = -INFINITY, l0 = 0.0f, l1 = 0.0f;
    float Of[4][4];
#pragma unroll
    for (int nb = 0; nb < 4; nb++)
#pragma unroll
        for (int c = 0; c < 4; c++) Of[nb][c] = 0.0f;

    const int nt = q0 / 64 + 1;
    for (int tix = 0; tix < nt; tix++) {
        const int j0 = tix * 64;
        // load K,V tiles (16B chunks)
#pragma unroll
        for (int i = 0; i < 2; i++) {
            int id = tid + i * 128;
            int r = id >> 2, c = id & 3;
            uint32_t so = r * 32 + ((c ^ ((r >> 1) & 3)) << 3);
            size_t go = (size_t)(j0 + r) * HR_DIM + h * 32 + c * 8;
            *reinterpret_cast<uint4*>(sK + so) = *reinterpret_cast<const uint4*>(K + go);
            *reinterpret_cast<uint4*>(sV + so) = *reinterpret_cast<const uint4*>(V + go);
        }
        __syncthreads();

        // S = Q @ K^T  (16 rows x 64 keys per warp)
        float Sf[8][4];
#pragma unroll
        for (int nb = 0; nb < 8; nb++)
#pragma unroll
            for (int c = 0; c < 4; c++) Sf[nb][c] = 0.0f;
#pragma unroll
        for (int kk = 0; kk < 2; kk++) {
            uint32_t af[4], bf[8][2];
            ldsm4(af[0], af[1], af[2], af[3],
                  uQ + aRowByte + (uint32_t)(((2*kk + cAbit) ^ aMask) << 4));
#pragma unroll
            for (int p = 0; p < 4; p++)
                ldsm4(bf[p*2][0], bf[p*2][1], bf[p*2+1][0], bf[p*2+1][1],
                      uK + bRowByte[p] + (uint32_t)(((2*kk + cBbit) ^ bMask[p]) << 4));
#pragma unroll
            for (int nb = 0; nb < 8; nb++)
                mma16816(Sf[nb], af, bf[nb]);
        }

        // causal mask on the diagonal tile
        if (j0 == q0) {
            const int lr0 = q0 + w * 16 + g;
#pragma unroll
            for (int nb = 0; nb < 8; nb++) {
                int j = j0 + nb * 8 + tig * 2;
                if (j     > lr0    ) Sf[nb][0] = -1e30f;
                if (j + 1 > lr0    ) Sf[nb][1] = -1e30f;
                if (j     > lr0 + 8) Sf[nb][2] = -1e30f;
                if (j + 1 > lr0 + 8) Sf[nb][3] = -1e30f;
            }
        }

        // online softmax (rows g and g+8)
        float mx0 = -INFINITY, mx1 = -INFINITY;
#pragma unroll
        for (int nb = 0; nb < 8; nb++) {
            mx0 = fmaxf(mx0, fmaxf(Sf[nb][0], Sf[nb][1]));
            mx1 = fmaxf(mx1, fmaxf(Sf[nb][2], Sf[nb][3]));
        }
        mx0 = fmaxf(mx0, __shfl_xor_sync(0xffffffffu, mx0, 1));
        mx0 = fmaxf(mx0, __shfl_xor_sync(0xffffffffu, mx0, 2));
        mx1 = fmaxf(mx1, __shfl_xor_sync(0xffffffffu, mx1, 1));
        mx1 = fmaxf(mx1, __shfl_xor_sync(0xffffffffu, mx1, 2));
        float mn0 = fmaxf(m0, mx0), mn1 = fmaxf(m1, mx1);
        float al0 = __expf(m0 - mn0), al1 = __expf(m1 - mn1);
        float ps0 = 0.0f, ps1 = 0.0f;
#pragma unroll
        for (int nb = 0; nb < 8; nb++) {
            Sf[nb][0] = __expf(Sf[nb][0] - mn0);
            Sf[nb][1] = __expf(Sf[nb][1] - mn0);
            Sf[nb][2] = __expf(Sf[nb][2] - mn1);
            Sf[nb][3] = __expf(Sf[nb][3] - mn1);
            ps0 += Sf[nb][0] + Sf[nb][1];
            ps1 += Sf[nb][2] + Sf[nb][3];
        }
        ps0 += __shfl_xor_sync(0xffffffffu, ps0, 1);
        ps0 += __shfl_xor_sync(0xffffffffu, ps0, 2);
        ps1 += __shfl_xor_sync(0xffffffffu, ps1, 1);
        ps1 += __shfl_xor_sync(0xffffffffu, ps1, 2);
        l0 = l0 * al0 + ps0;
        l1 = l1 * al1 + ps1;
        m0 = mn0; m1 = mn1;
#pragma unroll
        for (int nb = 0; nb < 4; nb++) {
            Of[nb][0] *= al0; Of[nb][1] *= al0;
            Of[nb][2] *= al1; Of[nb][3] *= al1;
        }

        // P (fp16) @ V : A-frags from Sf, B-frags via ldmatrix.trans on V
#pragma unroll
        for (int kk = 0; kk < 4; kk++) {
            uint32_t pf[4];
            pf[0] = packh2(Sf[2*kk  ][0], Sf[2*kk  ][1]);
            pf[1] = packh2(Sf[2*kk  ][2], Sf[2*kk  ][3]);
            pf[2] = packh2(Sf[2*kk+1][0], Sf[2*kk+1][1]);
            pf[3] = packh2(Sf[2*kk+1][2], Sf[2*kk+1][3]);
#pragma unroll
            for (int p = 0; p < 2; p++) {
                uint32_t v0, v1, v2, v3;
                int dchunk = 2 * p + vCbit;
                ldsm4t(v0, v1, v2, v3,
                       uV + vRowByte + (uint32_t)(kk * 16 * 64)
                          + (uint32_t)((dchunk ^ vMask) << 4));
                uint32_t b0[2] = {v0, v1};
                uint32_t b1[2] = {v2, v3};
                mma16816(Of[p*2],   pf, b0);
                mma16816(Of[p*2+1], pf, b1);
            }
        }
        __syncthreads();
    }

    // write O = Of / l
    float inv0 = 1.0f / l0, inv1 = 1.0f / l1;
    const int lr = q0 + w * 16 + g;
#pragma unroll
    for (int nb = 0; nb < 4; nb++) {
        int d0 = nb * 8 + tig * 2;
        *reinterpret_cast<float2*>(O + (size_t)lr * HR_DIM + h * 32 + d0) =
            make_float2(Of[nb][0] * inv0, Of[nb][1] * inv0);
        *reinterpret_cast<float2*>(O + (size_t)(lr + 8) * HR_DIM + h * 32 + d0) =
            make_float2(Of[nb][2] * inv1, Of[nb][3] * inv1);
    }
}

// ------------------------- LayerNorm (rows of 1024, fp16 out) ---------
__global__ __launch_bounds__(256)
void layernorm_k(const float* __restrict__ in, const float* __restrict__ w,
                 const float* __restrict__ b, __half* __restrict__ out)
{
    __shared__ float red[8];
    const int row = blockIdx.x;
    const int tid = threadIdx.x;
    const int lane = tid & 31, wid = tid >> 5;
    float4 v = reinterpret_cast<const float4*>(in + (size_t)row * HR_DIM)[tid];

    float s = v.x + v.y + v.z + v.w;
#pragma unroll
    for (int o = 16; o; o >>= 1) s += __shfl_xor_sync(0xffffffffu, s, o);
    if (lane == 0) red[wid] = s;
    __syncthreads();
    float tot = red[0]+red[1]+red[2]+red[3]+red[4]+red[5]+red[6]+red[7];
    float mu = tot * (1.0f / HR_DIM);

    float dx0 = v.x - mu, dx1 = v.y - mu, dx2 = v.z - mu, dx3 = v.w - mu;
    float sq = dx0*dx0 + dx1*dx1 + dx2*dx2 + dx3*dx3;
#pragma unroll
    for (int o = 16; o; o >>= 1) sq += __shfl_xor_sync(0xffffffffu, sq, o);
    __syncthreads();
    if (lane == 0) red[wid] = sq;
    __syncthreads();
    float var = (red[0]+red[1]+red[2]+red[3]+red[4]+red[5]+red[6]+red[7]) * (1.0f / HR_DIM);
    float rstd = rsqrtf(var + 1e-5f);

    float4 wv = reinterpret_cast<const float4*>(w)[tid];
    float4 bv = reinterpret_cast<const float4*>(b)[tid];
    uint2 o;
    o.x = packh2(dx0 * rstd * wv.x + bv.x, dx1 * rstd * wv.y + bv.y);
    o.y = packh2(dx2 * rstd * wv.z + bv.z, dx3 * rstd * wv.w + bv.w);
    reinterpret_cast<uint2*>(out + (size_t)row * HR_DIM)[tid] = o;
}

// ------------------------- launcher -----------------------------------
static void launch_cvt(const float* src, __half* dst, size_t n) {
    cvt_k<<<(unsigned)(n / 1024), 256>>>((const float4*)src, (uint2*)dst);
}

extern "C" void kernel_launch(void* const* d_in, const int* in_sizes, int n_in,
                              void* d_out, int out_size)
{
    const float* x    = (const float*)d_in[0];
    const float* Wi   = (const float*)d_in[1];
    const float* Wq   = (const float*)d_in[2];
    const float* Wk   = (const float*)d_in[3];
    const float* Wv   = (const float*)d_in[4];
    const float* ln1w = (const float*)d_in[5];
    const float* ln1b = (const float*)d_in[6];
    const float* Wf1  = (const float*)d_in[7];
    const float* bf1  = (const float*)d_in[8];
    const float* Wf2  = (const float*)d_in[9];
    const float* bf2  = (const float*)d_in[10];
    const float* Wqi1 = (const float*)d_in[11];
    const float* Wqi2 = (const float*)d_in[12];
    const float* Wki1 = (const float*)d_in[13];
    const float* Wki2 = (const float*)d_in[14];
    float* out = (float*)d_out;

    float *attn;
    __half *xh,*hWi,*hWq,*hWk,*hWv,*hWf1,*hWf2,*hWqi1,*hWki1,*hWqi2,*hWki2;
    __half *hrh,*qh,*kh,*vh,*lnh,*f1h,*hidh,*aqh,*akh;
    cudaGetSymbolAddress((void**)&attn, g_attn);
    cudaGetSymbolAddress((void**)&xh,    g_xh);
    cudaGetSymbolAddress((void**)&hWi,   g_hWi);
    cudaGetSymbolAddress((void**)&hWq,   g_hWq);
    cudaGetSymbolAddress((void**)&hWk,   g_hWk);
    cudaGetSymbolAddress((void**)&hWv,   g_hWv);
    cudaGetSymbolAddress((void**)&hWf1,  g_hWf1);
    cudaGetSymbolAddress((void**)&hWf2,  g_hWf2);
    cudaGetSymbolAddress((void**)&hWqi1, g_hWqi1);
    cudaGetSymbolAddress((void**)&hWki1, g_hWki1);
    cudaGetSymbolAddress((void**)&hWqi2, g_hWqi2);
    cudaGetSymbolAddress((void**)&hWki2, g_hWki2);
    cudaGetSymbolAddress((void**)&hrh,   g_hrh);
    cudaGetSymbolAddress((void**)&qh,    g_qh);
    cudaGetSymbolAddress((void**)&kh,    g_kh);
    cudaGetSymbolAddress((void**)&vh,    g_vh);
    cudaGetSymbolAddress((void**)&lnh,   g_lnh);
    cudaGetSymbolAddress((void**)&f1h,   g_f1h);
    cudaGetSymbolAddress((void**)&hidh,  g_hidh);
    cudaGetSymbolAddress((void**)&aqh,   g_aqh);
    cudaGetSymbolAddress((void**)&akh,   g_akh);

    F16 t16; for (int i = 0; i < 16; i++) t16.f[i] = (float)(1.0 / pow(10000.0, (double)i / 16.0));
    F16 t8 = {}; for (int i = 0; i < 8; i++) t8.f[i] = (float)(1.0 / pow(10000.0, (double)i / 8.0));
    F16 t0 = {};

    // convert all GEMM operands to fp16
    launch_cvt(x,    xh,    (size_t)L_SEQ*E_DIM);
    launch_cvt(Wi,   hWi,   (size_t)HR_DIM*E_DIM);
    launch_cvt(Wq,   hWq,   (size_t)HR_DIM*HR_DIM);
    launch_cvt(Wk,   hWk,   (size_t)HR_DIM*HR_DIM);
    launch_cvt(Wv,   hWv,   (size_t)HR_DIM*HR_DIM);
    launch_cvt(Wf1,  hWf1,  (size_t)2*HR_DIM*HR_DIM);
    launch_cvt(Wf2,  hWf2,  (size_t)E_DIM*2*HR_DIM);
    launch_cvt(Wqi1, hWqi1, (size_t)HR_DIM*E_DIM);
    launch_cvt(Wki1, hWki1, (size_t)HR_DIM*E_DIM);
    launch_cvt(Wqi2, hWqi2, (size_t)OUT_FEAT*HR_DIM);
    launch_cvt(Wki2, hWki2, (size_t)OUT_FEAT*HR_DIM);

    GArgs ga;

    // hr = x @ Wi^T  (fp16 out)
    ga.A[0] = xh; ga.B[0] = hWi; ga.C[0] = hrh;
    tgemm<0,1><<<dim3(HR_DIM/128, 16, 1), 256>>>(ga, nullptr, nullptr, HR_DIM, E_DIM, t0);

    // q, k, v with fused rope (q scaled), fp16 out
    ga.A[0] = hrh; ga.A[1] = hrh; ga.A[2] = hrh;
    ga.B[0] = hWq; ga.B[1] = hWk; ga.B[2] = hWv;
    ga.C[0] = qh;  ga.C[1] = kh;  ga.C[2] = vh;
    tgemm<5,1><<<dim3(HR_DIM/128, 16, 3), 256>>>(ga, nullptr, nullptr, HR_DIM, HR_DIM, t16);

    attn_mma<<<dim3(L_SEQ/64, NH), 128>>>(qh, kh, vh, attn);
    layernorm_k<<<L_SEQ, 256>>>(attn, ln1w, ln1b, lnh);

    // ffn1: gelu(ln @ Wf1^T + bf1) -> fp16
    ga.A[0] = lnh; ga.B[0] = hWf1; ga.C[0] = f1h;
    tgemm<1,1><<<dim3(2*HR_DIM/128, 16, 1), 256>>>(ga, bf1, nullptr, 2*HR_DIM, HR_DIM, t0);

    // ffn2 + residual -> fp16
    ga.A[0] = f1h; ga.B[0] = hWf2; ga.C[0] = hidh;
    tgemm<2,1><<<dim3(E_DIM/128, 16, 1), 256>>>(ga, bf2, x, E_DIM, 2*HR_DIM, t0);

    // silu projections -> fp16
    ga.A[0] = hidh; ga.A[1] = hidh;
    ga.B[0] = hWqi1; ga.B[1] = hWki1;
    ga.C[0] = aqh;  ga.C[1] = akh;
    tgemm<3,1><<<dim3(HR_DIM/128, 16, 2), 256>>>(ga, nullptr, nullptr, HR_DIM, E_DIM, t0);

    // importance projections with fused rope+permute into output
    ga.A[0] = aqh; ga.A[1] = akh;
    ga.B[0] = hWqi2; ga.B[1] = hWki2;
    ga.C[0] = out;  ga.C[1] = out + (size_t)NLAY*NH*L_SEQ*DD;
    tgemm<4,0><<<dim3(OUT_FEAT/128, 16, 2), 256>>>(ga, nullptr, nullptr, OUT_FEAT, HR_DIM, t8);
}

// round 12
// speedup vs baseline: 8.7297x; 1.0132x over previous
#include <cuda_runtime.h>
#include <cuda_fp16.h>
#include <math.h>
#include <stdint.h>

// ------------------------- problem dimensions -------------------------
#define L_SEQ   2048
#define E_DIM   4096
#define HR_DIM  1024
#define NH      32
#define D_ATT   32
#define NLAY    32
#define DD      16
#define OUT_FEAT (NLAY*NH*DD)   // 16384

// ------------------------- scratch (static device mem) ----------------
__device__ float g_attn[(size_t)L_SEQ*HR_DIM];
__device__ __half g_xh   [(size_t)L_SEQ*E_DIM];
__device__ __half g_hWi  [(size_t)HR_DIM*E_DIM];
__device__ __half g_hWq  [(size_t)HR_DIM*HR_DIM];
__device__ __half g_hWk  [(size_t)HR_DIM*HR_DIM];
__device__ __half g_hWv  [(size_t)HR_DIM*HR_DIM];
__device__ __half g_hWf1 [(size_t)2*HR_DIM*HR_DIM];
__device__ __half g_hWf2 [(size_t)E_DIM*2*HR_DIM];
__device__ __half g_hWqi1[(size_t)HR_DIM*E_DIM];
__device__ __half g_hWki1[(size_t)HR_DIM*E_DIM];
__device__ __half g_hWqi2[(size_t)OUT_FEAT*HR_DIM];
__device__ __half g_hWki2[(size_t)OUT_FEAT*HR_DIM];
__device__ __half g_hrh  [(size_t)L_SEQ*HR_DIM];
__device__ __half g_qh   [(size_t)L_SEQ*HR_DIM];
__device__ __half g_kh   [(size_t)L_SEQ*HR_DIM];
__device__ __half g_vh   [(size_t)L_SEQ*HR_DIM];
__device__ __half g_lnh  [(size_t)L_SEQ*HR_DIM];
__device__ __half g_f1h  [(size_t)L_SEQ*2*HR_DIM];
__device__ __half g_hidh [(size_t)L_SEQ*E_DIM];
__device__ __half g_aqh  [(size_t)L_SEQ*HR_DIM];
__device__ __half g_akh  [(size_t)L_SEQ*HR_DIM];

struct F16 { float f[16]; };
struct GArgs { const __half* A[3]; const __half* B[3]; void* C[3]; };
struct CvtArgs {
    const float4* src[11];
    uint2* dst[11];
    unsigned off[12];   // cumulative float4 counts
};

// ------------------------- helpers ------------------------------------
__device__ __forceinline__ float gelu_f(float x) {
    return 0.5f * x * (1.0f + erff(x * 0.7071067811865476f));
}
__device__ __forceinline__ float silu_f(float x) {
    return x / (1.0f + expf(-x));
}
__device__ __forceinline__ void mma16816(float c[4], const uint32_t a[4], const uint32_t b[2]) {
    asm volatile(
        "mma.sync.aligned.m16n8k16.row.col.f32.f16.f16.f32 "
        "{%0,%1,%2,%3}, {%4,%5,%6,%7}, {%8,%9}, {%0,%1,%2,%3};"
        : "+f"(c[0]), "+f"(c[1]), "+f"(c[2]), "+f"(c[3])
        : "r"(a[0]), "r"(a[1]), "r"(a[2]), "r"(a[3]), "r"(b[0]), "r"(b[1]));
}
__device__ __forceinline__ void cpa16(uint32_t saddr, const __half* g) {
    asm volatile("cp.async.cg.shared.global [%0], [%1], 16;\n" :: "r"(saddr), "l"(g));
}
#define CP_COMMIT() asm volatile("cp.async.commit_group;\n" ::: "memory")
#define CP_WAIT(n)  asm volatile("cp.async.wait_group %0;\n" :: "n"(n) : "memory")
__device__ __forceinline__ void ldsm4(uint32_t& r0, uint32_t& r1, uint32_t& r2, uint32_t& r3,
                                      uint32_t addr) {
    asm volatile("ldmatrix.sync.aligned.m8n8.x4.shared.b16 {%0,%1,%2,%3}, [%4];"
                 : "=r"(r0), "=r"(r1), "=r"(r2), "=r"(r3) : "r"(addr));
}
__device__ __forceinline__ void ldsm4t(uint32_t& r0, uint32_t& r1, uint32_t& r2, uint32_t& r3,
                                       uint32_t addr) {
    asm volatile("ldmatrix.sync.aligned.m8n8.x4.trans.shared.b16 {%0,%1,%2,%3}, [%4];"
                 : "=r"(r0), "=r"(r1), "=r"(r2), "=r"(r3) : "r"(addr));
}
__device__ __forceinline__ uint32_t packh2(float a, float b) {
    __half2 h = __floats2half2_rn(a, b);
    return *reinterpret_cast<uint32_t*>(&h);
}

// ------------------ batched convert: dst[s] = half(src[s]) ------------
__global__ __launch_bounds__(256)
void cvt_all(CvtArgs a)
{
    unsigned gid = blockIdx.x * 256u + threadIdx.x;
    if (gid >= a.off[11]) return;
    int s = 0;
#pragma unroll
    for (int i = 1; i < 11; i++) s += (gid >= a.off[i]) ? 1 : 0;
    unsigned idx = gid - a.off[s];
    float4 v = a.src[s][idx];
    uint2 o;
    o.x = packh2(v.x, v.y);
    o.y = packh2(v.z, v.w);
    a.dst[s][idx] = o;
}

// ---------------- FP16 GEMM: C[2048,N] = A[2048,K] * B[N,K]^T ---------
// CTA tile 128x128x32, 8 warps (2m x 4n), warp tile 64x32.
// 2-stage cp.async (round-10 proven structure).
// EPI: 0 none, 1 gelu(acc+bias), 2 acc+bias+resid, 3 silu(acc),
//      4 rope+permute into output (qi/ki), 5 qkv rope (z<2) fp16 out
// OUTH: 1 -> fp16 C, 0 -> fp32 C
template<int EPI, int OUTH>
__global__ __launch_bounds__(256, 2)
void tgemm(GArgs ga, const float* __restrict__ bias,
           const float* __restrict__ resid, int N, int K, F16 ft)
{
    __shared__ __align__(16) __half sA[2][128*32];
    __shared__ __align__(16) __half sB[2][128*32];

    const __half* __restrict__ A = ga.A[blockIdx.z];
    const __half* __restrict__ B = ga.B[blockIdx.z];

    const int tid = threadIdx.x, wid = tid >> 5, lane = tid & 31;
    const int g = lane >> 2, tig = lane & 3;
    const int wm = (wid & 1) * 64;
    const int wn = (wid >> 1) * 32;
    const int bm = blockIdx.y * 128, bn = blockIdx.x * 128;

    uint32_t sA_u[2], sB_u[2];
    sA_u[0] = (uint32_t)__cvta_generic_to_shared(&sA[0][0]);
    sA_u[1] = (uint32_t)__cvta_generic_to_shared(&sA[1][0]);
    sB_u[0] = (uint32_t)__cvta_generic_to_shared(&sB[0][0]);
    sB_u[1] = (uint32_t)__cvta_generic_to_shared(&sB[1][0]);

    uint32_t aoff[2], boff[2];
    const __half* aptr[2];
    const __half* bptr[2];
#pragma unroll
    for (int i = 0; i < 2; i++) {
        int id = tid + i * 256;
        int r = id >> 2, c = id & 3;
        uint32_t off = (uint32_t)(r * 64 + ((c ^ ((r >> 1) & 3)) << 4));
        aoff[i] = off; boff[i] = off;
        aptr[i] = A + (size_t)(bm + r) * K + c * 8;
        bptr[i] = B + (size_t)(bn + r) * K + c * 8;
    }

    const int cAbit = lane >> 4;
    uint32_t aRowByte[4]; int aMask[4];
#pragma unroll
    for (int mi = 0; mi < 4; mi++) {
        int r = wm + mi * 16 + (lane & 15);
        aRowByte[mi] = (uint32_t)(r * 64);
        aMask[mi] = (r >> 1) & 3;
    }
    const int cBbit = (lane >> 3) & 1;
    uint32_t bRowByte[2]; int bMask[2];
#pragma unroll
    for (int p = 0; p < 2; p++) {
        int r = wn + p * 16 + ((lane >> 4) << 3) + (lane & 7);
        bRowByte[p] = (uint32_t)(r * 64);
        bMask[p] = (r >> 1) & 3;
    }

    float acc[4][4][4];
#pragma unroll
    for (int mi = 0; mi < 4; mi++)
#pragma unroll
        for (int ni = 0; ni < 4; ni++)
#pragma unroll
            for (int c = 0; c < 4; c++) acc[mi][ni][c] = 0.0f;

#pragma unroll
    for (int i = 0; i < 2; i++) { cpa16(sA_u[0] + aoff[i], aptr[i]); }
#pragma unroll
    for (int i = 0; i < 2; i++) { cpa16(sB_u[0] + boff[i], bptr[i]); }
    CP_COMMIT();
#pragma unroll
    for (int i = 0; i < 2; i++) { aptr[i] += 32; bptr[i] += 32; }

    const int T = K >> 5;
    for (int t = 0; t < T; t++) {
        const int cur = t & 1, nxt = cur ^ 1;
        if (t + 1 < T) {
#pragma unroll
            for (int i = 0; i < 2; i++) { cpa16(sA_u[nxt] + aoff[i], aptr[i]); }
#pragma unroll
            for (int i = 0; i < 2; i++) { cpa16(sB_u[nxt] + boff[i], bptr[i]); }
            CP_COMMIT();
#pragma unroll
            for (int i = 0; i < 2; i++) { aptr[i] += 32; bptr[i] += 32; }
            CP_WAIT(1);
        } else {
            CP_WAIT(0);
        }
        __syncthreads();

        const uint32_t sAc = sA_u[cur], sBc = sB_u[cur];
#pragma unroll
        for (int kk = 0; kk < 2; kk++) {
            uint32_t af[4][4], bf[4][2];
#pragma unroll
            for (int mi = 0; mi < 4; mi++)
                ldsm4(af[mi][0], af[mi][1], af[mi][2], af[mi][3],
                      sAc + aRowByte[mi] + (uint32_t)(((2*kk + cAbit) ^ aMask[mi]) << 4));
#pragma unroll
            for (int p = 0; p < 2; p++)
                ldsm4(bf[p*2][0], bf[p*2][1], bf[p*2+1][0], bf[p*2+1][1],
                      sBc + bRowByte[p] + (uint32_t)(((2*kk + cBbit) ^ bMask[p]) << 4));
#pragma unroll
            for (int mi = 0; mi < 4; mi++)
#pragma unroll
                for (int ni = 0; ni < 4; ni++)
                    mma16816(acc[mi][ni], af[mi], bf[ni]);
        }
        __syncthreads();
    }

    // ---------------- epilogue ----------------
    if (EPI == 4) {
        float* __restrict__ Cf = (float*)ga.C[blockIdx.z];
#pragma unroll
        for (int mi = 0; mi < 4; mi++) {
#pragma unroll
            for (int j = 0; j < 2; j++) {
                int nb = bn + wn + j * 16;
                int h  = (nb >> 4) & 31;
                int nl = nb >> 9;
                size_t ob0 = ((size_t)(nl * NH + h)) * L_SEQ;
                int i0 = tig * 2;
#pragma unroll
                for (int hf = 0; hf < 2; hf++) {
                    int l = bm + wm + mi * 16 + g + hf * 8;
                    size_t ob = (ob0 + l) * DD + i0;
                    float x1a = acc[mi][j*2  ][hf*2+0];
                    float x1b = acc[mi][j*2  ][hf*2+1];
                    float x2a = acc[mi][j*2+1][hf*2+0];
                    float x2b = acc[mi][j*2+1][hf*2+1];
                    float a0 = (float)l * ft.f[i0];
                    float a1 = (float)l * ft.f[i0+1];
                    float c0 = cosf(a0), s0 = sinf(a0);
                    float c1 = cosf(a1), s1 = sinf(a1);
                    *reinterpret_cast<float2*>(Cf + ob) =
                        make_float2(x1a*c0 - x2a*s0, x1b*c1 - x2b*s1);
                    *reinterpret_cast<float2*>(Cf + ob + 8) =
                        make_float2(x2a*c0 + x1a*s0, x2b*c1 + x1b*s1);
                }
            }
        }
        return;
    }
    if (EPI == 5) {
        __half* __restrict__ Ch = (__half*)ga.C[blockIdx.z];
        const bool dorope = (blockIdx.z < 2);
        const float sc = (blockIdx.z == 0) ? 0.17677669529663687f : 1.0f;
#pragma unroll
        for (int mi = 0; mi < 4; mi++) {
#pragma unroll
            for (int hf = 0; hf < 2; hf++) {
                int l = bm + wm + mi * 16 + g + hf * 8;
                size_t rowo = (size_t)l * N;
#pragma unroll
                for (int ni = 0; ni < 2; ni++) {
                    int i0 = ni * 8 + tig * 2;
                    int n0 = bn + wn + ni * 8 + tig * 2;
                    float x1a = acc[mi][ni  ][hf*2+0] * sc;
                    float x1b = acc[mi][ni  ][hf*2+1] * sc;
                    float x2a = acc[mi][ni+2][hf*2+0] * sc;
                    float x2b = acc[mi][ni+2][hf*2+1] * sc;
                    float y1a, y1b, y2a, y2b;
                    if (dorope) {
                        float a0 = (float)l * ft.f[i0];
                        float a1 = (float)l * ft.f[i0+1];
                        float c0 = cosf(a0), s0 = sinf(a0);
                        float c1 = cosf(a1), s1 = sinf(a1);
                        y1a = x1a*c0 - x2a*s0; y1b = x1b*c1 - x2b*s1;
                        y2a = x2a*c0 + x1a*s0; y2b = x2b*c1 + x1b*s1;
                    } else {
                        y1a = x1a; y1b = x1b; y2a = x2a; y2b = x2b;
                    }
                    *reinterpret_cast<uint32_t*>(Ch + rowo + n0)      = packh2(y1a, y1b);
                    *reinterpret_cast<uint32_t*>(Ch + rowo + n0 + 16) = packh2(y2a, y2b);
                }
            }
        }
        return;
    }

#pragma unroll
    for (int mi = 0; mi < 4; mi++) {
#pragma unroll
        for (int ni = 0; ni < 4; ni++) {
            int m0 = bm + wm + mi * 16 + g;
            int n0 = bn + wn + ni * 8 + tig * 2;
#pragma unroll
            for (int hf = 0; hf < 2; hf++) {
                int m = m0 + hf * 8;
                size_t off = (size_t)m * N + n0;
                float v0 = acc[mi][ni][hf * 2 + 0];
                float v1 = acc[mi][ni][hf * 2 + 1];
                if (EPI == 1) {
                    v0 = gelu_f(v0 + bias[n0]); v1 = gelu_f(v1 + bias[n0 + 1]);
                } else if (EPI == 2) {
                    v0 = v0 + bias[n0] + resid[off];
                    v1 = v1 + bias[n0 + 1] + resid[off + 1];
                } else if (EPI == 3) {
                    v0 = silu_f(v0); v1 = silu_f(v1);
                }
                if (OUTH) {
                    *reinterpret_cast<uint32_t*>((__half*)ga.C[blockIdx.z] + off) = packh2(v0, v1);
                } else {
                    *reinterpret_cast<float2*>((float*)ga.C[blockIdx.z] + off) =
                        make_float2(v0, v1);
                }
            }
        }
    }
}

// ---------------- tensor-core causal flash attention ------------------
// block = (64 queries, 1 head), 4 warps x 16 rows; K/V tiles of 64 keys.
__global__ __launch_bounds__(128)
void attn_mma(const __half* __restrict__ Q, const __half* __restrict__ K,
              const __half* __restrict__ V, float* __restrict__ O)
{
    __shared__ __align__(16) __half sQ[64*32];
    __shared__ __align__(16) __half sK[64*32];
    __shared__ __align__(16) __half sV[64*32];
    const int h = blockIdx.y;
    const int q0 = blockIdx.x * 64;
    const int tid = threadIdx.x, w = tid >> 5, lane = tid & 31;
    const int g = lane >> 2, tig = lane & 3;

    const uint32_t uQ = (uint32_t)__cvta_generic_to_shared(sQ);
    const uint32_t uK = (uint32_t)__cvta_generic_to_shared(sK);
    const uint32_t uV = (uint32_t)__cvta_generic_to_shared(sV);

#pragma unroll
    for (int i = 0; i < 2; i++) {
        int id = tid + i * 128;
        int r = id >> 2, c = id & 3;
        *reinterpret_cast<uint4*>(sQ + r * 32 + ((c ^ ((r >> 1) & 3)) << 3)) =
            *reinterpret_cast<const uint4*>(Q + (size_t)(q0 + r) * HR_DIM + h * 32 + c * 8);
    }

    const int cAbit = lane >> 4;
    const int aR = w * 16 + (lane & 15);
    const uint32_t aRowByte = (uint32_t)(aR * 64);
    const int aMask = (aR >> 1) & 3;
    const int cBbit = (lane >> 3) & 1;
    uint32_t bRowByte[4]; int bMask[4];
#pragma unroll
    for (int p = 0; p < 4; p++) {
        int r = p * 16 + ((lane >> 4) << 3) + (lane & 7);
        bRowByte[p] = (uint32_t)(r * 64);
        bMask[p] = (r >> 1) & 3;
    }
    const int vR0 = ((lane >> 3) & 1) * 8 + (lane & 7);
    const uint32_t vRowByte = (uint32_t)(vR0 * 64);
    const int vMask = (vR0 >> 1) & 3;
    const int vCbit = lane >> 4;

    float m0 = -INFINITY, m1 = -INFINITY, l0 = 0.0f, l1 = 0.0f;
    float Of[4][4];
#pragma unroll
    for (int nb = 0; nb < 4; nb++)
#pragma unroll
        for (int c = 0; c < 4; c++) Of[nb][c] = 0.0f;

    const int nt = q0 / 64 + 1;
    for (int tix = 0; tix < nt; tix++) {
        const int j0 = tix * 64;
#pragma unroll
        for (int i = 0; i < 2; i++) {
            int id = tid + i * 128;
            int r = id >> 2, c = id & 3;
            uint32_t so = r * 32 + ((c ^ ((r >> 1) & 3)) << 3);
            size_t go = (size_t)(j0 + r) * HR_DIM + h * 32 + c * 8;
            *reinterpret_cast<uint4*>(sK + so) = *reinterpret_cast<const uint4*>(K + go);
            *reinterpret_cast<uint4*>(sV + so) = *reinterpret_cast<const uint4*>(V + go);
        }
        __syncthreads();

        float Sf[8][4];
#pragma unroll
        for (int nb = 0; nb < 8; nb++)
#pragma unroll
            for (int c = 0; c < 4; c++) Sf[nb][c] = 0.0f;
#pragma unroll
        for (int kk = 0; kk < 2; kk++) {
            uint32_t af[4], bf[8][2];
            ldsm4(af[0], af[1], af[2], af[3],
                  uQ + aRowByte + (uint32_t)(((2*kk + cAbit) ^ aMask) << 4));
#pragma unroll
            for (int p = 0; p < 4; p++)
                ldsm4(bf[p*2][0], bf[p*2][1], bf[p*2+1][0], bf[p*2+1][1],
                      uK + bRowByte[p] + (uint32_t)(((2*kk + cBbit) ^ bMask[p]) << 4));
#pragma unroll
            for (int nb = 0; nb < 8; nb++)
                mma16816(Sf[nb], af, bf[nb]);
        }

        if (j0 == q0) {
            const int lr0 = q0 + w * 16 + g;
#pragma unroll
            for (int nb = 0; nb < 8; nb++) {
                int j = j0 + nb * 8 + tig * 2;
                if (j     > lr0    ) Sf[nb][0] = -1e30f;
                if (j + 1 > lr0    ) Sf[nb][1] = -1e30f;
                if (j     > lr0 + 8) Sf[nb][2] = -1e30f;
                if (j + 1 > lr0 + 8) Sf[nb][3] = -1e30f;
            }
        }

        float mx0 = -INFINITY, mx1 = -INFINITY;
#pragma unroll
        for (int nb = 0; nb < 8; nb++) {
            mx0 = fmaxf(mx0, fmaxf(Sf[nb][0], Sf[nb][1]));
            mx1 = fmaxf(mx1, fmaxf(Sf[nb][2], Sf[nb][3]));
        }
        mx0 = fmaxf(mx0, __shfl_xor_sync(0xffffffffu, mx0, 1));
        mx0 = fmaxf(mx0, __shfl_xor_sync(0xffffffffu, mx0, 2));
        mx1 = fmaxf(mx1, __shfl_xor_sync(0xffffffffu, mx1, 1));
        mx1 = fmaxf(mx1, __shfl_xor_sync(0xffffffffu, mx1, 2));
        float mn0 = fmaxf(m0, mx0), mn1 = fmaxf(m1, mx1);
        float al0 = __expf(m0 - mn0), al1 = __expf(m1 - mn1);
        float ps0 = 0.0f, ps1 = 0.0f;
#pragma unroll
        for (int nb = 0; nb < 8; nb++) {
            Sf[nb][0] = __expf(Sf[nb][0] - mn0);
            Sf[nb][1] = __expf(Sf[nb][1] - mn0);
            Sf[nb][2] = __expf(Sf[nb][2] - mn1);
            Sf[nb][3] = __expf(Sf[nb][3] - mn1);
            ps0 += Sf[nb][0] + Sf[nb][1];
            ps1 += Sf[nb][2] + Sf[nb][3];
        }
        ps0 += __shfl_xor_sync(0xffffffffu, ps0, 1);
        ps0 += __shfl_xor_sync(0xffffffffu, ps0, 2);
        ps1 += __shfl_xor_sync(0xffffffffu, ps1, 1);
        ps1 += __shfl_xor_sync(0xffffffffu, ps1, 2);
        l0 = l0 * al0 + ps0;
        l1 = l1 * al1 + ps1;
        m0 = mn0; m1 = mn1;
#pragma unroll
        for (int nb = 0; nb < 4; nb++) {
            Of[nb][0] *= al0; Of[nb][1] *= al0;
            Of[nb][2] *= al1; Of[nb][3] *= al1;
        }

#pragma unroll
        for (int kk = 0; kk < 4; kk++) {
            uint32_t pf[4];
            pf[0] = packh2(Sf[2*kk  ][0], Sf[2*kk  ][1]);
            pf[1] = packh2(Sf[2*kk  ][2], Sf[2*kk  ][3]);
            pf[2] = packh2(Sf[2*kk+1][0], Sf[2*kk+1][1]);
            pf[3] = packh2(Sf[2*kk+1][2], Sf[2*kk+1][3]);
#pragma unroll
            for (int p = 0; p < 2; p++) {
                uint32_t v0, v1, v2, v3;
                int dchunk = 2 * p + vCbit;
                ldsm4t(v0, v1, v2, v3,
                       uV + vRowByte + (uint32_t)(kk * 16 * 64)
                          + (uint32_t)((dchunk ^ vMask) << 4));
                uint32_t b0[2] = {v0, v1};
                uint32_t b1[2] = {v2, v3};
                mma16816(Of[p*2],   pf, b0);
                mma16816(Of[p*2+1], pf, b1);
            }
        }
        __syncthreads();
    }

    float inv0 = 1.0f / l0, inv1 = 1.0f / l1;
    const int lr = q0 + w * 16 + g;
#pragma unroll
    for (int nb = 0; nb < 4; nb++) {
        int d0 = nb * 8 + tig * 2;
        *reinterpret_cast<float2*>(O + (size_t)lr * HR_DIM + h * 32 + d0) =
            make_float2(Of[nb][0] * inv0, Of[nb][1] * inv0);
        *reinterpret_cast<float2*>(O + (size_t)(lr + 8) * HR_DIM + h * 32 + d0) =
            make_float2(Of[nb][2] * inv1, Of[nb][3] * inv1);
    }
}

// ------------------------- LayerNorm (rows of 1024, fp16 out) ---------
__global__ __launch_bounds__(256)
void layernorm_k(const float* __restrict__ in, const float* __restrict__ w,
                 const float* __restrict__ b, __half* __restrict__ out)
{
    __shared__ float red[8];
    const int row = blockIdx.x;
    const int tid = threadIdx.x;
    const int lane = tid & 31, wid = tid >> 5;
    float4 v = reinterpret_cast<const float4*>(in + (size_t)row * HR_DIM)[tid];

    float s = v.x + v.y + v.z + v.w;
#pragma unroll
    for (int o = 16; o; o >>= 1) s += __shfl_xor_sync(0xffffffffu, s, o);
    if (lane == 0) red[wid] = s;
    __syncthreads();
    float tot = red[0]+red[1]+red[2]+red[3]+red[4]+red[5]+red[6]+red[7];
    float mu = tot * (1.0f / HR_DIM);

    float dx0 = v.x - mu, dx1 = v.y - mu, dx2 = v.z - mu, dx3 = v.w - mu;
    float sq = dx0*dx0 + dx1*dx1 + dx2*dx2 + dx3*dx3;
#pragma unroll
    for (int o = 16; o; o >>= 1) sq += __shfl_xor_sync(0xffffffffu, sq, o);
    __syncthreads();
    if (lane == 0) red[wid] = sq;
    __syncthreads();
    float var = (red[0]+red[1]+red[2]+red[3]+red[4]+red[5]+red[6]+red[7]) * (1.0f / HR_DIM);
    float rstd = rsqrtf(var + 1e-5f);

    float4 wv = reinterpret_cast<const float4*>(w)[tid];
    float4 bv = reinterpret_cast<const float4*>(b)[tid];
    uint2 o;
    o.x = packh2(dx0 * rstd * wv.x + bv.x, dx1 * rstd * wv.y + bv.y);
    o.y = packh2(dx2 * rstd * wv.z + bv.z, dx3 * rstd * wv.w + bv.w);
    reinterpret_cast<uint2*>(out + (size_t)row * HR_DIM)[tid] = o;
}

// ------------------------- launcher -----------------------------------
extern "C" void kernel_launch(void* const* d_in, const int* in_sizes, int n_in,
                              void* d_out, int out_size)
{
    const float* x    = (const float*)d_in[0];
    const float* Wi   = (const float*)d_in[1];
    const float* Wq   = (const float*)d_in[2];
    const float* Wk   = (const float*)d_in[3];
    const float* Wv   = (const float*)d_in[4];
    const float* ln1w = (const float*)d_in[5];
    const float* ln1b = (const float*)d_in[6];
    const float* Wf1  = (const float*)d_in[7];
    const float* bf1  = (const float*)d_in[8];
    const float* Wf2  = (const float*)d_in[9];
    const float* bf2  = (const float*)d_in[10];
    const float* Wqi1 = (const float*)d_in[11];
    const float* Wqi2 = (const float*)d_in[12];
    const float* Wki1 = (const float*)d_in[13];
    const float* Wki2 = (const float*)d_in[14];
    float* out = (float*)d_out;

    float *attn;
    __half *xh,*hWi,*hWq,*hWk,*hWv,*hWf1,*hWf2,*hWqi1,*hWki1,*hWqi2,*hWki2;
    __half *hrh,*qh,*kh,*vh,*lnh,*f1h,*hidh,*aqh,*akh;
    cudaGetSymbolAddress((void**)&attn, g_attn);
    cudaGetSymbolAddress((void**)&xh,    g_xh);
    cudaGetSymbolAddress((void**)&hWi,   g_hWi);
    cudaGetSymbolAddress((void**)&hWq,   g_hWq);
    cudaGetSymbolAddress((void**)&hWk,   g_hWk);
    cudaGetSymbolAddress((void**)&hWv,   g_hWv);
    cudaGetSymbolAddress((void**)&hWf1,  g_hWf1);
    cudaGetSymbolAddress((void**)&hWf2,  g_hWf2);
    cudaGetSymbolAddress((void**)&hWqi1, g_hWqi1);
    cudaGetSymbolAddress((void**)&hWki1, g_hWki1);
    cudaGetSymbolAddress((void**)&hWqi2, g_hWqi2);
    cudaGetSymbolAddress((void**)&hWki2, g_hWki2);
    cudaGetSymbolAddress((void**)&hrh,   g_hrh);
    cudaGetSymbolAddress((void**)&qh,    g_qh);
    cudaGetSymbolAddress((void**)&kh,    g_kh);
    cudaGetSymbolAddress((void**)&vh,    g_vh);
    cudaGetSymbolAddress((void**)&lnh,   g_lnh);
    cudaGetSymbolAddress((void**)&f1h,   g_f1h);
    cudaGetSymbolAddress((void**)&hidh,  g_hidh);
    cudaGetSymbolAddress((void**)&aqh,   g_aqh);
    cudaGetSymbolAddress((void**)&akh,   g_akh);

    F16 t16; for (int i = 0; i < 16; i++) t16.f[i] = (float)(1.0 / pow(10000.0, (double)i / 16.0));
    F16 t8 = {}; for (int i = 0; i < 8; i++) t8.f[i] = (float)(1.0 / pow(10000.0, (double)i / 8.0));
    F16 t0 = {};

    // one batched fp32->fp16 convert over all 11 operands
    {
        CvtArgs ca;
        const float* srcs[11] = {x, Wi, Wq, Wk, Wv, Wf1, Wf2, Wqi1, Wki1, Wqi2, Wki2};
        __half* dsts[11] = {xh, hWi, hWq, hWk, hWv, hWf1, hWf2, hWqi1, hWki1, hWqi2, hWki2};
        size_t cnts[11] = {
            (size_t)L_SEQ*E_DIM, (size_t)HR_DIM*E_DIM,
            (size_t)HR_DIM*HR_DIM, (size_t)HR_DIM*HR_DIM, (size_t)HR_DIM*HR_DIM,
            (size_t)2*HR_DIM*HR_DIM, (size_t)E_DIM*2*HR_DIM,
            (size_t)HR_DIM*E_DIM, (size_t)HR_DIM*E_DIM,
            (size_t)OUT_FEAT*HR_DIM, (size_t)OUT_FEAT*HR_DIM
        };
        unsigned acc = 0;
        for (int i = 0; i < 11; i++) {
            ca.src[i] = (const float4*)srcs[i];
            ca.dst[i] = (uint2*)dsts[i];
            ca.off[i] = acc;
            acc += (unsigned)(cnts[i] / 4);
        }
        ca.off[11] = acc;
        cvt_all<<<(acc + 255) / 256, 256>>>(ca);
    }

    GArgs ga;

    // hr = x @ Wi^T  (fp16 out)
    ga.A[0] = xh; ga.B[0] = hWi; ga.C[0] = hrh;
    tgemm<0,1><<<dim3(HR_DIM/128, 16, 1), 256>>>(ga, nullptr, nullptr, HR_DIM, E_DIM, t0);

    // q, k, v with fused rope (q scaled), fp16 out
    ga.A[0] = hrh; ga.A[1] = hrh; ga.A[2] = hrh;
    ga.B[0] = hWq; ga.B[1] = hWk; ga.B[2] = hWv;
    ga.C[0] = qh;  ga.C[1] = kh;  ga.C[2] = vh;
    tgemm<5,1><<<dim3(HR_DIM/128, 16, 3), 256>>>(ga, nullptr, nullptr, HR_DIM, HR_DIM, t16);

    attn_mma<<<dim3(L_SEQ/64, NH), 128>>>(qh, kh, vh, attn);
    layernorm_k<<<L_SEQ, 256>>>(attn, ln1w, ln1b, lnh);

    // ffn1: gelu(ln @ Wf1^T + bf1) -> fp16
    ga.A[0] = lnh; ga.B[0] = hWf1; ga.C[0] = f1h;
    tgemm<1,1><<<dim3(2*HR_DIM/128, 16, 1), 256>>>(ga, bf1, nullptr, 2*HR_DIM, HR_DIM, t0);

    // ffn2 + residual -> fp16
    ga.A[0] = f1h; ga.B[0] = hWf2; ga.C[0] = hidh;
    tgemm<2,1><<<dim3(E_DIM/128, 16, 1), 256>>>(ga, bf2, x, E_DIM, 2*HR_DIM, t0);

    // silu projections -> fp16
    ga.A[0] = hidh; ga.A[1] = hidh;
    ga.B[0] = hWqi1; ga.B[1] = hWki1;
    ga.C[0] = aqh;  ga.C[1] = akh;
    tgemm<3,1><<<dim3(HR_DIM/128, 16, 2), 256>>>(ga, nullptr, nullptr, HR_DIM, E_DIM, t0);

    // importance projections with fused rope+permute into output
    ga.A[0] = aqh; ga.A[1] = akh;
    ga.B[0] = hWqi2; ga.B[1] = hWki2;
    ga.C[0] = out;  ga.C[1] = out + (size_t)NLAY*NH*L_SEQ*DD;
    tgemm<4,0><<<dim3(OUT_FEAT/128, 16, 2), 256>>>(ga, nullptr, nullptr, OUT_FEAT, HR_DIM, t8);
}